// round 1
// baseline (speedup 1.0000x reference)
#include <cuda_runtime.h>
#include <cuda_bf16.h>
#include <math_constants.h>
#include <cstdint>
#include <cstddef>

// ---------------------------------------------------------------------------
// Problem constants
// ---------------------------------------------------------------------------
#define D_MODEL 768
#define N_HEADS 12
#define D_HEAD  64
#define D_FF    3072
#define B_SZ    4
#define T_SEQ   2048
#define NTOK    (B_SZ * T_SEQ)      // 8192
#define D_QKV   (3 * D_MODEL)       // 2304
#define LN_EPS  1e-5f

// ---------------------------------------------------------------------------
// Scratch (device globals; no runtime allocation allowed)
// ---------------------------------------------------------------------------
__device__ float g_h   [NTOK * D_MODEL];   // LN output (reused for ln1 and ln2)
__device__ float g_qkv [NTOK * D_QKV];     // fused qkv
__device__ float g_attn[NTOK * D_MODEL];   // attention output (pre-projection)
__device__ float g_x1  [NTOK * D_MODEL];   // x + attn projection (residual 1)
__device__ float g_mid [NTOK * D_FF];      // gelu(ff1) intermediate

// ---------------------------------------------------------------------------
// LayerNorm: one warp per token (768 = 24 floats/lane)
// ---------------------------------------------------------------------------
__global__ __launch_bounds__(256) void ln_kernel(
    const float* __restrict__ x, const float* __restrict__ g,
    const float* __restrict__ b, float* __restrict__ out)
{
    int warp = (blockIdx.x * blockDim.x + threadIdx.x) >> 5;
    int lane = threadIdx.x & 31;
    if (warp >= NTOK) return;
    const float* xr = x + (size_t)warp * D_MODEL;
    float v[24];
    float s = 0.f;
#pragma unroll
    for (int i = 0; i < 24; i++) { v[i] = xr[lane + 32 * i]; s += v[i]; }
#pragma unroll
    for (int off = 16; off > 0; off >>= 1) s += __shfl_xor_sync(0xffffffffu, s, off);
    float mu = s * (1.f / D_MODEL);
    float sq = 0.f;
#pragma unroll
    for (int i = 0; i < 24; i++) { float d = v[i] - mu; sq += d * d; }
#pragma unroll
    for (int off = 16; off > 0; off >>= 1) sq += __shfl_xor_sync(0xffffffffu, sq, off);
    float rs = rsqrtf(sq * (1.f / D_MODEL) + LN_EPS);
    float* orow = out + (size_t)warp * D_MODEL;
#pragma unroll
    for (int i = 0; i < 24; i++) {
        int c = lane + 32 * i;
        orow[c] = (v[i] - mu) * rs * g[c] + b[c];
    }
}

// ---------------------------------------------------------------------------
// GELU (tanh approximation, matches jax.nn.gelu(approximate=True))
// ---------------------------------------------------------------------------
__device__ __forceinline__ float gelu_tanh(float x) {
    float x3 = x * x * x;
    float t = tanhf(0.7978845608028654f * (x + 0.044715f * x3));
    return 0.5f * x * (1.f + t);
}

// ---------------------------------------------------------------------------
// SGEMM: C[M,N] = A[M,K] @ W[K,N] + bias  (+ epilogue)
//   epi: 0 = none, 1 = gelu, 2 = + resid
// Tiling: BM=BN=128, BK=16, 256 threads, 8x8 per thread.
// ---------------------------------------------------------------------------
__global__ __launch_bounds__(256) void sgemm_kernel(
    const float* __restrict__ A, const float* __restrict__ W,
    const float* __restrict__ bias, const float* __restrict__ resid,
    float* __restrict__ C, int M, int N, int K, int epi)
{
    __shared__ float As[16][128];   // transposed: As[k][m]
    __shared__ float Bs[16][128];   // Bs[k][n]

    int tid = threadIdx.x;
    int tx = tid & 15, ty = tid >> 4;
    int rowBase = blockIdx.y * 128;
    int colBase = blockIdx.x * 128;

    float acc[8][8];
#pragma unroll
    for (int i = 0; i < 8; i++)
#pragma unroll
        for (int j = 0; j < 8; j++) acc[i][j] = 0.f;

    for (int k0 = 0; k0 < K; k0 += 16) {
#pragma unroll
        for (int p = 0; p < 2; p++) {
            int f = tid + p * 256;
            // A tile: 128 rows x 16 k, float4 along k
            int m  = f >> 2;
            int k4 = (f & 3) << 2;
            float4 va = *(const float4*)(A + (size_t)(rowBase + m) * K + k0 + k4);
            As[k4 + 0][m] = va.x;
            As[k4 + 1][m] = va.y;
            As[k4 + 2][m] = va.z;
            As[k4 + 3][m] = va.w;
            // B tile: 16 k x 128 n, float4 along n
            int kb = f >> 5;
            int n4 = (f & 31) << 2;
            *(float4*)&Bs[kb][n4] =
                *(const float4*)(W + (size_t)(k0 + kb) * N + colBase + n4);
        }
        __syncthreads();
#pragma unroll
        for (int kk = 0; kk < 16; kk++) {
            float a[8], bb[8];
            *(float4*)&a[0]  = *(const float4*)&As[kk][ty * 8];
            *(float4*)&a[4]  = *(const float4*)&As[kk][ty * 8 + 4];
            *(float4*)&bb[0] = *(const float4*)&Bs[kk][tx * 8];
            *(float4*)&bb[4] = *(const float4*)&Bs[kk][tx * 8 + 4];
#pragma unroll
            for (int i = 0; i < 8; i++)
#pragma unroll
                for (int j = 0; j < 8; j++)
                    acc[i][j] = fmaf(a[i], bb[j], acc[i][j]);
        }
        __syncthreads();
    }

    // epilogue
#pragma unroll
    for (int i = 0; i < 8; i++) {
        int row = rowBase + ty * 8 + i;
        size_t rbase = (size_t)row * N;
#pragma unroll
        for (int j = 0; j < 8; j++) {
            int col = colBase + tx * 8 + j;
            float c = acc[i][j] + bias[col];
            if (epi == 1) c = gelu_tanh(c);
            else if (epi == 2) c += resid[rbase + col];
            acc[i][j] = c;
        }
        *(float4*)(C + rbase + colBase + tx * 8) =
            make_float4(acc[i][0], acc[i][1], acc[i][2], acc[i][3]);
        *(float4*)(C + rbase + colBase + tx * 8 + 4) =
            make_float4(acc[i][4], acc[i][5], acc[i][6], acc[i][7]);
    }
}

// ---------------------------------------------------------------------------
// Flash attention (fp32, online softmax). One block per (q-tile, head, batch).
// BQ = BK = 128, dh = 64, 256 threads (16x16 grid, 8x8 S-tile per thread,
// 8x4 O-tile per thread).
// ---------------------------------------------------------------------------
#define BQ 128
#define BK 128
#define PS_STRIDE 136
#define RED_STRIDE 17

// smem floats: Qt 64*128 + Ktt 64*128 + Vs 128*64 + Ps 128*136 + red 128*17 + 3*128
#define FLASH_SMEM_FLOATS (64*128 + 64*128 + 128*64 + 128*PS_STRIDE + 128*RED_STRIDE + 3*128)
#define FLASH_SMEM_BYTES  (FLASH_SMEM_FLOATS * 4)

__global__ __launch_bounds__(256) void flash_kernel(
    const float* __restrict__ qkv, float* __restrict__ attn_out)
{
    extern __shared__ float sm[];
    float* Qt   = sm;                       // [64][BQ]
    float* Ktt  = Qt  + 64 * BQ;            // [64][BK]
    float* Vs   = Ktt + 64 * BK;            // [BK][64]
    float* Ps   = Vs  + BK * 64;            // [BQ][PS_STRIDE]
    float* red  = Ps  + BQ * PS_STRIDE;     // [BQ][RED_STRIDE]
    float* m_sh = red + BQ * RED_STRIDE;    // [BQ]
    float* l_sh = m_sh + BQ;
    float* sc_sh = l_sh + BQ;

    int qi = blockIdx.x, h = blockIdx.y, bb_ = blockIdx.z;
    int tid = threadIdx.x;
    int ty = tid >> 4, tx = tid & 15;

    size_t row0 = (size_t)bb_ * T_SEQ;
    const float* Qg = qkv + (row0 + (size_t)qi * BQ) * D_QKV + h * D_HEAD;
    const float* Kg = qkv + row0 * D_QKV + D_MODEL     + h * D_HEAD;
    const float* Vg = qkv + row0 * D_QKV + 2 * D_MODEL + h * D_HEAD;

    // load Q transposed (scaled by 1/sqrt(dh))
    const float qscale = 0.125f;
#pragma unroll
    for (int p = 0; p < 8; p++) {
        int f = tid + p * 256;            // 0..2047
        int r  = f >> 4;                  // 0..127
        int d4 = (f & 15) << 2;           // 0..60
        float4 v = *(const float4*)(Qg + (size_t)r * D_QKV + d4);
        Qt[(d4 + 0) * BQ + r] = v.x * qscale;
        Qt[(d4 + 1) * BQ + r] = v.y * qscale;
        Qt[(d4 + 2) * BQ + r] = v.z * qscale;
        Qt[(d4 + 3) * BQ + r] = v.w * qscale;
    }
    if (tid < BQ) { m_sh[tid] = -CUDART_INF_F; l_sh[tid] = 0.f; }

    float acc[8][4];
#pragma unroll
    for (int i = 0; i < 8; i++)
#pragma unroll
        for (int j = 0; j < 4; j++) acc[i][j] = 0.f;

    for (int kt = 0; kt < T_SEQ / BK; kt++) {
        __syncthreads();   // protect Ktt/Vs reuse (and Q/m_sh init on first iter)
        const float* Kgt = Kg + (size_t)kt * BK * D_QKV;
        const float* Vgt = Vg + (size_t)kt * BK * D_QKV;
#pragma unroll
        for (int p = 0; p < 8; p++) {
            int f = tid + p * 256;
            int r  = f >> 4;
            int d4 = (f & 15) << 2;
            float4 v = *(const float4*)(Kgt + (size_t)r * D_QKV + d4);
            Ktt[(d4 + 0) * BK + r] = v.x;
            Ktt[(d4 + 1) * BK + r] = v.y;
            Ktt[(d4 + 2) * BK + r] = v.z;
            Ktt[(d4 + 3) * BK + r] = v.w;
            float4 w = *(const float4*)(Vgt + (size_t)r * D_QKV + d4);
            *(float4*)&Vs[r * 64 + d4] = w;
        }
        __syncthreads();

        // S = (Q * scale) @ K^T  -> s[8][8] per thread
        float s[8][8];
#pragma unroll
        for (int i = 0; i < 8; i++)
#pragma unroll
            for (int j = 0; j < 8; j++) s[i][j] = 0.f;

#pragma unroll 8
        for (int kk = 0; kk < 64; kk++) {
            float a[8], bv[8];
            *(float4*)&a[0]  = *(const float4*)&Qt[kk * BQ + ty * 8];
            *(float4*)&a[4]  = *(const float4*)&Qt[kk * BQ + ty * 8 + 4];
            *(float4*)&bv[0] = *(const float4*)&Ktt[kk * BK + tx * 8];
            *(float4*)&bv[4] = *(const float4*)&Ktt[kk * BK + tx * 8 + 4];
#pragma unroll
            for (int i = 0; i < 8; i++)
#pragma unroll
                for (int j = 0; j < 8; j++)
                    s[i][j] = fmaf(a[i], bv[j], s[i][j]);
        }

        // per-thread row maxima
#pragma unroll
        for (int i = 0; i < 8; i++) {
            float mx = s[i][0];
#pragma unroll
            for (int j = 1; j < 8; j++) mx = fmaxf(mx, s[i][j]);
            red[(ty * 8 + i) * RED_STRIDE + tx] = mx;
        }
        __syncthreads();

        if (tid < BQ) {
            float mx = red[tid * RED_STRIDE];
#pragma unroll
            for (int t = 1; t < 16; t++) mx = fmaxf(mx, red[tid * RED_STRIDE + t]);
            float mo = m_sh[tid];
            float mn = fmaxf(mo, mx);
            sc_sh[tid] = __expf(mo - mn);   // 0 on first tile (mo = -inf)
            m_sh[tid]  = mn;
        }
        __syncthreads();

        // p = exp(s - m_new), row sums, rescale O accumulator, stage P
#pragma unroll
        for (int i = 0; i < 8; i++) {
            int r = ty * 8 + i;
            float mn = m_sh[r];
            float sc = sc_sh[r];
            float rs = 0.f;
#pragma unroll
            for (int j = 0; j < 8; j++) {
                s[i][j] = __expf(s[i][j] - mn);
                rs += s[i][j];
            }
            red[r * RED_STRIDE + tx] = rs;
#pragma unroll
            for (int j = 0; j < 4; j++) acc[i][j] *= sc;
            *(float4*)&Ps[r * PS_STRIDE + tx * 8] =
                make_float4(s[i][0], s[i][1], s[i][2], s[i][3]);
            *(float4*)&Ps[r * PS_STRIDE + tx * 8 + 4] =
                make_float4(s[i][4], s[i][5], s[i][6], s[i][7]);
        }
        __syncthreads();

        if (tid < BQ) {
            float rs = 0.f;
#pragma unroll
            for (int t = 0; t < 16; t++) rs += red[tid * RED_STRIDE + t];
            l_sh[tid] = l_sh[tid] * sc_sh[tid] + rs;
        }

        // O += P @ V   (contraction over keys, 4 at a time)
#pragma unroll 4
        for (int kq = 0; kq < BK; kq += 4) {
            float4 b0 = *(const float4*)&Vs[(kq + 0) * 64 + tx * 4];
            float4 b1 = *(const float4*)&Vs[(kq + 1) * 64 + tx * 4];
            float4 b2 = *(const float4*)&Vs[(kq + 2) * 64 + tx * 4];
            float4 b3 = *(const float4*)&Vs[(kq + 3) * 64 + tx * 4];
#pragma unroll
            for (int i = 0; i < 8; i++) {
                float4 av = *(const float4*)&Ps[(ty * 8 + i) * PS_STRIDE + kq];
                acc[i][0] = fmaf(av.x, b0.x, fmaf(av.y, b1.x, fmaf(av.z, b2.x, fmaf(av.w, b3.x, acc[i][0]))));
                acc[i][1] = fmaf(av.x, b0.y, fmaf(av.y, b1.y, fmaf(av.z, b2.y, fmaf(av.w, b3.y, acc[i][1]))));
                acc[i][2] = fmaf(av.x, b0.z, fmaf(av.y, b1.z, fmaf(av.z, b2.z, fmaf(av.w, b3.z, acc[i][2]))));
                acc[i][3] = fmaf(av.x, b0.w, fmaf(av.y, b1.w, fmaf(av.z, b2.w, fmaf(av.w, b3.w, acc[i][3]))));
            }
        }
    }

    __syncthreads();   // l_sh final values visible to all

    // write O = acc / l, into [token][h*64 + d]
#pragma unroll
    for (int i = 0; i < 8; i++) {
        int r = ty * 8 + i;
        float inv = 1.f / l_sh[r];
        size_t tok = row0 + (size_t)qi * BQ + r;
        float* orow = attn_out + tok * D_MODEL + h * D_HEAD + tx * 4;
        *(float4*)orow = make_float4(acc[i][0] * inv, acc[i][1] * inv,
                                     acc[i][2] * inv, acc[i][3] * inv);
    }
}

// ---------------------------------------------------------------------------
// Launch
// ---------------------------------------------------------------------------
extern "C" void kernel_launch(void* const* d_in, const int* in_sizes, int n_in,
                              void* d_out, int out_size)
{
    const float* x          = (const float*)d_in[0];
    const float* ln1_g      = (const float*)d_in[1];
    const float* ln1_b      = (const float*)d_in[2];
    const float* qkv_w      = (const float*)d_in[3];
    const float* qkv_b      = (const float*)d_in[4];
    const float* attn_out_w = (const float*)d_in[5];
    const float* attn_out_b = (const float*)d_in[6];
    const float* ln2_g      = (const float*)d_in[7];
    const float* ln2_b      = (const float*)d_in[8];
    const float* ff1_w      = (const float*)d_in[9];
    const float* ff1_b      = (const float*)d_in[10];
    const float* ff2_w      = (const float*)d_in[11];
    const float* ff2_b      = (const float*)d_in[12];
    float* out = (float*)d_out;

    void *p_h, *p_qkv, *p_attn, *p_x1, *p_mid;
    cudaGetSymbolAddress(&p_h,    g_h);
    cudaGetSymbolAddress(&p_qkv,  g_qkv);
    cudaGetSymbolAddress(&p_attn, g_attn);
    cudaGetSymbolAddress(&p_x1,   g_x1);
    cudaGetSymbolAddress(&p_mid,  g_mid);
    float* h    = (float*)p_h;
    float* qkv  = (float*)p_qkv;
    float* attn = (float*)p_attn;
    float* x1   = (float*)p_x1;
    float* mid  = (float*)p_mid;

    cudaFuncSetAttribute(flash_kernel,
                         cudaFuncAttributeMaxDynamicSharedMemorySize,
                         FLASH_SMEM_BYTES);

    // 1. h = LN1(x)
    ln_kernel<<<NTOK / 8, 256>>>(x, ln1_g, ln1_b, h);
    // 2. qkv = h @ qkv_w + qkv_b
    sgemm_kernel<<<dim3(D_QKV / 128, NTOK / 128), 256>>>(
        h, qkv_w, qkv_b, nullptr, qkv, NTOK, D_QKV, D_MODEL, 0);
    // 3. attention
    flash_kernel<<<dim3(T_SEQ / BQ, N_HEADS, B_SZ), 256, FLASH_SMEM_BYTES>>>(
        qkv, attn);
    // 4. x1 = x + attn @ attn_out_w + attn_out_b
    sgemm_kernel<<<dim3(D_MODEL / 128, NTOK / 128), 256>>>(
        attn, attn_out_w, attn_out_b, x, x1, NTOK, D_MODEL, D_MODEL, 2);
    // 5. h = LN2(x1)
    ln_kernel<<<NTOK / 8, 256>>>(x1, ln2_g, ln2_b, h);
    // 6. mid = gelu(h @ ff1_w + ff1_b)
    sgemm_kernel<<<dim3(D_FF / 128, NTOK / 128), 256>>>(
        h, ff1_w, ff1_b, nullptr, mid, NTOK, D_FF, D_MODEL, 1);
    // 7. out = x1 + mid @ ff2_w + ff2_b
    sgemm_kernel<<<dim3(D_MODEL / 128, NTOK / 128), 256>>>(
        mid, ff2_w, ff2_b, x1, out, NTOK, D_MODEL, D_FF, 2);
}

// round 2
// speedup vs baseline: 1.7831x; 1.7831x over previous
#include <cuda_runtime.h>
#include <cuda_bf16.h>
#include <math_constants.h>
#include <cstdint>
#include <cstddef>

// ---------------------------------------------------------------------------
// Problem constants
// ---------------------------------------------------------------------------
#define D_MODEL 768
#define N_HEADS 12
#define D_HEAD  64
#define D_FF    3072
#define B_SZ    4
#define T_SEQ   2048
#define NTOK    (B_SZ * T_SEQ)      // 8192
#define D_QKV   (3 * D_MODEL)       // 2304
#define LN_EPS  1e-5f

// ---------------------------------------------------------------------------
// Scratch (device globals; no runtime allocation allowed)
// ---------------------------------------------------------------------------
__device__ float g_h   [NTOK * D_MODEL];
__device__ float g_qkv [NTOK * D_QKV];
__device__ float g_attn[NTOK * D_MODEL];
__device__ float g_x1  [NTOK * D_MODEL];
__device__ float g_mid [NTOK * D_FF];

// ---------------------------------------------------------------------------
// LayerNorm: one warp per token
// ---------------------------------------------------------------------------
__global__ __launch_bounds__(256) void ln_kernel(
    const float* __restrict__ x, const float* __restrict__ g,
    const float* __restrict__ b, float* __restrict__ out)
{
    int warp = (blockIdx.x * blockDim.x + threadIdx.x) >> 5;
    int lane = threadIdx.x & 31;
    if (warp >= NTOK) return;
    const float* xr = x + (size_t)warp * D_MODEL;
    float v[24];
    float s = 0.f;
#pragma unroll
    for (int i = 0; i < 24; i++) { v[i] = xr[lane + 32 * i]; s += v[i]; }
#pragma unroll
    for (int off = 16; off > 0; off >>= 1) s += __shfl_xor_sync(0xffffffffu, s, off);
    float mu = s * (1.f / D_MODEL);
    float sq = 0.f;
#pragma unroll
    for (int i = 0; i < 24; i++) { float d = v[i] - mu; sq += d * d; }
#pragma unroll
    for (int off = 16; off > 0; off >>= 1) sq += __shfl_xor_sync(0xffffffffu, sq, off);
    float rs = rsqrtf(sq * (1.f / D_MODEL) + LN_EPS);
    float* orow = out + (size_t)warp * D_MODEL;
#pragma unroll
    for (int i = 0; i < 24; i++) {
        int c = lane + 32 * i;
        orow[c] = (v[i] - mu) * rs * g[c] + b[c];
    }
}

// ---------------------------------------------------------------------------
// GELU (tanh approx)
// ---------------------------------------------------------------------------
__device__ __forceinline__ float gelu_tanh(float x) {
    float x3 = x * x * x;
    float t = tanhf(0.7978845608028654f * (x + 0.044715f * x3));
    return 0.5f * x * (1.f + t);
}

// ---------------------------------------------------------------------------
// tf32 helpers
// ---------------------------------------------------------------------------
__device__ __forceinline__ uint32_t f2tf32(float f) {
    uint32_t u;
    asm("cvt.rna.tf32.f32 %0, %1;" : "=r"(u) : "f"(f));
    return u;
}

__device__ __forceinline__ void mma_tf32(float c[4], const uint32_t a[4],
                                         const uint32_t b[2]) {
    asm volatile(
        "mma.sync.aligned.m16n8k8.row.col.f32.tf32.tf32.f32 "
        "{%0,%1,%2,%3}, {%4,%5,%6,%7}, {%8,%9}, {%0,%1,%2,%3};"
        : "+f"(c[0]), "+f"(c[1]), "+f"(c[2]), "+f"(c[3])
        : "r"(a[0]), "r"(a[1]), "r"(a[2]), "r"(a[3]), "r"(b[0]), "r"(b[1]));
}

__device__ __forceinline__ void cp_async16(void* smem_dst, const void* gsrc) {
    uint32_t d = (uint32_t)__cvta_generic_to_shared(smem_dst);
    asm volatile("cp.async.ca.shared.global [%0], [%1], 16;\n" ::"r"(d), "l"(gsrc));
}

// ---------------------------------------------------------------------------
// tf32 tensor-core GEMM: C[M,N] = A[M,K] @ W[K,N] + bias (+ epilogue)
//   epi: 0 none, 1 gelu, 2 +resid
// Block tile 128x128, BK=32, 256 threads (8 warps, 64x32 warp tiles),
// double-buffered cp.async pipeline.
//   As: [128 m][36] (stride 36 -> conflict-free frag loads)
//   Bs: [32 k][136]
// ---------------------------------------------------------------------------
#define AS_STRIDE 36
#define BS_STRIDE 136
#define AS_FLOATS (128 * AS_STRIDE)     // 4608 per stage
#define BS_FLOATS (32 * BS_STRIDE)      // 4352 per stage
#define GEMM_SMEM_BYTES ((2 * AS_FLOATS + 2 * BS_FLOATS) * 4)  // 71680

__global__ __launch_bounds__(256, 2) void tf32_gemm_kernel(
    const float* __restrict__ A, const float* __restrict__ W,
    const float* __restrict__ bias, const float* __restrict__ resid,
    float* __restrict__ C, int M, int N, int K, int epi)
{
    extern __shared__ float sm[];
    float* Asm = sm;                    // 2 stages
    float* Bsm = sm + 2 * AS_FLOATS;    // 2 stages

    int tid = threadIdx.x;
    int lane = tid & 31;
    int warp = tid >> 5;
    int g = lane >> 2;     // groupID 0..7
    int t = lane & 3;      // thread-in-group 0..3
    int wm = warp >> 2;    // 0..1  -> warp M offset = wm*64
    int wn = warp & 3;     // 0..3  -> warp N offset = wn*32
    int m_w = wm * 64;
    int n_w = wn * 32;

    int rowBase = blockIdx.y * 128;
    int colBase = blockIdx.x * 128;

    const float* Ag = A + (size_t)rowBase * K;
    const float* Wg = W + colBase;

    float acc[4][4][4];
#pragma unroll
    for (int mf = 0; mf < 4; mf++)
#pragma unroll
        for (int nf = 0; nf < 4; nf++)
#pragma unroll
            for (int i = 0; i < 4; i++) acc[mf][nf][i] = 0.f;

    int ntiles = K / 32;

    // ---- stage copy (4 A chunks + 4 B chunks of 16B per thread) ----
    auto issue_copy = [&](int s, int kt) {
        float* as = Asm + s * AS_FLOATS;
        float* bs = Bsm + s * BS_FLOATS;
#pragma unroll
        for (int i = 0; i < 4; i++) {
            int id = tid + i * 256;
            int r = id >> 3;            // 0..127
            int c4 = (id & 7) << 2;     // 0..28
            cp_async16(as + r * AS_STRIDE + c4, Ag + (size_t)r * K + kt + c4);
        }
#pragma unroll
        for (int i = 0; i < 4; i++) {
            int id = tid + i * 256;
            int r = id >> 5;            // 0..31
            int c4 = (id & 31) << 2;    // 0..124
            cp_async16(bs + r * BS_STRIDE + c4, Wg + (size_t)(kt + r) * N + c4);
        }
        asm volatile("cp.async.commit_group;\n");
    };

    issue_copy(0, 0);

    for (int kt = 0; kt < ntiles; kt++) {
        if (kt + 1 < ntiles) {
            issue_copy((kt + 1) & 1, (kt + 1) * 32);
            asm volatile("cp.async.wait_group 1;\n");
        } else {
            asm volatile("cp.async.wait_group 0;\n");
        }
        __syncthreads();

        const float* as = Asm + (kt & 1) * AS_FLOATS;
        const float* bs = Bsm + (kt & 1) * BS_FLOATS;

#pragma unroll
        for (int ks = 0; ks < 4; ks++) {
            int k0 = ks * 8;
            uint32_t af[4][4];
            uint32_t bf[4][2];
#pragma unroll
            for (int mf = 0; mf < 4; mf++) {
                const float* base = as + (m_w + mf * 16 + g) * AS_STRIDE + k0 + t;
                af[mf][0] = f2tf32(base[0]);
                af[mf][2] = f2tf32(base[4]);
                af[mf][1] = f2tf32(base[8 * AS_STRIDE]);
                af[mf][3] = f2tf32(base[8 * AS_STRIDE + 4]);
            }
#pragma unroll
            for (int nf = 0; nf < 4; nf++) {
                const float* bb = bs + (k0 + t) * BS_STRIDE + n_w + nf * 8 + g;
                bf[nf][0] = f2tf32(bb[0]);
                bf[nf][1] = f2tf32(bb[4 * BS_STRIDE]);
            }
#pragma unroll
            for (int mf = 0; mf < 4; mf++)
#pragma unroll
                for (int nf = 0; nf < 4; nf++)
                    mma_tf32(acc[mf][nf], af[mf], bf[nf]);
        }
        __syncthreads();
    }

    // ---- epilogue ----
#pragma unroll
    for (int mf = 0; mf < 4; mf++) {
        int row0 = rowBase + m_w + mf * 16 + g;
        int row1 = row0 + 8;
#pragma unroll
        for (int nf = 0; nf < 4; nf++) {
            int col = colBase + n_w + nf * 8 + 2 * t;
            float2 bv = *(const float2*)&bias[col];
            float v00 = acc[mf][nf][0] + bv.x;
            float v01 = acc[mf][nf][1] + bv.y;
            float v10 = acc[mf][nf][2] + bv.x;
            float v11 = acc[mf][nf][3] + bv.y;
            if (epi == 1) {
                v00 = gelu_tanh(v00); v01 = gelu_tanh(v01);
                v10 = gelu_tanh(v10); v11 = gelu_tanh(v11);
            } else if (epi == 2) {
                float2 r0 = *(const float2*)&resid[(size_t)row0 * N + col];
                float2 r1 = *(const float2*)&resid[(size_t)row1 * N + col];
                v00 += r0.x; v01 += r0.y; v10 += r1.x; v11 += r1.y;
            }
            *(float2*)&C[(size_t)row0 * N + col] = make_float2(v00, v01);
            *(float2*)&C[(size_t)row1 * N + col] = make_float2(v10, v11);
        }
    }
}

// ---------------------------------------------------------------------------
// Flash attention (fp32, online softmax) — unchanged from R1
// ---------------------------------------------------------------------------
#define BQ 128
#define BK 128
#define PS_STRIDE 136
#define RED_STRIDE 17
#define FLASH_SMEM_FLOATS (64*128 + 64*128 + 128*64 + 128*PS_STRIDE + 128*RED_STRIDE + 3*128)
#define FLASH_SMEM_BYTES  (FLASH_SMEM_FLOATS * 4)

__global__ __launch_bounds__(256) void flash_kernel(
    const float* __restrict__ qkv, float* __restrict__ attn_out)
{
    extern __shared__ float smf[];
    float* Qt   = smf;
    float* Ktt  = Qt  + 64 * BQ;
    float* Vs   = Ktt + 64 * BK;
    float* Ps   = Vs  + BK * 64;
    float* red  = Ps  + BQ * PS_STRIDE;
    float* m_sh = red + BQ * RED_STRIDE;
    float* l_sh = m_sh + BQ;
    float* sc_sh = l_sh + BQ;

    int qi = blockIdx.x, h = blockIdx.y, bb_ = blockIdx.z;
    int tid = threadIdx.x;
    int ty = tid >> 4, tx = tid & 15;

    size_t row0 = (size_t)bb_ * T_SEQ;
    const float* Qg = qkv + (row0 + (size_t)qi * BQ) * D_QKV + h * D_HEAD;
    const float* Kg = qkv + row0 * D_QKV + D_MODEL     + h * D_HEAD;
    const float* Vg = qkv + row0 * D_QKV + 2 * D_MODEL + h * D_HEAD;

    const float qscale = 0.125f;
#pragma unroll
    for (int p = 0; p < 8; p++) {
        int f = tid + p * 256;
        int r  = f >> 4;
        int d4 = (f & 15) << 2;
        float4 v = *(const float4*)(Qg + (size_t)r * D_QKV + d4);
        Qt[(d4 + 0) * BQ + r] = v.x * qscale;
        Qt[(d4 + 1) * BQ + r] = v.y * qscale;
        Qt[(d4 + 2) * BQ + r] = v.z * qscale;
        Qt[(d4 + 3) * BQ + r] = v.w * qscale;
    }
    if (tid < BQ) { m_sh[tid] = -CUDART_INF_F; l_sh[tid] = 0.f; }

    float acc[8][4];
#pragma unroll
    for (int i = 0; i < 8; i++)
#pragma unroll
        for (int j = 0; j < 4; j++) acc[i][j] = 0.f;

    for (int kt = 0; kt < T_SEQ / BK; kt++) {
        __syncthreads();
        const float* Kgt = Kg + (size_t)kt * BK * D_QKV;
        const float* Vgt = Vg + (size_t)kt * BK * D_QKV;
#pragma unroll
        for (int p = 0; p < 8; p++) {
            int f = tid + p * 256;
            int r  = f >> 4;
            int d4 = (f & 15) << 2;
            float4 v = *(const float4*)(Kgt + (size_t)r * D_QKV + d4);
            Ktt[(d4 + 0) * BK + r] = v.x;
            Ktt[(d4 + 1) * BK + r] = v.y;
            Ktt[(d4 + 2) * BK + r] = v.z;
            Ktt[(d4 + 3) * BK + r] = v.w;
            float4 w = *(const float4*)(Vgt + (size_t)r * D_QKV + d4);
            *(float4*)&Vs[r * 64 + d4] = w;
        }
        __syncthreads();

        float s[8][8];
#pragma unroll
        for (int i = 0; i < 8; i++)
#pragma unroll
            for (int j = 0; j < 8; j++) s[i][j] = 0.f;

#pragma unroll 8
        for (int kk = 0; kk < 64; kk++) {
            float a[8], bv[8];
            *(float4*)&a[0]  = *(const float4*)&Qt[kk * BQ + ty * 8];
            *(float4*)&a[4]  = *(const float4*)&Qt[kk * BQ + ty * 8 + 4];
            *(float4*)&bv[0] = *(const float4*)&Ktt[kk * BK + tx * 8];
            *(float4*)&bv[4] = *(const float4*)&Ktt[kk * BK + tx * 8 + 4];
#pragma unroll
            for (int i = 0; i < 8; i++)
#pragma unroll
                for (int j = 0; j < 8; j++)
                    s[i][j] = fmaf(a[i], bv[j], s[i][j]);
        }

#pragma unroll
        for (int i = 0; i < 8; i++) {
            float mx = s[i][0];
#pragma unroll
            for (int j = 1; j < 8; j++) mx = fmaxf(mx, s[i][j]);
            red[(ty * 8 + i) * RED_STRIDE + tx] = mx;
        }
        __syncthreads();

        if (tid < BQ) {
            float mx = red[tid * RED_STRIDE];
#pragma unroll
            for (int tt = 1; tt < 16; tt++) mx = fmaxf(mx, red[tid * RED_STRIDE + tt]);
            float mo = m_sh[tid];
            float mn = fmaxf(mo, mx);
            sc_sh[tid] = __expf(mo - mn);
            m_sh[tid]  = mn;
        }
        __syncthreads();

#pragma unroll
        for (int i = 0; i < 8; i++) {
            int r = ty * 8 + i;
            float mn = m_sh[r];
            float sc = sc_sh[r];
            float rs = 0.f;
#pragma unroll
            for (int j = 0; j < 8; j++) {
                s[i][j] = __expf(s[i][j] - mn);
                rs += s[i][j];
            }
            red[r * RED_STRIDE + tx] = rs;
#pragma unroll
            for (int j = 0; j < 4; j++) acc[i][j] *= sc;
            *(float4*)&Ps[r * PS_STRIDE + tx * 8] =
                make_float4(s[i][0], s[i][1], s[i][2], s[i][3]);
            *(float4*)&Ps[r * PS_STRIDE + tx * 8 + 4] =
                make_float4(s[i][4], s[i][5], s[i][6], s[i][7]);
        }
        __syncthreads();

        if (tid < BQ) {
            float rs = 0.f;
#pragma unroll
            for (int tt = 0; tt < 16; tt++) rs += red[tid * RED_STRIDE + tt];
            l_sh[tid] = l_sh[tid] * sc_sh[tid] + rs;
        }

#pragma unroll 4
        for (int kq = 0; kq < BK; kq += 4) {
            float4 b0 = *(const float4*)&Vs[(kq + 0) * 64 + tx * 4];
            float4 b1 = *(const float4*)&Vs[(kq + 1) * 64 + tx * 4];
            float4 b2 = *(const float4*)&Vs[(kq + 2) * 64 + tx * 4];
            float4 b3 = *(const float4*)&Vs[(kq + 3) * 64 + tx * 4];
#pragma unroll
            for (int i = 0; i < 8; i++) {
                float4 av = *(const float4*)&Ps[(ty * 8 + i) * PS_STRIDE + kq];
                acc[i][0] = fmaf(av.x, b0.x, fmaf(av.y, b1.x, fmaf(av.z, b2.x, fmaf(av.w, b3.x, acc[i][0]))));
                acc[i][1] = fmaf(av.x, b0.y, fmaf(av.y, b1.y, fmaf(av.z, b2.y, fmaf(av.w, b3.y, acc[i][1]))));
                acc[i][2] = fmaf(av.x, b0.z, fmaf(av.y, b1.z, fmaf(av.z, b2.z, fmaf(av.w, b3.z, acc[i][2]))));
                acc[i][3] = fmaf(av.x, b0.w, fmaf(av.y, b1.w, fmaf(av.z, b2.w, fmaf(av.w, b3.w, acc[i][3]))));
            }
        }
    }

    __syncthreads();

#pragma unroll
    for (int i = 0; i < 8; i++) {
        int r = ty * 8 + i;
        float inv = 1.f / l_sh[r];
        size_t tok = row0 + (size_t)qi * BQ + r;
        float* orow = attn_out + tok * D_MODEL + h * D_HEAD + tx * 4;
        *(float4*)orow = make_float4(acc[i][0] * inv, acc[i][1] * inv,
                                     acc[i][2] * inv, acc[i][3] * inv);
    }
}

// ---------------------------------------------------------------------------
// Launch
// ---------------------------------------------------------------------------
extern "C" void kernel_launch(void* const* d_in, const int* in_sizes, int n_in,
                              void* d_out, int out_size)
{
    const float* x          = (const float*)d_in[0];
    const float* ln1_g      = (const float*)d_in[1];
    const float* ln1_b      = (const float*)d_in[2];
    const float* qkv_w      = (const float*)d_in[3];
    const float* qkv_b      = (const float*)d_in[4];
    const float* attn_out_w = (const float*)d_in[5];
    const float* attn_out_b = (const float*)d_in[6];
    const float* ln2_g      = (const float*)d_in[7];
    const float* ln2_b      = (const float*)d_in[8];
    const float* ff1_w      = (const float*)d_in[9];
    const float* ff1_b      = (const float*)d_in[10];
    const float* ff2_w      = (const float*)d_in[11];
    const float* ff2_b      = (const float*)d_in[12];
    float* out = (float*)d_out;

    void *p_h, *p_qkv, *p_attn, *p_x1, *p_mid;
    cudaGetSymbolAddress(&p_h,    g_h);
    cudaGetSymbolAddress(&p_qkv,  g_qkv);
    cudaGetSymbolAddress(&p_attn, g_attn);
    cudaGetSymbolAddress(&p_x1,   g_x1);
    cudaGetSymbolAddress(&p_mid,  g_mid);
    float* h    = (float*)p_h;
    float* qkv  = (float*)p_qkv;
    float* attn = (float*)p_attn;
    float* x1   = (float*)p_x1;
    float* mid  = (float*)p_mid;

    cudaFuncSetAttribute(flash_kernel,
                         cudaFuncAttributeMaxDynamicSharedMemorySize,
                         FLASH_SMEM_BYTES);
    cudaFuncSetAttribute(tf32_gemm_kernel,
                         cudaFuncAttributeMaxDynamicSharedMemorySize,
                         GEMM_SMEM_BYTES);

    // 1. h = LN1(x)
    ln_kernel<<<NTOK / 8, 256>>>(x, ln1_g, ln1_b, h);
    // 2. qkv = h @ qkv_w + qkv_b
    tf32_gemm_kernel<<<dim3(D_QKV / 128, NTOK / 128), 256, GEMM_SMEM_BYTES>>>(
        h, qkv_w, qkv_b, nullptr, qkv, NTOK, D_QKV, D_MODEL, 0);
    // 3. attention
    flash_kernel<<<dim3(T_SEQ / BQ, N_HEADS, B_SZ), 256, FLASH_SMEM_BYTES>>>(
        qkv, attn);
    // 4. x1 = x + attn @ attn_out_w + attn_out_b
    tf32_gemm_kernel<<<dim3(D_MODEL / 128, NTOK / 128), 256, GEMM_SMEM_BYTES>>>(
        attn, attn_out_w, attn_out_b, x, x1, NTOK, D_MODEL, D_MODEL, 2);
    // 5. h = LN2(x1)
    ln_kernel<<<NTOK / 8, 256>>>(x1, ln2_g, ln2_b, h);
    // 6. mid = gelu(h @ ff1_w + ff1_b)
    tf32_gemm_kernel<<<dim3(D_FF / 128, NTOK / 128), 256, GEMM_SMEM_BYTES>>>(
        h, ff1_w, ff1_b, nullptr, mid, NTOK, D_FF, D_MODEL, 1);
    // 7. out = x1 + mid @ ff2_w + ff2_b
    tf32_gemm_kernel<<<dim3(D_MODEL / 128, NTOK / 128), 256, GEMM_SMEM_BYTES>>>(
        mid, ff2_w, ff2_b, x1, out, NTOK, D_MODEL, D_FF, 2);
}

// round 3
// speedup vs baseline: 3.1036x; 1.7405x over previous
#include <cuda_runtime.h>
#include <cuda_bf16.h>
#include <math_constants.h>
#include <cstdint>
#include <cstddef>

// ---------------------------------------------------------------------------
// Problem constants
// ---------------------------------------------------------------------------
#define D_MODEL 768
#define N_HEADS 12
#define D_HEAD  64
#define D_FF    3072
#define B_SZ    4
#define T_SEQ   2048
#define NTOK    (B_SZ * T_SEQ)      // 8192
#define D_QKV   (3 * D_MODEL)       // 2304
#define LN_EPS  1e-5f

// ---------------------------------------------------------------------------
// Scratch (device globals)
// ---------------------------------------------------------------------------
__device__ float g_h   [NTOK * D_MODEL];
__device__ float g_qkv [NTOK * D_QKV];
__device__ float g_attn[NTOK * D_MODEL];
__device__ float g_x1  [NTOK * D_MODEL];
__device__ float g_mid [NTOK * D_FF];

// ---------------------------------------------------------------------------
// LayerNorm: one warp per token
// ---------------------------------------------------------------------------
__global__ __launch_bounds__(256) void ln_kernel(
    const float* __restrict__ x, const float* __restrict__ g,
    const float* __restrict__ b, float* __restrict__ out)
{
    int warp = (blockIdx.x * blockDim.x + threadIdx.x) >> 5;
    int lane = threadIdx.x & 31;
    if (warp >= NTOK) return;
    const float* xr = x + (size_t)warp * D_MODEL;
    float v[24];
    float s = 0.f;
#pragma unroll
    for (int i = 0; i < 24; i++) { v[i] = xr[lane + 32 * i]; s += v[i]; }
#pragma unroll
    for (int off = 16; off > 0; off >>= 1) s += __shfl_xor_sync(0xffffffffu, s, off);
    float mu = s * (1.f / D_MODEL);
    float sq = 0.f;
#pragma unroll
    for (int i = 0; i < 24; i++) { float d = v[i] - mu; sq += d * d; }
#pragma unroll
    for (int off = 16; off > 0; off >>= 1) sq += __shfl_xor_sync(0xffffffffu, sq, off);
    float rs = rsqrtf(sq * (1.f / D_MODEL) + LN_EPS);
    float* orow = out + (size_t)warp * D_MODEL;
#pragma unroll
    for (int i = 0; i < 24; i++) {
        int c = lane + 32 * i;
        orow[c] = (v[i] - mu) * rs * g[c] + b[c];
    }
}

// ---------------------------------------------------------------------------
// GELU (tanh approx)
// ---------------------------------------------------------------------------
__device__ __forceinline__ float gelu_tanh(float x) {
    float x3 = x * x * x;
    float t = tanhf(0.7978845608028654f * (x + 0.044715f * x3));
    return 0.5f * x * (1.f + t);
}

// ---------------------------------------------------------------------------
// tf32 / mma helpers
// ---------------------------------------------------------------------------
__device__ __forceinline__ uint32_t f2tf32(float f) {
    uint32_t u;
    asm("cvt.rna.tf32.f32 %0, %1;" : "=r"(u) : "f"(f));
    return u;
}
__device__ __forceinline__ float f2tf32f(float f) {
    uint32_t u = f2tf32(f);
    return __uint_as_float(u);
}

__device__ __forceinline__ void mma_tf32(float c[4], const uint32_t a[4],
                                         const uint32_t b[2]) {
    asm volatile(
        "mma.sync.aligned.m16n8k8.row.col.f32.tf32.tf32.f32 "
        "{%0,%1,%2,%3}, {%4,%5,%6,%7}, {%8,%9}, {%0,%1,%2,%3};"
        : "+f"(c[0]), "+f"(c[1]), "+f"(c[2]), "+f"(c[3])
        : "r"(a[0]), "r"(a[1]), "r"(a[2]), "r"(a[3]), "r"(b[0]), "r"(b[1]));
}

__device__ __forceinline__ void cp_async16(void* smem_dst, const void* gsrc) {
    uint32_t d = (uint32_t)__cvta_generic_to_shared(smem_dst);
    asm volatile("cp.async.ca.shared.global [%0], [%1], 16;\n" ::"r"(d), "l"(gsrc));
}

// ---------------------------------------------------------------------------
// tf32 tensor-core GEMM (unchanged from R2, validated)
// ---------------------------------------------------------------------------
#define AS_STRIDE 36
#define BS_STRIDE 136
#define AS_FLOATS (128 * AS_STRIDE)
#define BS_FLOATS (32 * BS_STRIDE)
#define GEMM_SMEM_BYTES ((2 * AS_FLOATS + 2 * BS_FLOATS) * 4)

__global__ __launch_bounds__(256, 2) void tf32_gemm_kernel(
    const float* __restrict__ A, const float* __restrict__ W,
    const float* __restrict__ bias, const float* __restrict__ resid,
    float* __restrict__ C, int M, int N, int K, int epi)
{
    extern __shared__ float sm[];
    float* Asm = sm;
    float* Bsm = sm + 2 * AS_FLOATS;

    int tid = threadIdx.x;
    int lane = tid & 31;
    int warp = tid >> 5;
    int g = lane >> 2;
    int t = lane & 3;
    int m_w = (warp >> 2) * 64;
    int n_w = (warp & 3) * 32;

    int rowBase = blockIdx.y * 128;
    int colBase = blockIdx.x * 128;

    const float* Ag = A + (size_t)rowBase * K;
    const float* Wg = W + colBase;

    float acc[4][4][4];
#pragma unroll
    for (int mf = 0; mf < 4; mf++)
#pragma unroll
        for (int nf = 0; nf < 4; nf++)
#pragma unroll
            for (int i = 0; i < 4; i++) acc[mf][nf][i] = 0.f;

    int ntiles = K / 32;

    auto issue_copy = [&](int s, int kt) {
        float* as = Asm + s * AS_FLOATS;
        float* bs = Bsm + s * BS_FLOATS;
#pragma unroll
        for (int i = 0; i < 4; i++) {
            int id = tid + i * 256;
            int r = id >> 3;
            int c4 = (id & 7) << 2;
            cp_async16(as + r * AS_STRIDE + c4, Ag + (size_t)r * K + kt + c4);
        }
#pragma unroll
        for (int i = 0; i < 4; i++) {
            int id = tid + i * 256;
            int r = id >> 5;
            int c4 = (id & 31) << 2;
            cp_async16(bs + r * BS_STRIDE + c4, Wg + (size_t)(kt + r) * N + c4);
        }
        asm volatile("cp.async.commit_group;\n");
    };

    issue_copy(0, 0);

    for (int kt = 0; kt < ntiles; kt++) {
        if (kt + 1 < ntiles) {
            issue_copy((kt + 1) & 1, (kt + 1) * 32);
            asm volatile("cp.async.wait_group 1;\n");
        } else {
            asm volatile("cp.async.wait_group 0;\n");
        }
        __syncthreads();

        const float* as = Asm + (kt & 1) * AS_FLOATS;
        const float* bs = Bsm + (kt & 1) * BS_FLOATS;

#pragma unroll
        for (int ks = 0; ks < 4; ks++) {
            int k0 = ks * 8;
            uint32_t af[4][4];
            uint32_t bf[4][2];
#pragma unroll
            for (int mf = 0; mf < 4; mf++) {
                const float* base = as + (m_w + mf * 16 + g) * AS_STRIDE + k0 + t;
                af[mf][0] = f2tf32(base[0]);
                af[mf][2] = f2tf32(base[4]);
                af[mf][1] = f2tf32(base[8 * AS_STRIDE]);
                af[mf][3] = f2tf32(base[8 * AS_STRIDE + 4]);
            }
#pragma unroll
            for (int nf = 0; nf < 4; nf++) {
                const float* bb = bs + (k0 + t) * BS_STRIDE + n_w + nf * 8 + g;
                bf[nf][0] = f2tf32(bb[0]);
                bf[nf][1] = f2tf32(bb[4 * BS_STRIDE]);
            }
#pragma unroll
            for (int mf = 0; mf < 4; mf++)
#pragma unroll
                for (int nf = 0; nf < 4; nf++)
                    mma_tf32(acc[mf][nf], af[mf], bf[nf]);
        }
        __syncthreads();
    }

#pragma unroll
    for (int mf = 0; mf < 4; mf++) {
        int row0 = rowBase + m_w + mf * 16 + g;
        int row1 = row0 + 8;
#pragma unroll
        for (int nf = 0; nf < 4; nf++) {
            int col = colBase + n_w + nf * 8 + 2 * t;
            float2 bv = *(const float2*)&bias[col];
            float v00 = acc[mf][nf][0] + bv.x;
            float v01 = acc[mf][nf][1] + bv.y;
            float v10 = acc[mf][nf][2] + bv.x;
            float v11 = acc[mf][nf][3] + bv.y;
            if (epi == 1) {
                v00 = gelu_tanh(v00); v01 = gelu_tanh(v01);
                v10 = gelu_tanh(v10); v11 = gelu_tanh(v11);
            } else if (epi == 2) {
                float2 r0 = *(const float2*)&resid[(size_t)row0 * N + col];
                float2 r1 = *(const float2*)&resid[(size_t)row1 * N + col];
                v00 += r0.x; v01 += r0.y; v10 += r1.x; v11 += r1.y;
            }
            *(float2*)&C[(size_t)row0 * N + col] = make_float2(v00, v01);
            *(float2*)&C[(size_t)row1 * N + col] = make_float2(v10, v11);
        }
    }
}

// ---------------------------------------------------------------------------
// Flash attention with tf32 tensor cores.
// BQ = BK = 128, dh = 64, 256 threads = 8 warps; warp strip = 16 rows x 128 cols.
// Online softmax fully in registers (quad shuffles). P staged via smem
// (warp-private rows -> __syncwarp only). K/V double-buffered cp.async.
// ---------------------------------------------------------------------------
#define KS_STRIDE 68      // (4g+t)%32 distinct for K b-frag reads
#define VS_STRIDE 72      // (8t+g)%32 distinct for V b-frag reads
#define PS2_STRIDE 132    // P / Q-staging region
#define F2_PS_FLOATS (128 * PS2_STRIDE)
#define F2_K_FLOATS  (128 * KS_STRIDE)
#define F2_V_FLOATS  (128 * VS_STRIDE)
#define FLASH2_SMEM_BYTES ((F2_PS_FLOATS + 2 * F2_K_FLOATS + 2 * F2_V_FLOATS) * 4)

__global__ __launch_bounds__(256, 1) void flash_tc_kernel(
    const float* __restrict__ qkv, float* __restrict__ attn_out)
{
    extern __shared__ float smf[];
    float* Ps  = smf;                        // Q staging, then P tiles
    float* Kst = smf + F2_PS_FLOATS;         // 2 stages
    float* Vst = Kst + 2 * F2_K_FLOATS;      // 2 stages

    int qi = blockIdx.x, h = blockIdx.y, bz = blockIdx.z;
    int tid = threadIdx.x;
    int lane = tid & 31;
    int warp = tid >> 5;
    int g = lane >> 2;      // 0..7
    int t = lane & 3;       // 0..3
    int m_w = warp * 16;

    size_t rowB = (size_t)bz * T_SEQ;
    const float* Qg = qkv + (rowB + (size_t)qi * 128) * D_QKV + h * D_HEAD;
    const float* Kg = qkv + rowB * D_QKV + D_MODEL     + h * D_HEAD;
    const float* Vg = qkv + rowB * D_QKV + 2 * D_MODEL + h * D_HEAD;

    // stage Q into Ps region (stride PS2_STRIDE)
#pragma unroll
    for (int i = 0; i < 8; i++) {
        int id = tid + i * 256;
        int r = id >> 4;
        int c4 = (id & 15) << 2;
        cp_async16(Ps + r * PS2_STRIDE + c4, Qg + (size_t)r * D_QKV + c4);
    }
    asm volatile("cp.async.commit_group;\n");

    auto load_kv = [&](int s, int kt) {
        const float* Kt_ = Kg + (size_t)kt * 128 * D_QKV;
        const float* Vt_ = Vg + (size_t)kt * 128 * D_QKV;
        float* ks_ = Kst + s * F2_K_FLOATS;
        float* vs_ = Vst + s * F2_V_FLOATS;
#pragma unroll
        for (int i = 0; i < 8; i++) {
            int id = tid + i * 256;
            int r = id >> 4;
            int c4 = (id & 15) << 2;
            cp_async16(ks_ + r * KS_STRIDE + c4, Kt_ + (size_t)r * D_QKV + c4);
            cp_async16(vs_ + r * VS_STRIDE + c4, Vt_ + (size_t)r * D_QKV + c4);
        }
        asm volatile("cp.async.commit_group;\n");
    };
    load_kv(0, 0);

    // wait for Q (kv0 may still be in flight)
    asm volatile("cp.async.wait_group 1;\n");
    __syncthreads();

    // pull Q fragments to registers (scaled by 1/sqrt(dh))
    uint32_t qa[8][4];
    {
        const float* q0 = Ps + (m_w + g) * PS2_STRIDE;
        const float* q1 = Ps + (m_w + g + 8) * PS2_STRIDE;
#pragma unroll
        for (int ks = 0; ks < 8; ks++) {
            qa[ks][0] = f2tf32(q0[ks * 8 + t]     * 0.125f);
            qa[ks][1] = f2tf32(q1[ks * 8 + t]     * 0.125f);
            qa[ks][2] = f2tf32(q0[ks * 8 + t + 4] * 0.125f);
            qa[ks][3] = f2tf32(q1[ks * 8 + t + 4] * 0.125f);
        }
    }

    float o[8][4];
#pragma unroll
    for (int nf = 0; nf < 8; nf++)
#pragma unroll
        for (int i = 0; i < 4; i++) o[nf][i] = 0.f;
    float m0 = -CUDART_INF_F, m1 = -CUDART_INF_F;
    float l0 = 0.f, l1 = 0.f;

    for (int kt = 0; kt < T_SEQ / 128; kt++) {
        int s = kt & 1;
        if (kt + 1 < T_SEQ / 128) {
            load_kv((kt + 1) & 1, kt + 1);
            asm volatile("cp.async.wait_group 1;\n");
        } else {
            asm volatile("cp.async.wait_group 0;\n");
        }
        __syncthreads();

        const float* ks_ = Kst + s * F2_K_FLOATS;
        const float* vs_ = Vst + s * F2_V_FLOATS;

        // ---- S = (Q*scale) @ K^T : 16 n-frags per warp ----
        float sf[16][4];
#pragma unroll
        for (int nf = 0; nf < 16; nf++) {
            sf[nf][0] = sf[nf][1] = sf[nf][2] = sf[nf][3] = 0.f;
            const float* kb = ks_ + (nf * 8 + g) * KS_STRIDE;
#pragma unroll
            for (int ksi = 0; ksi < 8; ksi++) {
                uint32_t bfr[2];
                bfr[0] = f2tf32(kb[ksi * 8 + t]);
                bfr[1] = f2tf32(kb[ksi * 8 + t + 4]);
                mma_tf32(sf[nf], qa[ksi], bfr);
            }
        }

        // ---- online softmax (registers only) ----
        float mx0 = -CUDART_INF_F, mx1 = -CUDART_INF_F;
#pragma unroll
        for (int nf = 0; nf < 16; nf++) {
            mx0 = fmaxf(mx0, fmaxf(sf[nf][0], sf[nf][1]));
            mx1 = fmaxf(mx1, fmaxf(sf[nf][2], sf[nf][3]));
        }
#pragma unroll
        for (int off = 1; off <= 2; off <<= 1) {
            mx0 = fmaxf(mx0, __shfl_xor_sync(0xffffffffu, mx0, off));
            mx1 = fmaxf(mx1, __shfl_xor_sync(0xffffffffu, mx1, off));
        }
        float mn0 = fmaxf(m0, mx0), mn1 = fmaxf(m1, mx1);
        float sc0 = __expf(m0 - mn0), sc1 = __expf(m1 - mn1);
        m0 = mn0; m1 = mn1;

        float rs0 = 0.f, rs1 = 0.f;
        float* prow0 = Ps + (m_w + g) * PS2_STRIDE;
        float* prow1 = Ps + (m_w + g + 8) * PS2_STRIDE;
#pragma unroll
        for (int nf = 0; nf < 16; nf++) {
            float p0 = __expf(sf[nf][0] - mn0);
            float p1 = __expf(sf[nf][1] - mn0);
            float p2 = __expf(sf[nf][2] - mn1);
            float p3 = __expf(sf[nf][3] - mn1);
            rs0 += p0 + p1;
            rs1 += p2 + p3;
            *(float2*)(prow0 + nf * 8 + 2 * t) = make_float2(f2tf32f(p0), f2tf32f(p1));
            *(float2*)(prow1 + nf * 8 + 2 * t) = make_float2(f2tf32f(p2), f2tf32f(p3));
        }
#pragma unroll
        for (int off = 1; off <= 2; off <<= 1) {
            rs0 += __shfl_xor_sync(0xffffffffu, rs0, off);
            rs1 += __shfl_xor_sync(0xffffffffu, rs1, off);
        }
        l0 = l0 * sc0 + rs0;
        l1 = l1 * sc1 + rs1;
#pragma unroll
        for (int nf = 0; nf < 8; nf++) {
            o[nf][0] *= sc0; o[nf][1] *= sc0;
            o[nf][2] *= sc1; o[nf][3] *= sc1;
        }
        __syncwarp();

        // ---- O += P @ V ----
#pragma unroll
        for (int ksi = 0; ksi < 16; ksi++) {
            uint32_t a[4];
            const float* pr0 = Ps + (m_w + g) * PS2_STRIDE + ksi * 8;
            const float* pr1 = pr0 + 8 * PS2_STRIDE;
            a[0] = __float_as_uint(pr0[t]);
            a[1] = __float_as_uint(pr1[t]);
            a[2] = __float_as_uint(pr0[t + 4]);
            a[3] = __float_as_uint(pr1[t + 4]);
            const float* vb = vs_ + (ksi * 8 + t) * VS_STRIDE;
#pragma unroll
            for (int nf = 0; nf < 8; nf++) {
                uint32_t bfr[2];
                bfr[0] = f2tf32(vb[nf * 8 + g]);
                bfr[1] = f2tf32(vb[4 * VS_STRIDE + nf * 8 + g]);
                mma_tf32(o[nf], a, bfr);
            }
        }
        __syncthreads();   // all warps done with K/V stage s before refill
    }

    // ---- epilogue ----
    float i0 = 1.f / l0, i1 = 1.f / l1;
    size_t tok0 = rowB + (size_t)qi * 128 + m_w + g;
    float* out0 = attn_out + tok0 * D_MODEL + h * D_HEAD;
    float* out1 = out0 + 8 * (size_t)D_MODEL;
#pragma unroll
    for (int nf = 0; nf < 8; nf++) {
        *(float2*)(out0 + nf * 8 + 2 * t) =
            make_float2(o[nf][0] * i0, o[nf][1] * i0);
        *(float2*)(out1 + nf * 8 + 2 * t) =
            make_float2(o[nf][2] * i1, o[nf][3] * i1);
    }
}

// ---------------------------------------------------------------------------
// Launch
// ---------------------------------------------------------------------------
extern "C" void kernel_launch(void* const* d_in, const int* in_sizes, int n_in,
                              void* d_out, int out_size)
{
    const float* x          = (const float*)d_in[0];
    const float* ln1_g      = (const float*)d_in[1];
    const float* ln1_b      = (const float*)d_in[2];
    const float* qkv_w      = (const float*)d_in[3];
    const float* qkv_b      = (const float*)d_in[4];
    const float* attn_out_w = (const float*)d_in[5];
    const float* attn_out_b = (const float*)d_in[6];
    const float* ln2_g      = (const float*)d_in[7];
    const float* ln2_b      = (const float*)d_in[8];
    const float* ff1_w      = (const float*)d_in[9];
    const float* ff1_b      = (const float*)d_in[10];
    const float* ff2_w      = (const float*)d_in[11];
    const float* ff2_b      = (const float*)d_in[12];
    float* out = (float*)d_out;

    void *p_h, *p_qkv, *p_attn, *p_x1, *p_mid;
    cudaGetSymbolAddress(&p_h,    g_h);
    cudaGetSymbolAddress(&p_qkv,  g_qkv);
    cudaGetSymbolAddress(&p_attn, g_attn);
    cudaGetSymbolAddress(&p_x1,   g_x1);
    cudaGetSymbolAddress(&p_mid,  g_mid);
    float* h    = (float*)p_h;
    float* qkv  = (float*)p_qkv;
    float* attn = (float*)p_attn;
    float* x1   = (float*)p_x1;
    float* mid  = (float*)p_mid;

    cudaFuncSetAttribute(flash_tc_kernel,
                         cudaFuncAttributeMaxDynamicSharedMemorySize,
                         FLASH2_SMEM_BYTES);
    cudaFuncSetAttribute(tf32_gemm_kernel,
                         cudaFuncAttributeMaxDynamicSharedMemorySize,
                         GEMM_SMEM_BYTES);

    // 1. h = LN1(x)
    ln_kernel<<<NTOK / 8, 256>>>(x, ln1_g, ln1_b, h);
    // 2. qkv = h @ qkv_w + qkv_b
    tf32_gemm_kernel<<<dim3(D_QKV / 128, NTOK / 128), 256, GEMM_SMEM_BYTES>>>(
        h, qkv_w, qkv_b, nullptr, qkv, NTOK, D_QKV, D_MODEL, 0);
    // 3. attention (tf32 tensor cores)
    flash_tc_kernel<<<dim3(T_SEQ / 128, N_HEADS, B_SZ), 256, FLASH2_SMEM_BYTES>>>(
        qkv, attn);
    // 4. x1 = x + attn @ attn_out_w + attn_out_b
    tf32_gemm_kernel<<<dim3(D_MODEL / 128, NTOK / 128), 256, GEMM_SMEM_BYTES>>>(
        attn, attn_out_w, attn_out_b, x, x1, NTOK, D_MODEL, D_MODEL, 2);
    // 5. h = LN2(x1)
    ln_kernel<<<NTOK / 8, 256>>>(x1, ln2_g, ln2_b, h);
    // 6. mid = gelu(h @ ff1_w + ff1_b)
    tf32_gemm_kernel<<<dim3(D_FF / 128, NTOK / 128), 256, GEMM_SMEM_BYTES>>>(
        h, ff1_w, ff1_b, nullptr, mid, NTOK, D_FF, D_MODEL, 1);
    // 7. out = x1 + mid @ ff2_w + ff2_b
    tf32_gemm_kernel<<<dim3(D_MODEL / 128, NTOK / 128), 256, GEMM_SMEM_BYTES>>>(
        mid, ff2_w, ff2_b, x1, out, NTOK, D_MODEL, D_FF, 2);
}

// round 4
// speedup vs baseline: 3.9902x; 1.2857x over previous
#include <cuda_runtime.h>
#include <cuda_bf16.h>
#include <math_constants.h>
#include <cstdint>
#include <cstddef>

// ---------------------------------------------------------------------------
// Problem constants
// ---------------------------------------------------------------------------
#define D_MODEL 768
#define N_HEADS 12
#define D_HEAD  64
#define D_FF    3072
#define B_SZ    4
#define T_SEQ   2048
#define NTOK    (B_SZ * T_SEQ)      // 8192
#define D_QKV   (3 * D_MODEL)       // 2304
#define LN_EPS  1e-5f

// ---------------------------------------------------------------------------
// Scratch (device globals)
// ---------------------------------------------------------------------------
__device__ float          g_h   [NTOK * D_MODEL];
__device__ __nv_bfloat16  g_qkvb[NTOK * D_QKV];     // qkv in bf16
__device__ float          g_attn[NTOK * D_MODEL];
__device__ float          g_x1  [NTOK * D_MODEL];
__device__ float          g_mid [NTOK * D_FF];

// ---------------------------------------------------------------------------
// LayerNorm: one warp per token
// ---------------------------------------------------------------------------
__global__ __launch_bounds__(256) void ln_kernel(
    const float* __restrict__ x, const float* __restrict__ g,
    const float* __restrict__ b, float* __restrict__ out)
{
    int warp = (blockIdx.x * blockDim.x + threadIdx.x) >> 5;
    int lane = threadIdx.x & 31;
    if (warp >= NTOK) return;
    const float* xr = x + (size_t)warp * D_MODEL;
    float v[24];
    float s = 0.f;
#pragma unroll
    for (int i = 0; i < 24; i++) { v[i] = xr[lane + 32 * i]; s += v[i]; }
#pragma unroll
    for (int off = 16; off > 0; off >>= 1) s += __shfl_xor_sync(0xffffffffu, s, off);
    float mu = s * (1.f / D_MODEL);
    float sq = 0.f;
#pragma unroll
    for (int i = 0; i < 24; i++) { float d = v[i] - mu; sq += d * d; }
#pragma unroll
    for (int off = 16; off > 0; off >>= 1) sq += __shfl_xor_sync(0xffffffffu, sq, off);
    float rs = rsqrtf(sq * (1.f / D_MODEL) + LN_EPS);
    float* orow = out + (size_t)warp * D_MODEL;
#pragma unroll
    for (int i = 0; i < 24; i++) {
        int c = lane + 32 * i;
        orow[c] = (v[i] - mu) * rs * g[c] + b[c];
    }
}

// ---------------------------------------------------------------------------
// GELU (tanh approx)
// ---------------------------------------------------------------------------
__device__ __forceinline__ float gelu_tanh(float x) {
    float x3 = x * x * x;
    float t = tanhf(0.7978845608028654f * (x + 0.044715f * x3));
    return 0.5f * x * (1.f + t);
}

// ---------------------------------------------------------------------------
// mma / ldmatrix helpers
// ---------------------------------------------------------------------------
__device__ __forceinline__ uint32_t f2tf32(float f) {
    uint32_t u;
    asm("cvt.rna.tf32.f32 %0, %1;" : "=r"(u) : "f"(f));
    return u;
}

__device__ __forceinline__ void mma_tf32(float c[4], const uint32_t a[4],
                                         const uint32_t b[2]) {
    asm volatile(
        "mma.sync.aligned.m16n8k8.row.col.f32.tf32.tf32.f32 "
        "{%0,%1,%2,%3}, {%4,%5,%6,%7}, {%8,%9}, {%0,%1,%2,%3};"
        : "+f"(c[0]), "+f"(c[1]), "+f"(c[2]), "+f"(c[3])
        : "r"(a[0]), "r"(a[1]), "r"(a[2]), "r"(a[3]), "r"(b[0]), "r"(b[1]));
}

__device__ __forceinline__ void mma_bf16(float c[4], const uint32_t a[4],
                                         const uint32_t b[2]) {
    asm volatile(
        "mma.sync.aligned.m16n8k16.row.col.f32.bf16.bf16.f32 "
        "{%0,%1,%2,%3}, {%4,%5,%6,%7}, {%8,%9}, {%0,%1,%2,%3};"
        : "+f"(c[0]), "+f"(c[1]), "+f"(c[2]), "+f"(c[3])
        : "r"(a[0]), "r"(a[1]), "r"(a[2]), "r"(a[3]), "r"(b[0]), "r"(b[1]));
}

__device__ __forceinline__ void ldsm_x4(uint32_t& r0, uint32_t& r1,
                                        uint32_t& r2, uint32_t& r3,
                                        const void* p) {
    uint32_t sa = (uint32_t)__cvta_generic_to_shared(p);
    asm volatile("ldmatrix.sync.aligned.m8n8.x4.shared.b16 {%0,%1,%2,%3}, [%4];"
                 : "=r"(r0), "=r"(r1), "=r"(r2), "=r"(r3) : "r"(sa));
}

__device__ __forceinline__ void ldsm_x4_t(uint32_t& r0, uint32_t& r1,
                                          uint32_t& r2, uint32_t& r3,
                                          const void* p) {
    uint32_t sa = (uint32_t)__cvta_generic_to_shared(p);
    asm volatile("ldmatrix.sync.aligned.m8n8.x4.trans.shared.b16 {%0,%1,%2,%3}, [%4];"
                 : "=r"(r0), "=r"(r1), "=r"(r2), "=r"(r3) : "r"(sa));
}

__device__ __forceinline__ void cp_async16(void* smem_dst, const void* gsrc) {
    uint32_t d = (uint32_t)__cvta_generic_to_shared(smem_dst);
    asm volatile("cp.async.ca.shared.global [%0], [%1], 16;\n" ::"r"(d), "l"(gsrc));
}

// ---------------------------------------------------------------------------
// tf32 tensor-core GEMM: C = A @ W + bias (+ epilogue)
//   epi: 0 none, 1 gelu, 2 +resid ;  out_bf16: store as bf16
// ---------------------------------------------------------------------------
#define AS_STRIDE 36
#define BS_STRIDE 136
#define AS_FLOATS (128 * AS_STRIDE)
#define BS_FLOATS (32 * BS_STRIDE)
#define GEMM_SMEM_BYTES ((2 * AS_FLOATS + 2 * BS_FLOATS) * 4)

__global__ __launch_bounds__(256, 2) void tf32_gemm_kernel(
    const float* __restrict__ A, const float* __restrict__ W,
    const float* __restrict__ bias, const float* __restrict__ resid,
    float* __restrict__ C, int M, int N, int K, int epi, int out_bf16)
{
    extern __shared__ float sm[];
    float* Asm = sm;
    float* Bsm = sm + 2 * AS_FLOATS;

    int tid = threadIdx.x;
    int lane = tid & 31;
    int warp = tid >> 5;
    int g = lane >> 2;
    int t = lane & 3;
    int m_w = (warp >> 2) * 64;
    int n_w = (warp & 3) * 32;

    int rowBase = blockIdx.y * 128;
    int colBase = blockIdx.x * 128;

    const float* Ag = A + (size_t)rowBase * K;
    const float* Wg = W + colBase;

    float acc[4][4][4];
#pragma unroll
    for (int mf = 0; mf < 4; mf++)
#pragma unroll
        for (int nf = 0; nf < 4; nf++)
#pragma unroll
            for (int i = 0; i < 4; i++) acc[mf][nf][i] = 0.f;

    int ntiles = K / 32;

    auto issue_copy = [&](int s, int kt) {
        float* as = Asm + s * AS_FLOATS;
        float* bs = Bsm + s * BS_FLOATS;
#pragma unroll
        for (int i = 0; i < 4; i++) {
            int id = tid + i * 256;
            int r = id >> 3;
            int c4 = (id & 7) << 2;
            cp_async16(as + r * AS_STRIDE + c4, Ag + (size_t)r * K + kt + c4);
        }
#pragma unroll
        for (int i = 0; i < 4; i++) {
            int id = tid + i * 256;
            int r = id >> 5;
            int c4 = (id & 31) << 2;
            cp_async16(bs + r * BS_STRIDE + c4, Wg + (size_t)(kt + r) * N + c4);
        }
        asm volatile("cp.async.commit_group;\n");
    };

    issue_copy(0, 0);

    for (int kt = 0; kt < ntiles; kt++) {
        if (kt + 1 < ntiles) {
            issue_copy((kt + 1) & 1, (kt + 1) * 32);
            asm volatile("cp.async.wait_group 1;\n");
        } else {
            asm volatile("cp.async.wait_group 0;\n");
        }
        __syncthreads();

        const float* as = Asm + (kt & 1) * AS_FLOATS;
        const float* bs = Bsm + (kt & 1) * BS_FLOATS;

#pragma unroll
        for (int ks = 0; ks < 4; ks++) {
            int k0 = ks * 8;
            uint32_t af[4][4];
            uint32_t bf[4][2];
#pragma unroll
            for (int mf = 0; mf < 4; mf++) {
                const float* base = as + (m_w + mf * 16 + g) * AS_STRIDE + k0 + t;
                af[mf][0] = f2tf32(base[0]);
                af[mf][2] = f2tf32(base[4]);
                af[mf][1] = f2tf32(base[8 * AS_STRIDE]);
                af[mf][3] = f2tf32(base[8 * AS_STRIDE + 4]);
            }
#pragma unroll
            for (int nf = 0; nf < 4; nf++) {
                const float* bb = bs + (k0 + t) * BS_STRIDE + n_w + nf * 8 + g;
                bf[nf][0] = f2tf32(bb[0]);
                bf[nf][1] = f2tf32(bb[4 * BS_STRIDE]);
            }
#pragma unroll
            for (int mf = 0; mf < 4; mf++)
#pragma unroll
                for (int nf = 0; nf < 4; nf++)
                    mma_tf32(acc[mf][nf], af[mf], bf[nf]);
        }
        __syncthreads();
    }

#pragma unroll
    for (int mf = 0; mf < 4; mf++) {
        int row0 = rowBase + m_w + mf * 16 + g;
        int row1 = row0 + 8;
#pragma unroll
        for (int nf = 0; nf < 4; nf++) {
            int col = colBase + n_w + nf * 8 + 2 * t;
            float2 bv = *(const float2*)&bias[col];
            float v00 = acc[mf][nf][0] + bv.x;
            float v01 = acc[mf][nf][1] + bv.y;
            float v10 = acc[mf][nf][2] + bv.x;
            float v11 = acc[mf][nf][3] + bv.y;
            if (epi == 1) {
                v00 = gelu_tanh(v00); v01 = gelu_tanh(v01);
                v10 = gelu_tanh(v10); v11 = gelu_tanh(v11);
            } else if (epi == 2) {
                float2 r0 = *(const float2*)&resid[(size_t)row0 * N + col];
                float2 r1 = *(const float2*)&resid[(size_t)row1 * N + col];
                v00 += r0.x; v01 += r0.y; v10 += r1.x; v11 += r1.y;
            }
            if (out_bf16) {
                __nv_bfloat16* Cb = reinterpret_cast<__nv_bfloat16*>(C);
                __nv_bfloat162 p0 = __float22bfloat162_rn(make_float2(v00, v01));
                __nv_bfloat162 p1 = __float22bfloat162_rn(make_float2(v10, v11));
                *(uint32_t*)&Cb[(size_t)row0 * N + col] = *(uint32_t*)&p0;
                *(uint32_t*)&Cb[(size_t)row1 * N + col] = *(uint32_t*)&p1;
            } else {
                *(float2*)&C[(size_t)row0 * N + col] = make_float2(v00, v01);
                *(float2*)&C[(size_t)row1 * N + col] = make_float2(v10, v11);
            }
        }
    }
}

// ---------------------------------------------------------------------------
// Flash attention, bf16 tensor cores (m16n8k16), online softmax in registers.
// 8 warps x 16 rows; K b-frags via ldmatrix, V b-frags via ldmatrix.trans;
// P stays in registers (C-frag layout == A-frag layout for bf16).
// ---------------------------------------------------------------------------
#define FST 72                       // bf16 per smem row (144B)
#define FTILE (128 * FST)            // elems per tile
#define FLASHB_SMEM_BYTES (5 * FTILE * 2)   // Q + 2K + 2V = 92160 B

__global__ __launch_bounds__(256, 1) void flash_bf16_kernel(
    const __nv_bfloat16* __restrict__ qkv, float* __restrict__ attn_out)
{
    extern __shared__ __align__(16) char smraw[];
    __nv_bfloat16* Qs = (__nv_bfloat16*)smraw;
    __nv_bfloat16* Ks = Qs + FTILE;       // 2 stages
    __nv_bfloat16* Vs = Ks + 2 * FTILE;   // 2 stages

    int qi = blockIdx.x, h = blockIdx.y, bz = blockIdx.z;
    int tid = threadIdx.x;
    int lane = tid & 31;
    int warp = tid >> 5;
    int g = lane >> 2, t = lane & 3;
    int m_w = warp * 16;

    size_t rowB = (size_t)bz * T_SEQ;
    const __nv_bfloat16* Qg = qkv + (rowB + (size_t)qi * 128) * D_QKV + h * D_HEAD;
    const __nv_bfloat16* Kg = qkv + rowB * D_QKV + D_MODEL     + h * D_HEAD;
    const __nv_bfloat16* Vg = qkv + rowB * D_QKV + 2 * D_MODEL + h * D_HEAD;

    // stage Q (group 0)
#pragma unroll
    for (int i = 0; i < 4; i++) {
        int id = tid + i * 256;
        int r = id >> 3, c = (id & 7) * 8;
        cp_async16(Qs + r * FST + c, Qg + (size_t)r * D_QKV + c);
    }
    asm volatile("cp.async.commit_group;\n");

    auto load_kv = [&](int s, int kt) {
        const __nv_bfloat16* Kt_ = Kg + (size_t)kt * 128 * D_QKV;
        const __nv_bfloat16* Vt_ = Vg + (size_t)kt * 128 * D_QKV;
        __nv_bfloat16* ks_ = Ks + s * FTILE;
        __nv_bfloat16* vs_ = Vs + s * FTILE;
#pragma unroll
        for (int i = 0; i < 4; i++) {
            int id = tid + i * 256;
            int r = id >> 3, c = (id & 7) * 8;
            cp_async16(ks_ + r * FST + c, Kt_ + (size_t)r * D_QKV + c);
            cp_async16(vs_ + r * FST + c, Vt_ + (size_t)r * D_QKV + c);
        }
        asm volatile("cp.async.commit_group;\n");
    };
    load_kv(0, 0);

    asm volatile("cp.async.wait_group 1;\n");   // Q ready (FIFO order)
    __syncthreads();

    // Q a-fragments, scaled by 1/sqrt(dh)=0.125 (exact in bf16)
    uint32_t qa[4][4];
    {
        const __nv_bfloat16* q0 = Qs + (m_w + g) * FST;
        const __nv_bfloat16* q1 = q0 + 8 * FST;
        __nv_bfloat162 sc2 = __float2bfloat162_rn(0.125f);
#pragma unroll
        for (int kb = 0; kb < 4; kb++) {
            __nv_bfloat162 v;
            v = __hmul2(*(const __nv_bfloat162*)(q0 + kb * 16 + 2 * t), sc2);
            qa[kb][0] = *(uint32_t*)&v;
            v = __hmul2(*(const __nv_bfloat162*)(q1 + kb * 16 + 2 * t), sc2);
            qa[kb][1] = *(uint32_t*)&v;
            v = __hmul2(*(const __nv_bfloat162*)(q0 + kb * 16 + 2 * t + 8), sc2);
            qa[kb][2] = *(uint32_t*)&v;
            v = __hmul2(*(const __nv_bfloat162*)(q1 + kb * 16 + 2 * t + 8), sc2);
            qa[kb][3] = *(uint32_t*)&v;
        }
    }

    float o[8][4];
#pragma unroll
    for (int nf = 0; nf < 8; nf++)
#pragma unroll
        for (int i = 0; i < 4; i++) o[nf][i] = 0.f;
    float m0 = -CUDART_INF_F, m1 = -CUDART_INF_F;
    float l0 = 0.f, l1 = 0.f;

    for (int kt = 0; kt < T_SEQ / 128; kt++) {
        if (kt + 1 < T_SEQ / 128) {
            load_kv((kt + 1) & 1, kt + 1);
            asm volatile("cp.async.wait_group 1;\n");
        } else {
            asm volatile("cp.async.wait_group 0;\n");
        }
        __syncthreads();

        const __nv_bfloat16* ks_ = Ks + (kt & 1) * FTILE;
        const __nv_bfloat16* vs_ = Vs + (kt & 1) * FTILE;

        // ---- S = (Q*scale) @ K^T ----
        float sf[16][4];
#pragma unroll
        for (int nf = 0; nf < 16; nf++) {
            sf[nf][0] = sf[nf][1] = sf[nf][2] = sf[nf][3] = 0.f;
            uint32_t b0[4], b1[4];
            const __nv_bfloat16* kp = ks_ + (nf * 8 + (lane & 7)) * FST + (lane >> 3) * 8;
            ldsm_x4(b0[0], b0[1], b0[2], b0[3], kp);
            ldsm_x4(b1[0], b1[1], b1[2], b1[3], kp + 32);
            { uint32_t bb[2] = {b0[0], b0[1]}; mma_bf16(sf[nf], qa[0], bb); }
            { uint32_t bb[2] = {b0[2], b0[3]}; mma_bf16(sf[nf], qa[1], bb); }
            { uint32_t bb[2] = {b1[0], b1[1]}; mma_bf16(sf[nf], qa[2], bb); }
            { uint32_t bb[2] = {b1[2], b1[3]}; mma_bf16(sf[nf], qa[3], bb); }
        }

        // ---- online softmax (registers only) ----
        float mx0 = -CUDART_INF_F, mx1 = -CUDART_INF_F;
#pragma unroll
        for (int nf = 0; nf < 16; nf++) {
            mx0 = fmaxf(mx0, fmaxf(sf[nf][0], sf[nf][1]));
            mx1 = fmaxf(mx1, fmaxf(sf[nf][2], sf[nf][3]));
        }
#pragma unroll
        for (int off = 1; off <= 2; off <<= 1) {
            mx0 = fmaxf(mx0, __shfl_xor_sync(0xffffffffu, mx0, off));
            mx1 = fmaxf(mx1, __shfl_xor_sync(0xffffffffu, mx1, off));
        }
        float mn0 = fmaxf(m0, mx0), mn1 = fmaxf(m1, mx1);
        float sc0 = __expf(m0 - mn0), sc1 = __expf(m1 - mn1);
        m0 = mn0; m1 = mn1;

        float rs0 = 0.f, rs1 = 0.f;
#pragma unroll
        for (int nf = 0; nf < 16; nf++) {
            sf[nf][0] = __expf(sf[nf][0] - mn0);
            sf[nf][1] = __expf(sf[nf][1] - mn0);
            sf[nf][2] = __expf(sf[nf][2] - mn1);
            sf[nf][3] = __expf(sf[nf][3] - mn1);
            rs0 += sf[nf][0] + sf[nf][1];
            rs1 += sf[nf][2] + sf[nf][3];
        }
#pragma unroll
        for (int off = 1; off <= 2; off <<= 1) {
            rs0 += __shfl_xor_sync(0xffffffffu, rs0, off);
            rs1 += __shfl_xor_sync(0xffffffffu, rs1, off);
        }
        l0 = l0 * sc0 + rs0;
        l1 = l1 * sc1 + rs1;
#pragma unroll
        for (int nf = 0; nf < 8; nf++) {
            o[nf][0] *= sc0; o[nf][1] *= sc0;
            o[nf][2] *= sc1; o[nf][3] *= sc1;
        }

        // ---- O += P @ V  (P a-frags built in registers) ----
#pragma unroll
        for (int kb = 0; kb < 8; kb++) {
            uint32_t a[4];
            __nv_bfloat162 p;
            p = __float22bfloat162_rn(make_float2(sf[2*kb][0],   sf[2*kb][1]));
            a[0] = *(uint32_t*)&p;
            p = __float22bfloat162_rn(make_float2(sf[2*kb][2],   sf[2*kb][3]));
            a[1] = *(uint32_t*)&p;
            p = __float22bfloat162_rn(make_float2(sf[2*kb+1][0], sf[2*kb+1][1]));
            a[2] = *(uint32_t*)&p;
            p = __float22bfloat162_rn(make_float2(sf[2*kb+1][2], sf[2*kb+1][3]));
            a[3] = *(uint32_t*)&p;

            const __nv_bfloat16* vp = vs_ + (kb * 16 + (lane & 15)) * FST + (lane >> 4) * 8;
#pragma unroll
            for (int nfp = 0; nfp < 4; nfp++) {
                uint32_t v0, v1, v2, v3;
                ldsm_x4_t(v0, v1, v2, v3, vp + nfp * 16);
                { uint32_t bb[2] = {v0, v1}; mma_bf16(o[2*nfp],     a, bb); }
                { uint32_t bb[2] = {v2, v3}; mma_bf16(o[2*nfp + 1], a, bb); }
            }
        }
        __syncthreads();   // stage reuse barrier
    }

    // ---- epilogue: O / l -> fp32 attn ----
    float i0 = 1.f / l0, i1 = 1.f / l1;
    size_t tok0 = rowB + (size_t)qi * 128 + m_w + g;
    float* out0 = attn_out + tok0 * D_MODEL + h * D_HEAD;
    float* out1 = out0 + 8 * (size_t)D_MODEL;
#pragma unroll
    for (int nf = 0; nf < 8; nf++) {
        *(float2*)(out0 + nf * 8 + 2 * t) =
            make_float2(o[nf][0] * i0, o[nf][1] * i0);
        *(float2*)(out1 + nf * 8 + 2 * t) =
            make_float2(o[nf][2] * i1, o[nf][3] * i1);
    }
}

// ---------------------------------------------------------------------------
// Launch
// ---------------------------------------------------------------------------
extern "C" void kernel_launch(void* const* d_in, const int* in_sizes, int n_in,
                              void* d_out, int out_size)
{
    const float* x          = (const float*)d_in[0];
    const float* ln1_g      = (const float*)d_in[1];
    const float* ln1_b      = (const float*)d_in[2];
    const float* qkv_w      = (const float*)d_in[3];
    const float* qkv_b      = (const float*)d_in[4];
    const float* attn_out_w = (const float*)d_in[5];
    const float* attn_out_b = (const float*)d_in[6];
    const float* ln2_g      = (const float*)d_in[7];
    const float* ln2_b      = (const float*)d_in[8];
    const float* ff1_w      = (const float*)d_in[9];
    const float* ff1_b      = (const float*)d_in[10];
    const float* ff2_w      = (const float*)d_in[11];
    const float* ff2_b      = (const float*)d_in[12];
    float* out = (float*)d_out;

    void *p_h, *p_qkvb, *p_attn, *p_x1, *p_mid;
    cudaGetSymbolAddress(&p_h,    g_h);
    cudaGetSymbolAddress(&p_qkvb, g_qkvb);
    cudaGetSymbolAddress(&p_attn, g_attn);
    cudaGetSymbolAddress(&p_x1,   g_x1);
    cudaGetSymbolAddress(&p_mid,  g_mid);
    float* h            = (float*)p_h;
    __nv_bfloat16* qkvb = (__nv_bfloat16*)p_qkvb;
    float* attn         = (float*)p_attn;
    float* x1           = (float*)p_x1;
    float* mid          = (float*)p_mid;

    cudaFuncSetAttribute(flash_bf16_kernel,
                         cudaFuncAttributeMaxDynamicSharedMemorySize,
                         FLASHB_SMEM_BYTES);
    cudaFuncSetAttribute(tf32_gemm_kernel,
                         cudaFuncAttributeMaxDynamicSharedMemorySize,
                         GEMM_SMEM_BYTES);

    // 1. h = LN1(x)
    ln_kernel<<<NTOK / 8, 256>>>(x, ln1_g, ln1_b, h);
    // 2. qkv(bf16) = h @ qkv_w + qkv_b
    tf32_gemm_kernel<<<dim3(D_QKV / 128, NTOK / 128), 256, GEMM_SMEM_BYTES>>>(
        h, qkv_w, qkv_b, nullptr, (float*)qkvb, NTOK, D_QKV, D_MODEL, 0, 1);
    // 3. attention (bf16 tensor cores)
    flash_bf16_kernel<<<dim3(T_SEQ / 128, N_HEADS, B_SZ), 256, FLASHB_SMEM_BYTES>>>(
        qkvb, attn);
    // 4. x1 = x + attn @ attn_out_w + attn_out_b
    tf32_gemm_kernel<<<dim3(D_MODEL / 128, NTOK / 128), 256, GEMM_SMEM_BYTES>>>(
        attn, attn_out_w, attn_out_b, x, x1, NTOK, D_MODEL, D_MODEL, 2, 0);
    // 5. h = LN2(x1)
    ln_kernel<<<NTOK / 8, 256>>>(x1, ln2_g, ln2_b, h);
    // 6. mid = gelu(h @ ff1_w + ff1_b)
    tf32_gemm_kernel<<<dim3(D_FF / 128, NTOK / 128), 256, GEMM_SMEM_BYTES>>>(
        h, ff1_w, ff1_b, nullptr, mid, NTOK, D_FF, D_MODEL, 1, 0);
    // 7. out = x1 + mid @ ff2_w + ff2_b
    tf32_gemm_kernel<<<dim3(D_MODEL / 128, NTOK / 128), 256, GEMM_SMEM_BYTES>>>(
        mid, ff2_w, ff2_b, x1, out, NTOK, D_MODEL, D_FF, 2, 0);
}

// round 5
// speedup vs baseline: 4.1072x; 1.0293x over previous
#include <cuda_runtime.h>
#include <cuda_bf16.h>
#include <math_constants.h>
#include <cstdint>
#include <cstddef>

// ---------------------------------------------------------------------------
// Problem constants
// ---------------------------------------------------------------------------
#define D_MODEL 768
#define N_HEADS 12
#define D_HEAD  64
#define D_FF    3072
#define B_SZ    4
#define T_SEQ   2048
#define NTOK    (B_SZ * T_SEQ)      // 8192
#define D_QKV   (3 * D_MODEL)       // 2304
#define LN_EPS  1e-5f

#define W_QKV_N   (D_MODEL * D_QKV)
#define W_AO_N    (D_MODEL * D_MODEL)
#define W_FF1_N   (D_MODEL * D_FF)
#define W_FF2_N   (D_FF * D_MODEL)

// ---------------------------------------------------------------------------
// Scratch (device globals)
// ---------------------------------------------------------------------------
__device__ float          g_h   [NTOK * D_MODEL];
__device__ __nv_bfloat16  g_qkvb[NTOK * D_QKV];
__device__ float          g_attn[NTOK * D_MODEL];
__device__ float          g_x1  [NTOK * D_MODEL];
__device__ float          g_mid [NTOK * D_FF];
__device__ float          g_w   [W_QKV_N + W_AO_N + W_FF1_N + W_FF2_N]; // tf32-rounded weights

// ---------------------------------------------------------------------------
// tf32 helpers
// ---------------------------------------------------------------------------
__device__ __forceinline__ uint32_t f2tf32(float f) {
    uint32_t u;
    asm("cvt.rna.tf32.f32 %0, %1;" : "=r"(u) : "f"(f));
    return u;
}
__device__ __forceinline__ float f2tf32f(float f) {
    uint32_t u = f2tf32(f);
    return __uint_as_float(u);
}

// round an array to tf32 (pre-pass for weights)
__global__ __launch_bounds__(256) void round_tf32_kernel(
    const float* __restrict__ src, float* __restrict__ dst, int n)
{
    int i = (blockIdx.x * blockDim.x + threadIdx.x) * 4;
    if (i >= n) return;
    float4 v = *(const float4*)(src + i);
    v.x = f2tf32f(v.x); v.y = f2tf32f(v.y);
    v.z = f2tf32f(v.z); v.w = f2tf32f(v.w);
    *(float4*)(dst + i) = v;
}

// ---------------------------------------------------------------------------
// LayerNorm: one warp per token; output rounded to tf32 (feeds MMA A)
// ---------------------------------------------------------------------------
__global__ __launch_bounds__(256) void ln_kernel(
    const float* __restrict__ x, const float* __restrict__ g,
    const float* __restrict__ b, float* __restrict__ out)
{
    int warp = (blockIdx.x * blockDim.x + threadIdx.x) >> 5;
    int lane = threadIdx.x & 31;
    if (warp >= NTOK) return;
    const float* xr = x + (size_t)warp * D_MODEL;
    float v[24];
    float s = 0.f;
#pragma unroll
    for (int i = 0; i < 24; i++) { v[i] = xr[lane + 32 * i]; s += v[i]; }
#pragma unroll
    for (int off = 16; off > 0; off >>= 1) s += __shfl_xor_sync(0xffffffffu, s, off);
    float mu = s * (1.f / D_MODEL);
    float sq = 0.f;
#pragma unroll
    for (int i = 0; i < 24; i++) { float d = v[i] - mu; sq += d * d; }
#pragma unroll
    for (int off = 16; off > 0; off >>= 1) sq += __shfl_xor_sync(0xffffffffu, sq, off);
    float rs = rsqrtf(sq * (1.f / D_MODEL) + LN_EPS);
    float* orow = out + (size_t)warp * D_MODEL;
#pragma unroll
    for (int i = 0; i < 24; i++) {
        int c = lane + 32 * i;
        orow[c] = f2tf32f((v[i] - mu) * rs * g[c] + b[c]);
    }
}

// ---------------------------------------------------------------------------
// GELU (tanh approx)
// ---------------------------------------------------------------------------
__device__ __forceinline__ float gelu_tanh(float x) {
    float x3 = x * x * x;
    float t = tanhf(0.7978845608028654f * (x + 0.044715f * x3));
    return 0.5f * x * (1.f + t);
}

// ---------------------------------------------------------------------------
// mma / ldmatrix helpers
// ---------------------------------------------------------------------------
__device__ __forceinline__ void mma_tf32(float c[4], const uint32_t a[4],
                                         const uint32_t b[2]) {
    asm volatile(
        "mma.sync.aligned.m16n8k8.row.col.f32.tf32.tf32.f32 "
        "{%0,%1,%2,%3}, {%4,%5,%6,%7}, {%8,%9}, {%0,%1,%2,%3};"
        : "+f"(c[0]), "+f"(c[1]), "+f"(c[2]), "+f"(c[3])
        : "r"(a[0]), "r"(a[1]), "r"(a[2]), "r"(a[3]), "r"(b[0]), "r"(b[1]));
}

__device__ __forceinline__ void mma_bf16(float c[4], const uint32_t a[4],
                                         const uint32_t b[2]) {
    asm volatile(
        "mma.sync.aligned.m16n8k16.row.col.f32.bf16.bf16.f32 "
        "{%0,%1,%2,%3}, {%4,%5,%6,%7}, {%8,%9}, {%0,%1,%2,%3};"
        : "+f"(c[0]), "+f"(c[1]), "+f"(c[2]), "+f"(c[3])
        : "r"(a[0]), "r"(a[1]), "r"(a[2]), "r"(a[3]), "r"(b[0]), "r"(b[1]));
}

__device__ __forceinline__ void ldsm_x4(uint32_t& r0, uint32_t& r1,
                                        uint32_t& r2, uint32_t& r3,
                                        const void* p) {
    uint32_t sa = (uint32_t)__cvta_generic_to_shared(p);
    asm volatile("ldmatrix.sync.aligned.m8n8.x4.shared.b16 {%0,%1,%2,%3}, [%4];"
                 : "=r"(r0), "=r"(r1), "=r"(r2), "=r"(r3) : "r"(sa));
}

__device__ __forceinline__ void ldsm_x4_t(uint32_t& r0, uint32_t& r1,
                                          uint32_t& r2, uint32_t& r3,
                                          const void* p) {
    uint32_t sa = (uint32_t)__cvta_generic_to_shared(p);
    asm volatile("ldmatrix.sync.aligned.m8n8.x4.trans.shared.b16 {%0,%1,%2,%3}, [%4];"
                 : "=r"(r0), "=r"(r1), "=r"(r2), "=r"(r3) : "r"(sa));
}

__device__ __forceinline__ void cp_async16(void* smem_dst, const void* gsrc) {
    uint32_t d = (uint32_t)__cvta_generic_to_shared(smem_dst);
    asm volatile("cp.async.ca.shared.global [%0], [%1], 16;\n" ::"r"(d), "l"(gsrc));
}

// ---------------------------------------------------------------------------
// tf32 tensor-core GEMM, zero-CVT: all operands pre-rounded to tf32.
//   epi: 0 none, 1 gelu (+round to tf32), 2 +resid ;  out_bf16: store bf16
// ---------------------------------------------------------------------------
#define AS_STRIDE 36
#define BS_STRIDE 136
#define AS_FLOATS (128 * AS_STRIDE)
#define BS_FLOATS (32 * BS_STRIDE)
#define GEMM_SMEM_BYTES ((2 * AS_FLOATS + 2 * BS_FLOATS) * 4)

__global__ __launch_bounds__(256, 2) void tf32_gemm_kernel(
    const float* __restrict__ A, const float* __restrict__ W,
    const float* __restrict__ bias, const float* __restrict__ resid,
    float* __restrict__ C, int M, int N, int K, int epi, int out_bf16)
{
    extern __shared__ float sm[];
    float* Asm = sm;
    float* Bsm = sm + 2 * AS_FLOATS;

    int tid = threadIdx.x;
    int lane = tid & 31;
    int warp = tid >> 5;
    int g = lane >> 2;
    int t = lane & 3;
    int m_w = (warp >> 2) * 64;
    int n_w = (warp & 3) * 32;

    int rowBase = blockIdx.y * 128;
    int colBase = blockIdx.x * 128;

    const float* Ag = A + (size_t)rowBase * K;
    const float* Wg = W + colBase;

    float acc[4][4][4];
#pragma unroll
    for (int mf = 0; mf < 4; mf++)
#pragma unroll
        for (int nf = 0; nf < 4; nf++)
#pragma unroll
            for (int i = 0; i < 4; i++) acc[mf][nf][i] = 0.f;

    int ntiles = K / 32;

    auto issue_copy = [&](int s, int kt) {
        float* as = Asm + s * AS_FLOATS;
        float* bs = Bsm + s * BS_FLOATS;
#pragma unroll
        for (int i = 0; i < 4; i++) {
            int id = tid + i * 256;
            int r = id >> 3;
            int c4 = (id & 7) << 2;
            cp_async16(as + r * AS_STRIDE + c4, Ag + (size_t)r * K + kt + c4);
        }
#pragma unroll
        for (int i = 0; i < 4; i++) {
            int id = tid + i * 256;
            int r = id >> 5;
            int c4 = (id & 31) << 2;
            cp_async16(bs + r * BS_STRIDE + c4, Wg + (size_t)(kt + r) * N + c4);
        }
        asm volatile("cp.async.commit_group;\n");
    };

    issue_copy(0, 0);

    for (int kt = 0; kt < ntiles; kt++) {
        if (kt + 1 < ntiles) {
            issue_copy((kt + 1) & 1, (kt + 1) * 32);
            asm volatile("cp.async.wait_group 1;\n");
        } else {
            asm volatile("cp.async.wait_group 0;\n");
        }
        __syncthreads();

        const float* as = Asm + (kt & 1) * AS_FLOATS;
        const float* bs = Bsm + (kt & 1) * BS_FLOATS;

#pragma unroll
        for (int ks = 0; ks < 4; ks++) {
            int k0 = ks * 8;
            uint32_t af[4][4];
            uint32_t bf[4][2];
#pragma unroll
            for (int mf = 0; mf < 4; mf++) {
                const float* base = as + (m_w + mf * 16 + g) * AS_STRIDE + k0 + t;
                af[mf][0] = __float_as_uint(base[0]);
                af[mf][2] = __float_as_uint(base[4]);
                af[mf][1] = __float_as_uint(base[8 * AS_STRIDE]);
                af[mf][3] = __float_as_uint(base[8 * AS_STRIDE + 4]);
            }
#pragma unroll
            for (int nf = 0; nf < 4; nf++) {
                const float* bb = bs + (k0 + t) * BS_STRIDE + n_w + nf * 8 + g;
                bf[nf][0] = __float_as_uint(bb[0]);
                bf[nf][1] = __float_as_uint(bb[4 * BS_STRIDE]);
            }
#pragma unroll
            for (int mf = 0; mf < 4; mf++)
#pragma unroll
                for (int nf = 0; nf < 4; nf++)
                    mma_tf32(acc[mf][nf], af[mf], bf[nf]);
        }
        __syncthreads();
    }

#pragma unroll
    for (int mf = 0; mf < 4; mf++) {
        int row0 = rowBase + m_w + mf * 16 + g;
        int row1 = row0 + 8;
#pragma unroll
        for (int nf = 0; nf < 4; nf++) {
            int col = colBase + n_w + nf * 8 + 2 * t;
            float2 bv = *(const float2*)&bias[col];
            float v00 = acc[mf][nf][0] + bv.x;
            float v01 = acc[mf][nf][1] + bv.y;
            float v10 = acc[mf][nf][2] + bv.x;
            float v11 = acc[mf][nf][3] + bv.y;
            if (epi == 1) {
                v00 = f2tf32f(gelu_tanh(v00)); v01 = f2tf32f(gelu_tanh(v01));
                v10 = f2tf32f(gelu_tanh(v10)); v11 = f2tf32f(gelu_tanh(v11));
            } else if (epi == 2) {
                float2 r0 = *(const float2*)&resid[(size_t)row0 * N + col];
                float2 r1 = *(const float2*)&resid[(size_t)row1 * N + col];
                v00 += r0.x; v01 += r0.y; v10 += r1.x; v11 += r1.y;
            }
            if (out_bf16) {
                __nv_bfloat16* Cb = reinterpret_cast<__nv_bfloat16*>(C);
                __nv_bfloat162 p0 = __float22bfloat162_rn(make_float2(v00, v01));
                __nv_bfloat162 p1 = __float22bfloat162_rn(make_float2(v10, v11));
                *(uint32_t*)&Cb[(size_t)row0 * N + col] = *(uint32_t*)&p0;
                *(uint32_t*)&Cb[(size_t)row1 * N + col] = *(uint32_t*)&p1;
            } else {
                *(float2*)&C[(size_t)row0 * N + col] = make_float2(v00, v01);
                *(float2*)&C[(size_t)row1 * N + col] = make_float2(v10, v11);
            }
        }
    }
}

// ---------------------------------------------------------------------------
// Flash attention, bf16 mma, BK=64 -> 55KB smem -> 2 CTAs/SM.
// 8 warps x 16 Q rows; online softmax in registers; P never hits smem.
// Output rounded to tf32 (feeds attn_out GEMM A).
// ---------------------------------------------------------------------------
#define FST 72                         // bf16 per smem row (144B)
#define FQ_ELEMS (128 * FST)
#define FKV_ELEMS (64 * FST)
#define FLASHB_SMEM_BYTES ((FQ_ELEMS + 4 * FKV_ELEMS) * 2)   // 55296 B

__global__ __launch_bounds__(256, 2) void flash_bf16_kernel(
    const __nv_bfloat16* __restrict__ qkv, float* __restrict__ attn_out)
{
    extern __shared__ __align__(16) char smraw[];
    __nv_bfloat16* Qs = (__nv_bfloat16*)smraw;
    __nv_bfloat16* Ks = Qs + FQ_ELEMS;        // 2 stages of 64 rows
    __nv_bfloat16* Vs = Ks + 2 * FKV_ELEMS;   // 2 stages of 64 rows

    int qi = blockIdx.x, h = blockIdx.y, bz = blockIdx.z;
    int tid = threadIdx.x;
    int lane = tid & 31;
    int warp = tid >> 5;
    int g = lane >> 2, t = lane & 3;
    int m_w = warp * 16;

    size_t rowB = (size_t)bz * T_SEQ;
    const __nv_bfloat16* Qg = qkv + (rowB + (size_t)qi * 128) * D_QKV + h * D_HEAD;
    const __nv_bfloat16* Kg = qkv + rowB * D_QKV + D_MODEL     + h * D_HEAD;
    const __nv_bfloat16* Vg = qkv + rowB * D_QKV + 2 * D_MODEL + h * D_HEAD;

    // stage Q: 128 rows x 64 cols
#pragma unroll
    for (int i = 0; i < 4; i++) {
        int id = tid + i * 256;
        int r = id >> 3, c = (id & 7) * 8;
        cp_async16(Qs + r * FST + c, Qg + (size_t)r * D_QKV + c);
    }
    asm volatile("cp.async.commit_group;\n");

    auto load_kv = [&](int s, int kt) {
        const __nv_bfloat16* Kt_ = Kg + (size_t)kt * 64 * D_QKV;
        const __nv_bfloat16* Vt_ = Vg + (size_t)kt * 64 * D_QKV;
        __nv_bfloat16* ks_ = Ks + s * FKV_ELEMS;
        __nv_bfloat16* vs_ = Vs + s * FKV_ELEMS;
#pragma unroll
        for (int i = 0; i < 2; i++) {
            int id = tid + i * 256;
            int r = id >> 3, c = (id & 7) * 8;
            cp_async16(ks_ + r * FST + c, Kt_ + (size_t)r * D_QKV + c);
            cp_async16(vs_ + r * FST + c, Vt_ + (size_t)r * D_QKV + c);
        }
        asm volatile("cp.async.commit_group;\n");
    };
    load_kv(0, 0);

    asm volatile("cp.async.wait_group 1;\n");   // Q ready
    __syncthreads();

    // Q a-fragments, scaled by 0.125 (exact in bf16)
    uint32_t qa[4][4];
    {
        const __nv_bfloat16* q0 = Qs + (m_w + g) * FST;
        const __nv_bfloat16* q1 = q0 + 8 * FST;
        __nv_bfloat162 sc2 = __float2bfloat162_rn(0.125f);
#pragma unroll
        for (int kb = 0; kb < 4; kb++) {
            __nv_bfloat162 v;
            v = __hmul2(*(const __nv_bfloat162*)(q0 + kb * 16 + 2 * t), sc2);
            qa[kb][0] = *(uint32_t*)&v;
            v = __hmul2(*(const __nv_bfloat162*)(q1 + kb * 16 + 2 * t), sc2);
            qa[kb][1] = *(uint32_t*)&v;
            v = __hmul2(*(const __nv_bfloat162*)(q0 + kb * 16 + 2 * t + 8), sc2);
            qa[kb][2] = *(uint32_t*)&v;
            v = __hmul2(*(const __nv_bfloat162*)(q1 + kb * 16 + 2 * t + 8), sc2);
            qa[kb][3] = *(uint32_t*)&v;
        }
    }

    float o[8][4];
#pragma unroll
    for (int nf = 0; nf < 8; nf++)
#pragma unroll
        for (int i = 0; i < 4; i++) o[nf][i] = 0.f;
    float m0 = -CUDART_INF_F, m1 = -CUDART_INF_F;
    float l0 = 0.f, l1 = 0.f;

    const int NITER = T_SEQ / 64;   // 32
    for (int kt = 0; kt < NITER; kt++) {
        if (kt + 1 < NITER) {
            load_kv((kt + 1) & 1, kt + 1);
            asm volatile("cp.async.wait_group 1;\n");
        } else {
            asm volatile("cp.async.wait_group 0;\n");
        }
        __syncthreads();

        const __nv_bfloat16* ks_ = Ks + (kt & 1) * FKV_ELEMS;
        const __nv_bfloat16* vs_ = Vs + (kt & 1) * FKV_ELEMS;

        // ---- S = (Q*scale) @ K^T : 8 n-frags of 8 cols ----
        float sf[8][4];
#pragma unroll
        for (int nf = 0; nf < 8; nf++) {
            sf[nf][0] = sf[nf][1] = sf[nf][2] = sf[nf][3] = 0.f;
            uint32_t b0[4], b1[4];
            const __nv_bfloat16* kp = ks_ + (nf * 8 + (lane & 7)) * FST + (lane >> 3) * 8;
            ldsm_x4(b0[0], b0[1], b0[2], b0[3], kp);
            ldsm_x4(b1[0], b1[1], b1[2], b1[3], kp + 32);
            { uint32_t bb[2] = {b0[0], b0[1]}; mma_bf16(sf[nf], qa[0], bb); }
            { uint32_t bb[2] = {b0[2], b0[3]}; mma_bf16(sf[nf], qa[1], bb); }
            { uint32_t bb[2] = {b1[0], b1[1]}; mma_bf16(sf[nf], qa[2], bb); }
            { uint32_t bb[2] = {b1[2], b1[3]}; mma_bf16(sf[nf], qa[3], bb); }
        }

        // ---- online softmax (registers only) ----
        float mx0 = -CUDART_INF_F, mx1 = -CUDART_INF_F;
#pragma unroll
        for (int nf = 0; nf < 8; nf++) {
            mx0 = fmaxf(mx0, fmaxf(sf[nf][0], sf[nf][1]));
            mx1 = fmaxf(mx1, fmaxf(sf[nf][2], sf[nf][3]));
        }
#pragma unroll
        for (int off = 1; off <= 2; off <<= 1) {
            mx0 = fmaxf(mx0, __shfl_xor_sync(0xffffffffu, mx0, off));
            mx1 = fmaxf(mx1, __shfl_xor_sync(0xffffffffu, mx1, off));
        }
        float mn0 = fmaxf(m0, mx0), mn1 = fmaxf(m1, mx1);
        float sc0 = __expf(m0 - mn0), sc1 = __expf(m1 - mn1);
        m0 = mn0; m1 = mn1;

        float rs0 = 0.f, rs1 = 0.f;
#pragma unroll
        for (int nf = 0; nf < 8; nf++) {
            sf[nf][0] = __expf(sf[nf][0] - mn0);
            sf[nf][1] = __expf(sf[nf][1] - mn0);
            sf[nf][2] = __expf(sf[nf][2] - mn1);
            sf[nf][3] = __expf(sf[nf][3] - mn1);
            rs0 += sf[nf][0] + sf[nf][1];
            rs1 += sf[nf][2] + sf[nf][3];
        }
#pragma unroll
        for (int off = 1; off <= 2; off <<= 1) {
            rs0 += __shfl_xor_sync(0xffffffffu, rs0, off);
            rs1 += __shfl_xor_sync(0xffffffffu, rs1, off);
        }
        l0 = l0 * sc0 + rs0;
        l1 = l1 * sc1 + rs1;
#pragma unroll
        for (int nf = 0; nf < 8; nf++) {
            o[nf][0] *= sc0; o[nf][1] *= sc0;
            o[nf][2] *= sc1; o[nf][3] *= sc1;
        }

        // ---- O += P @ V : P a-frags built in registers ----
#pragma unroll
        for (int kb = 0; kb < 4; kb++) {
            uint32_t a[4];
            __nv_bfloat162 p;
            p = __float22bfloat162_rn(make_float2(sf[2*kb][0],   sf[2*kb][1]));
            a[0] = *(uint32_t*)&p;
            p = __float22bfloat162_rn(make_float2(sf[2*kb][2],   sf[2*kb][3]));
            a[1] = *(uint32_t*)&p;
            p = __float22bfloat162_rn(make_float2(sf[2*kb+1][0], sf[2*kb+1][1]));
            a[2] = *(uint32_t*)&p;
            p = __float22bfloat162_rn(make_float2(sf[2*kb+1][2], sf[2*kb+1][3]));
            a[3] = *(uint32_t*)&p;

            const __nv_bfloat16* vp = vs_ + (kb * 16 + (lane & 15)) * FST + (lane >> 4) * 8;
#pragma unroll
            for (int nfp = 0; nfp < 4; nfp++) {
                uint32_t v0, v1, v2, v3;
                ldsm_x4_t(v0, v1, v2, v3, vp + nfp * 16);
                { uint32_t bb[2] = {v0, v1}; mma_bf16(o[2*nfp],     a, bb); }
                { uint32_t bb[2] = {v2, v3}; mma_bf16(o[2*nfp + 1], a, bb); }
            }
        }
        __syncthreads();   // stage reuse barrier
    }

    // ---- epilogue: O / l, rounded to tf32 (feeds next GEMM A) ----
    float i0 = 1.f / l0, i1 = 1.f / l1;
    size_t tok0 = rowB + (size_t)qi * 128 + m_w + g;
    float* out0 = attn_out + tok0 * D_MODEL + h * D_HEAD;
    float* out1 = out0 + 8 * (size_t)D_MODEL;
#pragma unroll
    for (int nf = 0; nf < 8; nf++) {
        *(float2*)(out0 + nf * 8 + 2 * t) =
            make_float2(f2tf32f(o[nf][0] * i0), f2tf32f(o[nf][1] * i0));
        *(float2*)(out1 + nf * 8 + 2 * t) =
            make_float2(f2tf32f(o[nf][2] * i1), f2tf32f(o[nf][3] * i1));
    }
}

// ---------------------------------------------------------------------------
// Launch
// ---------------------------------------------------------------------------
extern "C" void kernel_launch(void* const* d_in, const int* in_sizes, int n_in,
                              void* d_out, int out_size)
{
    const float* x          = (const float*)d_in[0];
    const float* ln1_g      = (const float*)d_in[1];
    const float* ln1_b      = (const float*)d_in[2];
    const float* qkv_w      = (const float*)d_in[3];
    const float* qkv_b      = (const float*)d_in[4];
    const float* attn_out_w = (const float*)d_in[5];
    const float* attn_out_b = (const float*)d_in[6];
    const float* ln2_g      = (const float*)d_in[7];
    const float* ln2_b      = (const float*)d_in[8];
    const float* ff1_w      = (const float*)d_in[9];
    const float* ff1_b      = (const float*)d_in[10];
    const float* ff2_w      = (const float*)d_in[11];
    const float* ff2_b      = (const float*)d_in[12];
    float* out = (float*)d_out;

    void *p_h, *p_qkvb, *p_attn, *p_x1, *p_mid, *p_w;
    cudaGetSymbolAddress(&p_h,    g_h);
    cudaGetSymbolAddress(&p_qkvb, g_qkvb);
    cudaGetSymbolAddress(&p_attn, g_attn);
    cudaGetSymbolAddress(&p_x1,   g_x1);
    cudaGetSymbolAddress(&p_mid,  g_mid);
    cudaGetSymbolAddress(&p_w,    g_w);
    float* h            = (float*)p_h;
    __nv_bfloat16* qkvb = (__nv_bfloat16*)p_qkvb;
    float* attn         = (float*)p_attn;
    float* x1           = (float*)p_x1;
    float* mid          = (float*)p_mid;
    float* w_qkv        = (float*)p_w;
    float* w_ao         = w_qkv + W_QKV_N;
    float* w_ff1        = w_ao  + W_AO_N;
    float* w_ff2        = w_ff1 + W_FF1_N;

    cudaFuncSetAttribute(flash_bf16_kernel,
                         cudaFuncAttributeMaxDynamicSharedMemorySize,
                         FLASHB_SMEM_BYTES);
    cudaFuncSetAttribute(tf32_gemm_kernel,
                         cudaFuncAttributeMaxDynamicSharedMemorySize,
                         GEMM_SMEM_BYTES);

    // 0. pre-round weights to tf32 (graph-captured; deterministic)
    round_tf32_kernel<<<W_QKV_N / 1024, 256>>>(qkv_w, w_qkv, W_QKV_N);
    round_tf32_kernel<<<W_AO_N  / 1024, 256>>>(attn_out_w, w_ao, W_AO_N);
    round_tf32_kernel<<<W_FF1_N / 1024, 256>>>(ff1_w, w_ff1, W_FF1_N);
    round_tf32_kernel<<<W_FF2_N / 1024, 256>>>(ff2_w, w_ff2, W_FF2_N);

    // 1. h = LN1(x)  (tf32-rounded)
    ln_kernel<<<NTOK / 8, 256>>>(x, ln1_g, ln1_b, h);
    // 2. qkv(bf16) = h @ qkv_w + qkv_b
    tf32_gemm_kernel<<<dim3(D_QKV / 128, NTOK / 128), 256, GEMM_SMEM_BYTES>>>(
        h, w_qkv, qkv_b, nullptr, (float*)qkvb, NTOK, D_QKV, D_MODEL, 0, 1);
    // 3. attention (bf16 tensor cores, 2 CTAs/SM)
    flash_bf16_kernel<<<dim3(T_SEQ / 128, N_HEADS, B_SZ), 256, FLASHB_SMEM_BYTES>>>(
        qkvb, attn);
    // 4. x1 = x + attn @ attn_out_w + attn_out_b
    tf32_gemm_kernel<<<dim3(D_MODEL / 128, NTOK / 128), 256, GEMM_SMEM_BYTES>>>(
        attn, w_ao, attn_out_b, x, x1, NTOK, D_MODEL, D_MODEL, 2, 0);
    // 5. h = LN2(x1)  (tf32-rounded)
    ln_kernel<<<NTOK / 8, 256>>>(x1, ln2_g, ln2_b, h);
    // 6. mid = gelu(h @ ff1_w + ff1_b)  (tf32-rounded)
    tf32_gemm_kernel<<<dim3(D_FF / 128, NTOK / 128), 256, GEMM_SMEM_BYTES>>>(
        h, w_ff1, ff1_b, nullptr, mid, NTOK, D_FF, D_MODEL, 1, 0);
    // 7. out = x1 + mid @ ff2_w + ff2_b
    tf32_gemm_kernel<<<dim3(D_MODEL / 128, NTOK / 128), 256, GEMM_SMEM_BYTES>>>(
        mid, w_ff2, ff2_b, x1, out, NTOK, D_MODEL, D_FF, 2, 0);
}

// round 6
// speedup vs baseline: 4.1823x; 1.0183x over previous
#include <cuda_runtime.h>
#include <cuda_bf16.h>
#include <math_constants.h>
#include <cstdint>
#include <cstddef>

// ---------------------------------------------------------------------------
// Problem constants
// ---------------------------------------------------------------------------
#define D_MODEL 768
#define N_HEADS 12
#define D_HEAD  64
#define D_FF    3072
#define B_SZ    4
#define T_SEQ   2048
#define NTOK    (B_SZ * T_SEQ)      // 8192
#define D_QKV   (3 * D_MODEL)       // 2304
#define LN_EPS  1e-5f

#define W_QKV_N   (D_MODEL * D_QKV)
#define W_AO_N    (D_MODEL * D_MODEL)
#define W_FF1_N   (D_MODEL * D_FF)
#define W_FF2_N   (D_FF * D_MODEL)
#define W_TOTAL_N (W_QKV_N + W_AO_N + W_FF1_N + W_FF2_N)

// ---------------------------------------------------------------------------
// Scratch (device globals)
// ---------------------------------------------------------------------------
__device__ float          g_h   [NTOK * D_MODEL];
__device__ __nv_bfloat16  g_qkvb[NTOK * D_QKV];
__device__ float          g_attn[NTOK * D_MODEL];
__device__ float          g_x1  [NTOK * D_MODEL];
__device__ float          g_mid [NTOK * D_FF];
__device__ float          g_w   [W_TOTAL_N];   // tf32-rounded weights

// ---------------------------------------------------------------------------
// tf32 helpers
// ---------------------------------------------------------------------------
__device__ __forceinline__ uint32_t f2tf32(float f) {
    uint32_t u;
    asm("cvt.rna.tf32.f32 %0, %1;" : "=r"(u) : "f"(f));
    return u;
}
__device__ __forceinline__ float f2tf32f(float f) {
    uint32_t u = f2tf32(f);
    return __uint_as_float(u);
}

// single-launch weight rounding (all 4 matrices)
__global__ __launch_bounds__(256) void round_all_kernel(
    const float* __restrict__ w0, const float* __restrict__ w1,
    const float* __restrict__ w2, const float* __restrict__ w3,
    float* __restrict__ dst)
{
    int i = (blockIdx.x * blockDim.x + threadIdx.x) * 4;
    if (i >= W_TOTAL_N) return;
    const float* src;
    int off;
    if (i < W_QKV_N)                        { src = w0; off = 0; }
    else if (i < W_QKV_N + W_AO_N)          { src = w1; off = W_QKV_N; }
    else if (i < W_QKV_N + W_AO_N + W_FF1_N){ src = w2; off = W_QKV_N + W_AO_N; }
    else                                    { src = w3; off = W_QKV_N + W_AO_N + W_FF1_N; }
    float4 v = *(const float4*)(src + (i - off));
    v.x = f2tf32f(v.x); v.y = f2tf32f(v.y);
    v.z = f2tf32f(v.z); v.w = f2tf32f(v.w);
    *(float4*)(dst + i) = v;
}

// ---------------------------------------------------------------------------
// LayerNorm: one warp per token; output rounded to tf32
// ---------------------------------------------------------------------------
__global__ __launch_bounds__(256) void ln_kernel(
    const float* __restrict__ x, const float* __restrict__ g,
    const float* __restrict__ b, float* __restrict__ out)
{
    int warp = (blockIdx.x * blockDim.x + threadIdx.x) >> 5;
    int lane = threadIdx.x & 31;
    if (warp >= NTOK) return;
    const float* xr = x + (size_t)warp * D_MODEL;
    float v[24];
    float s = 0.f;
#pragma unroll
    for (int i = 0; i < 24; i++) { v[i] = xr[lane + 32 * i]; s += v[i]; }
#pragma unroll
    for (int off = 16; off > 0; off >>= 1) s += __shfl_xor_sync(0xffffffffu, s, off);
    float mu = s * (1.f / D_MODEL);
    float sq = 0.f;
#pragma unroll
    for (int i = 0; i < 24; i++) { float d = v[i] - mu; sq += d * d; }
#pragma unroll
    for (int off = 16; off > 0; off >>= 1) sq += __shfl_xor_sync(0xffffffffu, sq, off);
    float rs = rsqrtf(sq * (1.f / D_MODEL) + LN_EPS);
    float* orow = out + (size_t)warp * D_MODEL;
#pragma unroll
    for (int i = 0; i < 24; i++) {
        int c = lane + 32 * i;
        orow[c] = f2tf32f((v[i] - mu) * rs * g[c] + b[c]);
    }
}

// ---------------------------------------------------------------------------
// GELU (tanh approx)
// ---------------------------------------------------------------------------
__device__ __forceinline__ float gelu_tanh(float x) {
    float x3 = x * x * x;
    float t = tanhf(0.7978845608028654f * (x + 0.044715f * x3));
    return 0.5f * x * (1.f + t);
}

// ---------------------------------------------------------------------------
// mma / ldmatrix helpers
// ---------------------------------------------------------------------------
__device__ __forceinline__ void mma_tf32(float c[4], const uint32_t a[4],
                                         const uint32_t b[2]) {
    asm volatile(
        "mma.sync.aligned.m16n8k8.row.col.f32.tf32.tf32.f32 "
        "{%0,%1,%2,%3}, {%4,%5,%6,%7}, {%8,%9}, {%0,%1,%2,%3};"
        : "+f"(c[0]), "+f"(c[1]), "+f"(c[2]), "+f"(c[3])
        : "r"(a[0]), "r"(a[1]), "r"(a[2]), "r"(a[3]), "r"(b[0]), "r"(b[1]));
}

__device__ __forceinline__ void mma_bf16(float c[4], const uint32_t a[4],
                                         const uint32_t b[2]) {
    asm volatile(
        "mma.sync.aligned.m16n8k16.row.col.f32.bf16.bf16.f32 "
        "{%0,%1,%2,%3}, {%4,%5,%6,%7}, {%8,%9}, {%0,%1,%2,%3};"
        : "+f"(c[0]), "+f"(c[1]), "+f"(c[2]), "+f"(c[3])
        : "r"(a[0]), "r"(a[1]), "r"(a[2]), "r"(a[3]), "r"(b[0]), "r"(b[1]));
}

__device__ __forceinline__ void ldsm_x4(uint32_t& r0, uint32_t& r1,
                                        uint32_t& r2, uint32_t& r3,
                                        const void* p) {
    uint32_t sa = (uint32_t)__cvta_generic_to_shared(p);
    asm volatile("ldmatrix.sync.aligned.m8n8.x4.shared.b16 {%0,%1,%2,%3}, [%4];"
                 : "=r"(r0), "=r"(r1), "=r"(r2), "=r"(r3) : "r"(sa));
}

__device__ __forceinline__ void ldsm_x4_t(uint32_t& r0, uint32_t& r1,
                                          uint32_t& r2, uint32_t& r3,
                                          const void* p) {
    uint32_t sa = (uint32_t)__cvta_generic_to_shared(p);
    asm volatile("ldmatrix.sync.aligned.m8n8.x4.trans.shared.b16 {%0,%1,%2,%3}, [%4];"
                 : "=r"(r0), "=r"(r1), "=r"(r2), "=r"(r3) : "r"(sa));
}

__device__ __forceinline__ void cp_async16(void* smem_dst, const void* gsrc) {
    uint32_t d = (uint32_t)__cvta_generic_to_shared(smem_dst);
    asm volatile("cp.async.ca.shared.global [%0], [%1], 16;\n" ::"r"(d), "l"(gsrc));
}

// ---------------------------------------------------------------------------
// tf32 tensor-core GEMM, zero-CVT (operands pre-rounded)
// ---------------------------------------------------------------------------
#define AS_STRIDE 36
#define BS_STRIDE 136
#define AS_FLOATS (128 * AS_STRIDE)
#define BS_FLOATS (32 * BS_STRIDE)
#define GEMM_SMEM_BYTES ((2 * AS_FLOATS + 2 * BS_FLOATS) * 4)

__global__ __launch_bounds__(256, 2) void tf32_gemm_kernel(
    const float* __restrict__ A, const float* __restrict__ W,
    const float* __restrict__ bias, const float* __restrict__ resid,
    float* __restrict__ C, int M, int N, int K, int epi, int out_bf16)
{
    extern __shared__ float sm[];
    float* Asm = sm;
    float* Bsm = sm + 2 * AS_FLOATS;

    int tid = threadIdx.x;
    int lane = tid & 31;
    int warp = tid >> 5;
    int g = lane >> 2;
    int t = lane & 3;
    int m_w = (warp >> 2) * 64;
    int n_w = (warp & 3) * 32;

    int rowBase = blockIdx.y * 128;
    int colBase = blockIdx.x * 128;

    const float* Ag = A + (size_t)rowBase * K;
    const float* Wg = W + colBase;

    float acc[4][4][4];
#pragma unroll
    for (int mf = 0; mf < 4; mf++)
#pragma unroll
        for (int nf = 0; nf < 4; nf++)
#pragma unroll
            for (int i = 0; i < 4; i++) acc[mf][nf][i] = 0.f;

    int ntiles = K / 32;

    auto issue_copy = [&](int s, int kt) {
        float* as = Asm + s * AS_FLOATS;
        float* bs = Bsm + s * BS_FLOATS;
#pragma unroll
        for (int i = 0; i < 4; i++) {
            int id = tid + i * 256;
            int r = id >> 3;
            int c4 = (id & 7) << 2;
            cp_async16(as + r * AS_STRIDE + c4, Ag + (size_t)r * K + kt + c4);
        }
#pragma unroll
        for (int i = 0; i < 4; i++) {
            int id = tid + i * 256;
            int r = id >> 5;
            int c4 = (id & 31) << 2;
            cp_async16(bs + r * BS_STRIDE + c4, Wg + (size_t)(kt + r) * N + c4);
        }
        asm volatile("cp.async.commit_group;\n");
    };

    issue_copy(0, 0);

    for (int kt = 0; kt < ntiles; kt++) {
        if (kt + 1 < ntiles) {
            issue_copy((kt + 1) & 1, (kt + 1) * 32);
            asm volatile("cp.async.wait_group 1;\n");
        } else {
            asm volatile("cp.async.wait_group 0;\n");
        }
        __syncthreads();

        const float* as = Asm + (kt & 1) * AS_FLOATS;
        const float* bs = Bsm + (kt & 1) * BS_FLOATS;

#pragma unroll
        for (int ks = 0; ks < 4; ks++) {
            int k0 = ks * 8;
            uint32_t af[4][4];
            uint32_t bf[4][2];
#pragma unroll
            for (int mf = 0; mf < 4; mf++) {
                const float* base = as + (m_w + mf * 16 + g) * AS_STRIDE + k0 + t;
                af[mf][0] = __float_as_uint(base[0]);
                af[mf][2] = __float_as_uint(base[4]);
                af[mf][1] = __float_as_uint(base[8 * AS_STRIDE]);
                af[mf][3] = __float_as_uint(base[8 * AS_STRIDE + 4]);
            }
#pragma unroll
            for (int nf = 0; nf < 4; nf++) {
                const float* bb = bs + (k0 + t) * BS_STRIDE + n_w + nf * 8 + g;
                bf[nf][0] = __float_as_uint(bb[0]);
                bf[nf][1] = __float_as_uint(bb[4 * BS_STRIDE]);
            }
#pragma unroll
            for (int mf = 0; mf < 4; mf++)
#pragma unroll
                for (int nf = 0; nf < 4; nf++)
                    mma_tf32(acc[mf][nf], af[mf], bf[nf]);
        }
        __syncthreads();
    }

#pragma unroll
    for (int mf = 0; mf < 4; mf++) {
        int row0 = rowBase + m_w + mf * 16 + g;
        int row1 = row0 + 8;
#pragma unroll
        for (int nf = 0; nf < 4; nf++) {
            int col = colBase + n_w + nf * 8 + 2 * t;
            float2 bv = *(const float2*)&bias[col];
            float v00 = acc[mf][nf][0] + bv.x;
            float v01 = acc[mf][nf][1] + bv.y;
            float v10 = acc[mf][nf][2] + bv.x;
            float v11 = acc[mf][nf][3] + bv.y;
            if (epi == 1) {
                v00 = f2tf32f(gelu_tanh(v00)); v01 = f2tf32f(gelu_tanh(v01));
                v10 = f2tf32f(gelu_tanh(v10)); v11 = f2tf32f(gelu_tanh(v11));
            } else if (epi == 2) {
                float2 r0 = *(const float2*)&resid[(size_t)row0 * N + col];
                float2 r1 = *(const float2*)&resid[(size_t)row1 * N + col];
                v00 += r0.x; v01 += r0.y; v10 += r1.x; v11 += r1.y;
            }
            if (out_bf16) {
                __nv_bfloat16* Cb = reinterpret_cast<__nv_bfloat16*>(C);
                __nv_bfloat162 p0 = __float22bfloat162_rn(make_float2(v00, v01));
                __nv_bfloat162 p1 = __float22bfloat162_rn(make_float2(v10, v11));
                *(uint32_t*)&Cb[(size_t)row0 * N + col] = *(uint32_t*)&p0;
                *(uint32_t*)&Cb[(size_t)row1 * N + col] = *(uint32_t*)&p1;
            } else {
                *(float2*)&C[(size_t)row0 * N + col] = make_float2(v00, v01);
                *(float2*)&C[(size_t)row1 * N + col] = make_float2(v10, v11);
            }
        }
    }
}

// ---------------------------------------------------------------------------
// Flash attention, bf16 mma. BQ=64 (4 warps, 128 thr), BK=64, 2-stage.
// 45KB smem -> 4 CTAs/SM: cross-CTA overlap hides softmax/barrier phases.
// ---------------------------------------------------------------------------
#define FST 72                         // bf16 per smem row (144B)
#define FQ_ELEMS (64 * FST)
#define FKV_ELEMS (64 * FST)
#define FLASHB_SMEM_BYTES ((FQ_ELEMS + 4 * FKV_ELEMS) * 2)   // 46080 B

__global__ __launch_bounds__(128, 4) void flash_bf16_kernel(
    const __nv_bfloat16* __restrict__ qkv, float* __restrict__ attn_out)
{
    extern __shared__ __align__(16) char smraw[];
    __nv_bfloat16* Qs = (__nv_bfloat16*)smraw;
    __nv_bfloat16* Ks = Qs + FQ_ELEMS;        // 2 stages x 64 rows
    __nv_bfloat16* Vs = Ks + 2 * FKV_ELEMS;   // 2 stages x 64 rows

    int qi = blockIdx.x, h = blockIdx.y, bz = blockIdx.z;
    int tid = threadIdx.x;
    int lane = tid & 31;
    int warp = tid >> 5;            // 0..3
    int g = lane >> 2, t = lane & 3;
    int m_w = warp * 16;

    size_t rowB = (size_t)bz * T_SEQ;
    const __nv_bfloat16* Qg = qkv + (rowB + (size_t)qi * 64) * D_QKV + h * D_HEAD;
    const __nv_bfloat16* Kg = qkv + rowB * D_QKV + D_MODEL     + h * D_HEAD;
    const __nv_bfloat16* Vg = qkv + rowB * D_QKV + 2 * D_MODEL + h * D_HEAD;

    // stage Q: 64 rows x 64 cols (4 chunks/thread)
#pragma unroll
    for (int i = 0; i < 4; i++) {
        int id = tid + i * 128;
        int r = id >> 3, c = (id & 7) * 8;
        cp_async16(Qs + r * FST + c, Qg + (size_t)r * D_QKV + c);
    }
    asm volatile("cp.async.commit_group;\n");

    auto load_kv = [&](int s, int kt) {
        const __nv_bfloat16* Kt_ = Kg + (size_t)kt * 64 * D_QKV;
        const __nv_bfloat16* Vt_ = Vg + (size_t)kt * 64 * D_QKV;
        __nv_bfloat16* ks_ = Ks + s * FKV_ELEMS;
        __nv_bfloat16* vs_ = Vs + s * FKV_ELEMS;
#pragma unroll
        for (int i = 0; i < 4; i++) {
            int id = tid + i * 128;
            int r = id >> 3, c = (id & 7) * 8;
            cp_async16(ks_ + r * FST + c, Kt_ + (size_t)r * D_QKV + c);
            cp_async16(vs_ + r * FST + c, Vt_ + (size_t)r * D_QKV + c);
        }
        asm volatile("cp.async.commit_group;\n");
    };
    load_kv(0, 0);

    asm volatile("cp.async.wait_group 1;\n");   // Q ready
    __syncthreads();

    // Q a-fragments, scaled by 0.125 (exact in bf16)
    uint32_t qa[4][4];
    {
        const __nv_bfloat16* q0 = Qs + (m_w + g) * FST;
        const __nv_bfloat16* q1 = q0 + 8 * FST;
        __nv_bfloat162 sc2 = __float2bfloat162_rn(0.125f);
#pragma unroll
        for (int kb = 0; kb < 4; kb++) {
            __nv_bfloat162 v;
            v = __hmul2(*(const __nv_bfloat162*)(q0 + kb * 16 + 2 * t), sc2);
            qa[kb][0] = *(uint32_t*)&v;
            v = __hmul2(*(const __nv_bfloat162*)(q1 + kb * 16 + 2 * t), sc2);
            qa[kb][1] = *(uint32_t*)&v;
            v = __hmul2(*(const __nv_bfloat162*)(q0 + kb * 16 + 2 * t + 8), sc2);
            qa[kb][2] = *(uint32_t*)&v;
            v = __hmul2(*(const __nv_bfloat162*)(q1 + kb * 16 + 2 * t + 8), sc2);
            qa[kb][3] = *(uint32_t*)&v;
        }
    }

    float o[8][4];
#pragma unroll
    for (int nf = 0; nf < 8; nf++)
#pragma unroll
        for (int i = 0; i < 4; i++) o[nf][i] = 0.f;
    float m0 = -CUDART_INF_F, m1 = -CUDART_INF_F;
    float l0 = 0.f, l1 = 0.f;

    const int NITER = T_SEQ / 64;   // 32
    for (int kt = 0; kt < NITER; kt++) {
        if (kt + 1 < NITER) {
            load_kv((kt + 1) & 1, kt + 1);
            asm volatile("cp.async.wait_group 1;\n");
        } else {
            asm volatile("cp.async.wait_group 0;\n");
        }
        __syncthreads();

        const __nv_bfloat16* ks_ = Ks + (kt & 1) * FKV_ELEMS;
        const __nv_bfloat16* vs_ = Vs + (kt & 1) * FKV_ELEMS;

        // ---- S = (Q*scale) @ K^T ----
        float sf[8][4];
#pragma unroll
        for (int nf = 0; nf < 8; nf++) {
            sf[nf][0] = sf[nf][1] = sf[nf][2] = sf[nf][3] = 0.f;
            uint32_t b0[4], b1[4];
            const __nv_bfloat16* kp = ks_ + (nf * 8 + (lane & 7)) * FST + (lane >> 3) * 8;
            ldsm_x4(b0[0], b0[1], b0[2], b0[3], kp);
            ldsm_x4(b1[0], b1[1], b1[2], b1[3], kp + 32);
            { uint32_t bb[2] = {b0[0], b0[1]}; mma_bf16(sf[nf], qa[0], bb); }
            { uint32_t bb[2] = {b0[2], b0[3]}; mma_bf16(sf[nf], qa[1], bb); }
            { uint32_t bb[2] = {b1[0], b1[1]}; mma_bf16(sf[nf], qa[2], bb); }
            { uint32_t bb[2] = {b1[2], b1[3]}; mma_bf16(sf[nf], qa[3], bb); }
        }

        // ---- online softmax (registers only) ----
        float mx0 = -CUDART_INF_F, mx1 = -CUDART_INF_F;
#pragma unroll
        for (int nf = 0; nf < 8; nf++) {
            mx0 = fmaxf(mx0, fmaxf(sf[nf][0], sf[nf][1]));
            mx1 = fmaxf(mx1, fmaxf(sf[nf][2], sf[nf][3]));
        }
#pragma unroll
        for (int off = 1; off <= 2; off <<= 1) {
            mx0 = fmaxf(mx0, __shfl_xor_sync(0xffffffffu, mx0, off));
            mx1 = fmaxf(mx1, __shfl_xor_sync(0xffffffffu, mx1, off));
        }
        float mn0 = fmaxf(m0, mx0), mn1 = fmaxf(m1, mx1);
        float sc0 = __expf(m0 - mn0), sc1 = __expf(m1 - mn1);
        m0 = mn0; m1 = mn1;

        float rs0 = 0.f, rs1 = 0.f;
#pragma unroll
        for (int nf = 0; nf < 8; nf++) {
            sf[nf][0] = __expf(sf[nf][0] - mn0);
            sf[nf][1] = __expf(sf[nf][1] - mn0);
            sf[nf][2] = __expf(sf[nf][2] - mn1);
            sf[nf][3] = __expf(sf[nf][3] - mn1);
            rs0 += sf[nf][0] + sf[nf][1];
            rs1 += sf[nf][2] + sf[nf][3];
        }
#pragma unroll
        for (int off = 1; off <= 2; off <<= 1) {
            rs0 += __shfl_xor_sync(0xffffffffu, rs0, off);
            rs1 += __shfl_xor_sync(0xffffffffu, rs1, off);
        }
        l0 = l0 * sc0 + rs0;
        l1 = l1 * sc1 + rs1;
#pragma unroll
        for (int nf = 0; nf < 8; nf++) {
            o[nf][0] *= sc0; o[nf][1] *= sc0;
            o[nf][2] *= sc1; o[nf][3] *= sc1;
        }

        // ---- O += P @ V ----
#pragma unroll
        for (int kb = 0; kb < 4; kb++) {
            uint32_t a[4];
            __nv_bfloat162 p;
            p = __float22bfloat162_rn(make_float2(sf[2*kb][0],   sf[2*kb][1]));
            a[0] = *(uint32_t*)&p;
            p = __float22bfloat162_rn(make_float2(sf[2*kb][2],   sf[2*kb][3]));
            a[1] = *(uint32_t*)&p;
            p = __float22bfloat162_rn(make_float2(sf[2*kb+1][0], sf[2*kb+1][1]));
            a[2] = *(uint32_t*)&p;
            p = __float22bfloat162_rn(make_float2(sf[2*kb+1][2], sf[2*kb+1][3]));
            a[3] = *(uint32_t*)&p;

            const __nv_bfloat16* vp = vs_ + (kb * 16 + (lane & 15)) * FST + (lane >> 4) * 8;
#pragma unroll
            for (int nfp = 0; nfp < 4; nfp++) {
                uint32_t v0, v1, v2, v3;
                ldsm_x4_t(v0, v1, v2, v3, vp + nfp * 16);
                { uint32_t bb[2] = {v0, v1}; mma_bf16(o[2*nfp],     a, bb); }
                { uint32_t bb[2] = {v2, v3}; mma_bf16(o[2*nfp + 1], a, bb); }
            }
        }
        __syncthreads();   // stage reuse barrier
    }

    // ---- epilogue: O / l, rounded to tf32 (feeds next GEMM A) ----
    float i0 = 1.f / l0, i1 = 1.f / l1;
    size_t tok0 = rowB + (size_t)qi * 64 + m_w + g;
    float* out0 = attn_out + tok0 * D_MODEL + h * D_HEAD;
    float* out1 = out0 + 8 * (size_t)D_MODEL;
#pragma unroll
    for (int nf = 0; nf < 8; nf++) {
        *(float2*)(out0 + nf * 8 + 2 * t) =
            make_float2(f2tf32f(o[nf][0] * i0), f2tf32f(o[nf][1] * i0));
        *(float2*)(out1 + nf * 8 + 2 * t) =
            make_float2(f2tf32f(o[nf][2] * i1), f2tf32f(o[nf][3] * i1));
    }
}

// ---------------------------------------------------------------------------
// Launch
// ---------------------------------------------------------------------------
extern "C" void kernel_launch(void* const* d_in, const int* in_sizes, int n_in,
                              void* d_out, int out_size)
{
    const float* x          = (const float*)d_in[0];
    const float* ln1_g      = (const float*)d_in[1];
    const float* ln1_b      = (const float*)d_in[2];
    const float* qkv_w      = (const float*)d_in[3];
    const float* qkv_b      = (const float*)d_in[4];
    const float* attn_out_w = (const float*)d_in[5];
    const float* attn_out_b = (const float*)d_in[6];
    const float* ln2_g      = (const float*)d_in[7];
    const float* ln2_b      = (const float*)d_in[8];
    const float* ff1_w      = (const float*)d_in[9];
    const float* ff1_b      = (const float*)d_in[10];
    const float* ff2_w      = (const float*)d_in[11];
    const float* ff2_b      = (const float*)d_in[12];
    float* out = (float*)d_out;

    void *p_h, *p_qkvb, *p_attn, *p_x1, *p_mid, *p_w;
    cudaGetSymbolAddress(&p_h,    g_h);
    cudaGetSymbolAddress(&p_qkvb, g_qkvb);
    cudaGetSymbolAddress(&p_attn, g_attn);
    cudaGetSymbolAddress(&p_x1,   g_x1);
    cudaGetSymbolAddress(&p_mid,  g_mid);
    cudaGetSymbolAddress(&p_w,    g_w);
    float* h            = (float*)p_h;
    __nv_bfloat16* qkvb = (__nv_bfloat16*)p_qkvb;
    float* attn         = (float*)p_attn;
    float* x1           = (float*)p_x1;
    float* mid          = (float*)p_mid;
    float* w_qkv        = (float*)p_w;
    float* w_ao         = w_qkv + W_QKV_N;
    float* w_ff1        = w_ao  + W_AO_N;
    float* w_ff2        = w_ff1 + W_FF1_N;

    cudaFuncSetAttribute(flash_bf16_kernel,
                         cudaFuncAttributeMaxDynamicSharedMemorySize,
                         FLASHB_SMEM_BYTES);
    cudaFuncSetAttribute(tf32_gemm_kernel,
                         cudaFuncAttributeMaxDynamicSharedMemorySize,
                         GEMM_SMEM_BYTES);

    // 0. pre-round all weights to tf32 (single launch)
    round_all_kernel<<<(W_TOTAL_N / 4 + 255) / 256, 256>>>(
        qkv_w, attn_out_w, ff1_w, ff2_w, (float*)p_w);

    // 1. h = LN1(x)
    ln_kernel<<<NTOK / 8, 256>>>(x, ln1_g, ln1_b, h);
    // 2. qkv(bf16) = h @ qkv_w + qkv_b
    tf32_gemm_kernel<<<dim3(D_QKV / 128, NTOK / 128), 256, GEMM_SMEM_BYTES>>>(
        h, w_qkv, qkv_b, nullptr, (float*)qkvb, NTOK, D_QKV, D_MODEL, 0, 1);
    // 3. attention (bf16 tensor cores, 4 CTAs/SM)
    flash_bf16_kernel<<<dim3(T_SEQ / 64, N_HEADS, B_SZ), 128, FLASHB_SMEM_BYTES>>>(
        qkvb, attn);
    // 4. x1 = x + attn @ attn_out_w + attn_out_b
    tf32_gemm_kernel<<<dim3(D_MODEL / 128, NTOK / 128), 256, GEMM_SMEM_BYTES>>>(
        attn, w_ao, attn_out_b, x, x1, NTOK, D_MODEL, D_MODEL, 2, 0);
    // 5. h = LN2(x1)
    ln_kernel<<<NTOK / 8, 256>>>(x1, ln2_g, ln2_b, h);
    // 6. mid = gelu(h @ ff1_w + ff1_b)
    tf32_gemm_kernel<<<dim3(D_FF / 128, NTOK / 128), 256, GEMM_SMEM_BYTES>>>(
        h, w_ff1, ff1_b, nullptr, mid, NTOK, D_FF, D_MODEL, 1, 0);
    // 7. out = x1 + mid @ ff2_w + ff2_b
    tf32_gemm_kernel<<<dim3(D_MODEL / 128, NTOK / 128), 256, GEMM_SMEM_BYTES>>>(
        mid, w_ff2, ff2_b, x1, out, NTOK, D_MODEL, D_FF, 2, 0);
}

// round 7
// speedup vs baseline: 4.2563x; 1.0177x over previous
#include <cuda_runtime.h>
#include <cuda_bf16.h>
#include <math_constants.h>
#include <cstdint>
#include <cstddef>

// ---------------------------------------------------------------------------
// Problem constants
// ---------------------------------------------------------------------------
#define D_MODEL 768
#define N_HEADS 12
#define D_HEAD  64
#define D_FF    3072
#define B_SZ    4
#define T_SEQ   2048
#define NTOK    (B_SZ * T_SEQ)      // 8192
#define D_QKV   (3 * D_MODEL)       // 2304
#define LN_EPS  1e-5f

#define W_QKV_N   (D_MODEL * D_QKV)
#define W_AO_N    (D_MODEL * D_MODEL)
#define W_FF1_N   (D_MODEL * D_FF)
#define W_FF2_N   (D_FF * D_MODEL)
#define W_TOTAL_N (W_QKV_N + W_AO_N + W_FF1_N + W_FF2_N)

// ---------------------------------------------------------------------------
// Scratch (device globals)
// ---------------------------------------------------------------------------
__device__ float          g_h   [NTOK * D_MODEL];
__device__ __nv_bfloat16  g_qkvb[NTOK * D_QKV];
__device__ float          g_attn[NTOK * D_MODEL];
__device__ float          g_x1  [NTOK * D_MODEL];
__device__ float          g_mid [NTOK * D_FF];
__device__ float          g_w   [W_TOTAL_N];   // tf32-rounded weights

// ---------------------------------------------------------------------------
// tf32 helpers
// ---------------------------------------------------------------------------
__device__ __forceinline__ uint32_t f2tf32(float f) {
    uint32_t u;
    asm("cvt.rna.tf32.f32 %0, %1;" : "=r"(u) : "f"(f));
    return u;
}
__device__ __forceinline__ float f2tf32f(float f) {
    uint32_t u = f2tf32(f);
    return __uint_as_float(u);
}

// single-launch weight rounding (all 4 matrices)
__global__ __launch_bounds__(256) void round_all_kernel(
    const float* __restrict__ w0, const float* __restrict__ w1,
    const float* __restrict__ w2, const float* __restrict__ w3,
    float* __restrict__ dst)
{
    int i = (blockIdx.x * blockDim.x + threadIdx.x) * 4;
    if (i >= W_TOTAL_N) return;
    const float* src;
    int off;
    if (i < W_QKV_N)                        { src = w0; off = 0; }
    else if (i < W_QKV_N + W_AO_N)          { src = w1; off = W_QKV_N; }
    else if (i < W_QKV_N + W_AO_N + W_FF1_N){ src = w2; off = W_QKV_N + W_AO_N; }
    else                                    { src = w3; off = W_QKV_N + W_AO_N + W_FF1_N; }
    float4 v = *(const float4*)(src + (i - off));
    v.x = f2tf32f(v.x); v.y = f2tf32f(v.y);
    v.z = f2tf32f(v.z); v.w = f2tf32f(v.w);
    *(float4*)(dst + i) = v;
}

// ---------------------------------------------------------------------------
// LayerNorm: one warp per token; output rounded to tf32
// ---------------------------------------------------------------------------
__global__ __launch_bounds__(256) void ln_kernel(
    const float* __restrict__ x, const float* __restrict__ g,
    const float* __restrict__ b, float* __restrict__ out)
{
    int warp = (blockIdx.x * blockDim.x + threadIdx.x) >> 5;
    int lane = threadIdx.x & 31;
    if (warp >= NTOK) return;
    const float* xr = x + (size_t)warp * D_MODEL;
    float v[24];
    float s = 0.f;
#pragma unroll
    for (int i = 0; i < 24; i++) { v[i] = xr[lane + 32 * i]; s += v[i]; }
#pragma unroll
    for (int off = 16; off > 0; off >>= 1) s += __shfl_xor_sync(0xffffffffu, s, off);
    float mu = s * (1.f / D_MODEL);
    float sq = 0.f;
#pragma unroll
    for (int i = 0; i < 24; i++) { float d = v[i] - mu; sq += d * d; }
#pragma unroll
    for (int off = 16; off > 0; off >>= 1) sq += __shfl_xor_sync(0xffffffffu, sq, off);
    float rs = rsqrtf(sq * (1.f / D_MODEL) + LN_EPS);
    float* orow = out + (size_t)warp * D_MODEL;
#pragma unroll
    for (int i = 0; i < 24; i++) {
        int c = lane + 32 * i;
        orow[c] = f2tf32f((v[i] - mu) * rs * g[c] + b[c]);
    }
}

// ---------------------------------------------------------------------------
// GELU (tanh approx)
// ---------------------------------------------------------------------------
__device__ __forceinline__ float gelu_tanh(float x) {
    float x3 = x * x * x;
    float t = tanhf(0.7978845608028654f * (x + 0.044715f * x3));
    return 0.5f * x * (1.f + t);
}

// ---------------------------------------------------------------------------
// mma / ldmatrix helpers
// ---------------------------------------------------------------------------
__device__ __forceinline__ void mma_tf32(float c[4], const uint32_t a[4],
                                         const uint32_t b[2]) {
    asm volatile(
        "mma.sync.aligned.m16n8k8.row.col.f32.tf32.tf32.f32 "
        "{%0,%1,%2,%3}, {%4,%5,%6,%7}, {%8,%9}, {%0,%1,%2,%3};"
        : "+f"(c[0]), "+f"(c[1]), "+f"(c[2]), "+f"(c[3])
        : "r"(a[0]), "r"(a[1]), "r"(a[2]), "r"(a[3]), "r"(b[0]), "r"(b[1]));
}

__device__ __forceinline__ void mma_bf16(float c[4], const uint32_t a[4],
                                         const uint32_t b[2]) {
    asm volatile(
        "mma.sync.aligned.m16n8k16.row.col.f32.bf16.bf16.f32 "
        "{%0,%1,%2,%3}, {%4,%5,%6,%7}, {%8,%9}, {%0,%1,%2,%3};"
        : "+f"(c[0]), "+f"(c[1]), "+f"(c[2]), "+f"(c[3])
        : "r"(a[0]), "r"(a[1]), "r"(a[2]), "r"(a[3]), "r"(b[0]), "r"(b[1]));
}

__device__ __forceinline__ void ldsm_x4(uint32_t& r0, uint32_t& r1,
                                        uint32_t& r2, uint32_t& r3,
                                        const void* p) {
    uint32_t sa = (uint32_t)__cvta_generic_to_shared(p);
    asm volatile("ldmatrix.sync.aligned.m8n8.x4.shared.b16 {%0,%1,%2,%3}, [%4];"
                 : "=r"(r0), "=r"(r1), "=r"(r2), "=r"(r3) : "r"(sa));
}

__device__ __forceinline__ void ldsm_x4_t(uint32_t& r0, uint32_t& r1,
                                          uint32_t& r2, uint32_t& r3,
                                          const void* p) {
    uint32_t sa = (uint32_t)__cvta_generic_to_shared(p);
    asm volatile("ldmatrix.sync.aligned.m8n8.x4.trans.shared.b16 {%0,%1,%2,%3}, [%4];"
                 : "=r"(r0), "=r"(r1), "=r"(r2), "=r"(r3) : "r"(sa));
}

__device__ __forceinline__ void cp_async16(void* smem_dst, const void* gsrc) {
    uint32_t d = (uint32_t)__cvta_generic_to_shared(smem_dst);
    asm volatile("cp.async.ca.shared.global [%0], [%1], 16;\n" ::"r"(d), "l"(gsrc));
}

// ---------------------------------------------------------------------------
// tf32 tensor-core GEMM, zero-CVT (operands pre-rounded) — unchanged
// ---------------------------------------------------------------------------
#define AS_STRIDE 36
#define BS_STRIDE 136
#define AS_FLOATS (128 * AS_STRIDE)
#define BS_FLOATS (32 * BS_STRIDE)
#define GEMM_SMEM_BYTES ((2 * AS_FLOATS + 2 * BS_FLOATS) * 4)

__global__ __launch_bounds__(256, 2) void tf32_gemm_kernel(
    const float* __restrict__ A, const float* __restrict__ W,
    const float* __restrict__ bias, const float* __restrict__ resid,
    float* __restrict__ C, int M, int N, int K, int epi, int out_bf16)
{
    extern __shared__ float sm[];
    float* Asm = sm;
    float* Bsm = sm + 2 * AS_FLOATS;

    int tid = threadIdx.x;
    int lane = tid & 31;
    int warp = tid >> 5;
    int g = lane >> 2;
    int t = lane & 3;
    int m_w = (warp >> 2) * 64;
    int n_w = (warp & 3) * 32;

    int rowBase = blockIdx.y * 128;
    int colBase = blockIdx.x * 128;

    const float* Ag = A + (size_t)rowBase * K;
    const float* Wg = W + colBase;

    float acc[4][4][4];
#pragma unroll
    for (int mf = 0; mf < 4; mf++)
#pragma unroll
        for (int nf = 0; nf < 4; nf++)
#pragma unroll
            for (int i = 0; i < 4; i++) acc[mf][nf][i] = 0.f;

    int ntiles = K / 32;

    auto issue_copy = [&](int s, int kt) {
        float* as = Asm + s * AS_FLOATS;
        float* bs = Bsm + s * BS_FLOATS;
#pragma unroll
        for (int i = 0; i < 4; i++) {
            int id = tid + i * 256;
            int r = id >> 3;
            int c4 = (id & 7) << 2;
            cp_async16(as + r * AS_STRIDE + c4, Ag + (size_t)r * K + kt + c4);
        }
#pragma unroll
        for (int i = 0; i < 4; i++) {
            int id = tid + i * 256;
            int r = id >> 5;
            int c4 = (id & 31) << 2;
            cp_async16(bs + r * BS_STRIDE + c4, Wg + (size_t)(kt + r) * N + c4);
        }
        asm volatile("cp.async.commit_group;\n");
    };

    issue_copy(0, 0);

    for (int kt = 0; kt < ntiles; kt++) {
        if (kt + 1 < ntiles) {
            issue_copy((kt + 1) & 1, (kt + 1) * 32);
            asm volatile("cp.async.wait_group 1;\n");
        } else {
            asm volatile("cp.async.wait_group 0;\n");
        }
        __syncthreads();

        const float* as = Asm + (kt & 1) * AS_FLOATS;
        const float* bs = Bsm + (kt & 1) * BS_FLOATS;

#pragma unroll
        for (int ks = 0; ks < 4; ks++) {
            int k0 = ks * 8;
            uint32_t af[4][4];
            uint32_t bf[4][2];
#pragma unroll
            for (int mf = 0; mf < 4; mf++) {
                const float* base = as + (m_w + mf * 16 + g) * AS_STRIDE + k0 + t;
                af[mf][0] = __float_as_uint(base[0]);
                af[mf][2] = __float_as_uint(base[4]);
                af[mf][1] = __float_as_uint(base[8 * AS_STRIDE]);
                af[mf][3] = __float_as_uint(base[8 * AS_STRIDE + 4]);
            }
#pragma unroll
            for (int nf = 0; nf < 4; nf++) {
                const float* bb = bs + (k0 + t) * BS_STRIDE + n_w + nf * 8 + g;
                bf[nf][0] = __float_as_uint(bb[0]);
                bf[nf][1] = __float_as_uint(bb[4 * BS_STRIDE]);
            }
#pragma unroll
            for (int mf = 0; mf < 4; mf++)
#pragma unroll
                for (int nf = 0; nf < 4; nf++)
                    mma_tf32(acc[mf][nf], af[mf], bf[nf]);
        }
        __syncthreads();
    }

#pragma unroll
    for (int mf = 0; mf < 4; mf++) {
        int row0 = rowBase + m_w + mf * 16 + g;
        int row1 = row0 + 8;
#pragma unroll
        for (int nf = 0; nf < 4; nf++) {
            int col = colBase + n_w + nf * 8 + 2 * t;
            float2 bv = *(const float2*)&bias[col];
            float v00 = acc[mf][nf][0] + bv.x;
            float v01 = acc[mf][nf][1] + bv.y;
            float v10 = acc[mf][nf][2] + bv.x;
            float v11 = acc[mf][nf][3] + bv.y;
            if (epi == 1) {
                v00 = f2tf32f(gelu_tanh(v00)); v01 = f2tf32f(gelu_tanh(v01));
                v10 = f2tf32f(gelu_tanh(v10)); v11 = f2tf32f(gelu_tanh(v11));
            } else if (epi == 2) {
                float2 r0 = *(const float2*)&resid[(size_t)row0 * N + col];
                float2 r1 = *(const float2*)&resid[(size_t)row1 * N + col];
                v00 += r0.x; v01 += r0.y; v10 += r1.x; v11 += r1.y;
            }
            if (out_bf16) {
                __nv_bfloat16* Cb = reinterpret_cast<__nv_bfloat16*>(C);
                __nv_bfloat162 p0 = __float22bfloat162_rn(make_float2(v00, v01));
                __nv_bfloat162 p1 = __float22bfloat162_rn(make_float2(v10, v11));
                *(uint32_t*)&Cb[(size_t)row0 * N + col] = *(uint32_t*)&p0;
                *(uint32_t*)&Cb[(size_t)row1 * N + col] = *(uint32_t*)&p1;
            } else {
                *(float2*)&C[(size_t)row0 * N + col] = make_float2(v00, v01);
                *(float2*)&C[(size_t)row1 * N + col] = make_float2(v10, v11);
            }
        }
    }
}

// ---------------------------------------------------------------------------
// Flash attention, bf16 mma. BQ=128, 4 warps x 32 Q rows (2 m-frags/warp),
// BK=64, 2-stage. K/V fragment loads amortized over 2x the MMAs.
// 54KB smem -> 2 CTAs/SM.
// ---------------------------------------------------------------------------
#define FST 72                         // bf16 per smem row (144B)
#define FQ_ELEMS (128 * FST)
#define FKV_ELEMS (64 * FST)
#define FLASHB_SMEM_BYTES ((FQ_ELEMS + 4 * FKV_ELEMS) * 2)   // 55296 B

__global__ __launch_bounds__(128, 2) void flash_bf16_kernel(
    const __nv_bfloat16* __restrict__ qkv, float* __restrict__ attn_out)
{
    extern __shared__ __align__(16) char smraw[];
    __nv_bfloat16* Qs = (__nv_bfloat16*)smraw;
    __nv_bfloat16* Ks = Qs + FQ_ELEMS;        // 2 stages x 64 rows
    __nv_bfloat16* Vs = Ks + 2 * FKV_ELEMS;   // 2 stages x 64 rows

    int qi = blockIdx.x, h = blockIdx.y, bz = blockIdx.z;
    int tid = threadIdx.x;
    int lane = tid & 31;
    int warp = tid >> 5;            // 0..3
    int g = lane >> 2, t = lane & 3;
    int m_w = warp * 32;            // 32 rows per warp

    size_t rowB = (size_t)bz * T_SEQ;
    const __nv_bfloat16* Qg = qkv + (rowB + (size_t)qi * 128) * D_QKV + h * D_HEAD;
    const __nv_bfloat16* Kg = qkv + rowB * D_QKV + D_MODEL     + h * D_HEAD;
    const __nv_bfloat16* Vg = qkv + rowB * D_QKV + 2 * D_MODEL + h * D_HEAD;

    // stage Q: 128 rows x 64 cols (8 chunks/thread)
#pragma unroll
    for (int i = 0; i < 8; i++) {
        int id = tid + i * 128;
        int r = id >> 3, c = (id & 7) * 8;
        cp_async16(Qs + r * FST + c, Qg + (size_t)r * D_QKV + c);
    }
    asm volatile("cp.async.commit_group;\n");

    auto load_kv = [&](int s, int kt) {
        const __nv_bfloat16* Kt_ = Kg + (size_t)kt * 64 * D_QKV;
        const __nv_bfloat16* Vt_ = Vg + (size_t)kt * 64 * D_QKV;
        __nv_bfloat16* ks_ = Ks + s * FKV_ELEMS;
        __nv_bfloat16* vs_ = Vs + s * FKV_ELEMS;
#pragma unroll
        for (int i = 0; i < 4; i++) {
            int id = tid + i * 128;
            int r = id >> 3, c = (id & 7) * 8;
            cp_async16(ks_ + r * FST + c, Kt_ + (size_t)r * D_QKV + c);
            cp_async16(vs_ + r * FST + c, Vt_ + (size_t)r * D_QKV + c);
        }
        asm volatile("cp.async.commit_group;\n");
    };
    load_kv(0, 0);

    asm volatile("cp.async.wait_group 1;\n");   // Q ready
    __syncthreads();

    // Q a-fragments for both m-frags, scaled by 0.125 (exact in bf16)
    uint32_t qa[2][4][4];
#pragma unroll
    for (int mf = 0; mf < 2; mf++) {
        const __nv_bfloat16* q0 = Qs + (m_w + mf * 16 + g) * FST;
        const __nv_bfloat16* q1 = q0 + 8 * FST;
        __nv_bfloat162 sc2 = __float2bfloat162_rn(0.125f);
#pragma unroll
        for (int kb = 0; kb < 4; kb++) {
            __nv_bfloat162 v;
            v = __hmul2(*(const __nv_bfloat162*)(q0 + kb * 16 + 2 * t), sc2);
            qa[mf][kb][0] = *(uint32_t*)&v;
            v = __hmul2(*(const __nv_bfloat162*)(q1 + kb * 16 + 2 * t), sc2);
            qa[mf][kb][1] = *(uint32_t*)&v;
            v = __hmul2(*(const __nv_bfloat162*)(q0 + kb * 16 + 2 * t + 8), sc2);
            qa[mf][kb][2] = *(uint32_t*)&v;
            v = __hmul2(*(const __nv_bfloat162*)(q1 + kb * 16 + 2 * t + 8), sc2);
            qa[mf][kb][3] = *(uint32_t*)&v;
        }
    }

    float o[2][8][4];
    float m[2][2], l[2][2];
#pragma unroll
    for (int mf = 0; mf < 2; mf++) {
#pragma unroll
        for (int nf = 0; nf < 8; nf++)
#pragma unroll
            for (int i = 0; i < 4; i++) o[mf][nf][i] = 0.f;
        m[mf][0] = m[mf][1] = -CUDART_INF_F;
        l[mf][0] = l[mf][1] = 0.f;
    }

    const int NITER = T_SEQ / 64;   // 32
    for (int kt = 0; kt < NITER; kt++) {
        if (kt + 1 < NITER) {
            load_kv((kt + 1) & 1, kt + 1);
            asm volatile("cp.async.wait_group 1;\n");
        } else {
            asm volatile("cp.async.wait_group 0;\n");
        }
        __syncthreads();

        const __nv_bfloat16* ks_ = Ks + (kt & 1) * FKV_ELEMS;
        const __nv_bfloat16* vs_ = Vs + (kt & 1) * FKV_ELEMS;

        // ---- S = (Q*scale) @ K^T : K b-frags shared across both m-frags ----
        float sf[2][8][4];
#pragma unroll
        for (int nf = 0; nf < 8; nf++) {
            uint32_t b0[4], b1[4];
            const __nv_bfloat16* kp = ks_ + (nf * 8 + (lane & 7)) * FST + (lane >> 3) * 8;
            ldsm_x4(b0[0], b0[1], b0[2], b0[3], kp);
            ldsm_x4(b1[0], b1[1], b1[2], b1[3], kp + 32);
#pragma unroll
            for (int mf = 0; mf < 2; mf++) {
                sf[mf][nf][0] = sf[mf][nf][1] = sf[mf][nf][2] = sf[mf][nf][3] = 0.f;
                { uint32_t bb[2] = {b0[0], b0[1]}; mma_bf16(sf[mf][nf], qa[mf][0], bb); }
                { uint32_t bb[2] = {b0[2], b0[3]}; mma_bf16(sf[mf][nf], qa[mf][1], bb); }
                { uint32_t bb[2] = {b1[0], b1[1]}; mma_bf16(sf[mf][nf], qa[mf][2], bb); }
                { uint32_t bb[2] = {b1[2], b1[3]}; mma_bf16(sf[mf][nf], qa[mf][3], bb); }
            }
        }

        // ---- online softmax (registers only), per m-frag ----
        float sc_[2][2];
#pragma unroll
        for (int mf = 0; mf < 2; mf++) {
            float mx0 = -CUDART_INF_F, mx1 = -CUDART_INF_F;
#pragma unroll
            for (int nf = 0; nf < 8; nf++) {
                mx0 = fmaxf(mx0, fmaxf(sf[mf][nf][0], sf[mf][nf][1]));
                mx1 = fmaxf(mx1, fmaxf(sf[mf][nf][2], sf[mf][nf][3]));
            }
#pragma unroll
            for (int off = 1; off <= 2; off <<= 1) {
                mx0 = fmaxf(mx0, __shfl_xor_sync(0xffffffffu, mx0, off));
                mx1 = fmaxf(mx1, __shfl_xor_sync(0xffffffffu, mx1, off));
            }
            float mn0 = fmaxf(m[mf][0], mx0), mn1 = fmaxf(m[mf][1], mx1);
            sc_[mf][0] = __expf(m[mf][0] - mn0);
            sc_[mf][1] = __expf(m[mf][1] - mn1);
            m[mf][0] = mn0; m[mf][1] = mn1;

            float rs0 = 0.f, rs1 = 0.f;
#pragma unroll
            for (int nf = 0; nf < 8; nf++) {
                sf[mf][nf][0] = __expf(sf[mf][nf][0] - mn0);
                sf[mf][nf][1] = __expf(sf[mf][nf][1] - mn0);
                sf[mf][nf][2] = __expf(sf[mf][nf][2] - mn1);
                sf[mf][nf][3] = __expf(sf[mf][nf][3] - mn1);
                rs0 += sf[mf][nf][0] + sf[mf][nf][1];
                rs1 += sf[mf][nf][2] + sf[mf][nf][3];
            }
#pragma unroll
            for (int off = 1; off <= 2; off <<= 1) {
                rs0 += __shfl_xor_sync(0xffffffffu, rs0, off);
                rs1 += __shfl_xor_sync(0xffffffffu, rs1, off);
            }
            l[mf][0] = l[mf][0] * sc_[mf][0] + rs0;
            l[mf][1] = l[mf][1] * sc_[mf][1] + rs1;
#pragma unroll
            for (int nf = 0; nf < 8; nf++) {
                o[mf][nf][0] *= sc_[mf][0]; o[mf][nf][1] *= sc_[mf][0];
                o[mf][nf][2] *= sc_[mf][1]; o[mf][nf][3] *= sc_[mf][1];
            }
        }

        // ---- O += P @ V : V b-frags shared across both m-frags ----
#pragma unroll
        for (int kb = 0; kb < 4; kb++) {
            uint32_t a[2][4];
#pragma unroll
            for (int mf = 0; mf < 2; mf++) {
                __nv_bfloat162 p;
                p = __float22bfloat162_rn(make_float2(sf[mf][2*kb][0],   sf[mf][2*kb][1]));
                a[mf][0] = *(uint32_t*)&p;
                p = __float22bfloat162_rn(make_float2(sf[mf][2*kb][2],   sf[mf][2*kb][3]));
                a[mf][1] = *(uint32_t*)&p;
                p = __float22bfloat162_rn(make_float2(sf[mf][2*kb+1][0], sf[mf][2*kb+1][1]));
                a[mf][2] = *(uint32_t*)&p;
                p = __float22bfloat162_rn(make_float2(sf[mf][2*kb+1][2], sf[mf][2*kb+1][3]));
                a[mf][3] = *(uint32_t*)&p;
            }
            const __nv_bfloat16* vp = vs_ + (kb * 16 + (lane & 15)) * FST + (lane >> 4) * 8;
#pragma unroll
            for (int nfp = 0; nfp < 4; nfp++) {
                uint32_t v0, v1, v2, v3;
                ldsm_x4_t(v0, v1, v2, v3, vp + nfp * 16);
#pragma unroll
                for (int mf = 0; mf < 2; mf++) {
                    { uint32_t bb[2] = {v0, v1}; mma_bf16(o[mf][2*nfp],     a[mf], bb); }
                    { uint32_t bb[2] = {v2, v3}; mma_bf16(o[mf][2*nfp + 1], a[mf], bb); }
                }
            }
        }
        __syncthreads();   // stage reuse barrier
    }

    // ---- epilogue: O / l, rounded to tf32 (feeds next GEMM A) ----
#pragma unroll
    for (int mf = 0; mf < 2; mf++) {
        float i0 = 1.f / l[mf][0], i1 = 1.f / l[mf][1];
        size_t tok0 = rowB + (size_t)qi * 128 + m_w + mf * 16 + g;
        float* out0 = attn_out + tok0 * D_MODEL + h * D_HEAD;
        float* out1 = out0 + 8 * (size_t)D_MODEL;
#pragma unroll
        for (int nf = 0; nf < 8; nf++) {
            *(float2*)(out0 + nf * 8 + 2 * t) =
                make_float2(f2tf32f(o[mf][nf][0] * i0), f2tf32f(o[mf][nf][1] * i0));
            *(float2*)(out1 + nf * 8 + 2 * t) =
                make_float2(f2tf32f(o[mf][nf][2] * i1), f2tf32f(o[mf][nf][3] * i1));
        }
    }
}

// ---------------------------------------------------------------------------
// Launch
// ---------------------------------------------------------------------------
extern "C" void kernel_launch(void* const* d_in, const int* in_sizes, int n_in,
                              void* d_out, int out_size)
{
    const float* x          = (const float*)d_in[0];
    const float* ln1_g      = (const float*)d_in[1];
    const float* ln1_b      = (const float*)d_in[2];
    const float* qkv_w      = (const float*)d_in[3];
    const float* qkv_b      = (const float*)d_in[4];
    const float* attn_out_w = (const float*)d_in[5];
    const float* attn_out_b = (const float*)d_in[6];
    const float* ln2_g      = (const float*)d_in[7];
    const float* ln2_b      = (const float*)d_in[8];
    const float* ff1_w      = (const float*)d_in[9];
    const float* ff1_b      = (const float*)d_in[10];
    const float* ff2_w      = (const float*)d_in[11];
    const float* ff2_b      = (const float*)d_in[12];
    float* out = (float*)d_out;

    void *p_h, *p_qkvb, *p_attn, *p_x1, *p_mid, *p_w;
    cudaGetSymbolAddress(&p_h,    g_h);
    cudaGetSymbolAddress(&p_qkvb, g_qkvb);
    cudaGetSymbolAddress(&p_attn, g_attn);
    cudaGetSymbolAddress(&p_x1,   g_x1);
    cudaGetSymbolAddress(&p_mid,  g_mid);
    cudaGetSymbolAddress(&p_w,    g_w);
    float* h            = (float*)p_h;
    __nv_bfloat16* qkvb = (__nv_bfloat16*)p_qkvb;
    float* attn         = (float*)p_attn;
    float* x1           = (float*)p_x1;
    float* mid          = (float*)p_mid;
    float* w_qkv        = (float*)p_w;
    float* w_ao         = w_qkv + W_QKV_N;
    float* w_ff1        = w_ao  + W_AO_N;
    float* w_ff2        = w_ff1 + W_FF1_N;

    cudaFuncSetAttribute(flash_bf16_kernel,
                         cudaFuncAttributeMaxDynamicSharedMemorySize,
                         FLASHB_SMEM_BYTES);
    cudaFuncSetAttribute(tf32_gemm_kernel,
                         cudaFuncAttributeMaxDynamicSharedMemorySize,
                         GEMM_SMEM_BYTES);

    // 0. pre-round all weights to tf32 (single launch)
    round_all_kernel<<<(W_TOTAL_N / 4 + 255) / 256, 256>>>(
        qkv_w, attn_out_w, ff1_w, ff2_w, (float*)p_w);

    // 1. h = LN1(x)
    ln_kernel<<<NTOK / 8, 256>>>(x, ln1_g, ln1_b, h);
    // 2. qkv(bf16) = h @ qkv_w + qkv_b
    tf32_gemm_kernel<<<dim3(D_QKV / 128, NTOK / 128), 256, GEMM_SMEM_BYTES>>>(
        h, w_qkv, qkv_b, nullptr, (float*)qkvb, NTOK, D_QKV, D_MODEL, 0, 1);
    // 3. attention (bf16 tensor cores, 32 rows/warp, 2 CTAs/SM)
    flash_bf16_kernel<<<dim3(T_SEQ / 128, N_HEADS, B_SZ), 128, FLASHB_SMEM_BYTES>>>(
        qkvb, attn);
    // 4. x1 = x + attn @ attn_out_w + attn_out_b
    tf32_gemm_kernel<<<dim3(D_MODEL / 128, NTOK / 128), 256, GEMM_SMEM_BYTES>>>(
        attn, w_ao, attn_out_b, x, x1, NTOK, D_MODEL, D_MODEL, 2, 0);
    // 5. h = LN2(x1)
    ln_kernel<<<NTOK / 8, 256>>>(x1, ln2_g, ln2_b, h);
    // 6. mid = gelu(h @ ff1_w + ff1_b)
    tf32_gemm_kernel<<<dim3(D_FF / 128, NTOK / 128), 256, GEMM_SMEM_BYTES>>>(
        h, w_ff1, ff1_b, nullptr, mid, NTOK, D_FF, D_MODEL, 1, 0);
    // 7. out = x1 + mid @ ff2_w + ff2_b
    tf32_gemm_kernel<<<dim3(D_MODEL / 128, NTOK / 128), 256, GEMM_SMEM_BYTES>>>(
        mid, w_ff2, ff2_b, x1, out, NTOK, D_MODEL, D_FF, 2, 0);
}

// round 8
// speedup vs baseline: 7.2211x; 1.6966x over previous
#include <cuda_runtime.h>
#include <cuda_fp16.h>
#include <math_constants.h>
#include <cstdint>
#include <cstddef>

// ---------------------------------------------------------------------------
// Problem constants
// ---------------------------------------------------------------------------
#define D_MODEL 768
#define N_HEADS 12
#define D_HEAD  64
#define D_FF    3072
#define B_SZ    4
#define T_SEQ   2048
#define NTOK    (B_SZ * T_SEQ)      // 8192
#define D_QKV   (3 * D_MODEL)       // 2304
#define LN_EPS  1e-5f

#define W_QKV_N   (D_MODEL * D_QKV)
#define W_AO_N    (D_MODEL * D_MODEL)
#define W_FF1_N   (D_MODEL * D_FF)
#define W_FF2_N   (D_FF * D_MODEL)
#define W_TOTAL_N (W_QKV_N + W_AO_N + W_FF1_N + W_FF2_N)

// ---------------------------------------------------------------------------
// Scratch (device globals)
// ---------------------------------------------------------------------------
__device__ __half  g_h   [NTOK * D_MODEL];   // LN output (fp16)
__device__ __half  g_qkv [NTOK * D_QKV];     // qkv (fp16)
__device__ __half  g_attn[NTOK * D_MODEL];   // attention out (fp16)
__device__ float   g_x1  [NTOK * D_MODEL];   // residual 1 (fp32)
__device__ __half  g_mid [NTOK * D_FF];      // gelu(ff1) (fp16)
__device__ __half  g_w   [W_TOTAL_N];        // fp16 weights

// ---------------------------------------------------------------------------
// weight conversion fp32 -> fp16 (single launch)
// ---------------------------------------------------------------------------
__global__ __launch_bounds__(256) void round_all_kernel(
    const float* __restrict__ w0, const float* __restrict__ w1,
    const float* __restrict__ w2, const float* __restrict__ w3,
    __half* __restrict__ dst)
{
    int i = (blockIdx.x * blockDim.x + threadIdx.x) * 4;
    if (i >= W_TOTAL_N) return;
    const float* src;
    int off;
    if (i < W_QKV_N)                        { src = w0; off = 0; }
    else if (i < W_QKV_N + W_AO_N)          { src = w1; off = W_QKV_N; }
    else if (i < W_QKV_N + W_AO_N + W_FF1_N){ src = w2; off = W_QKV_N + W_AO_N; }
    else                                    { src = w3; off = W_QKV_N + W_AO_N + W_FF1_N; }
    float4 v = *(const float4*)(src + (i - off));
    __half2 h0 = __floats2half2_rn(v.x, v.y);
    __half2 h1 = __floats2half2_rn(v.z, v.w);
    uint2 packed = make_uint2(*(uint32_t*)&h0, *(uint32_t*)&h1);
    *(uint2*)(dst + i) = packed;
}

// ---------------------------------------------------------------------------
// LayerNorm: one warp per token; fp16 output (feeds GEMM A)
// ---------------------------------------------------------------------------
__global__ __launch_bounds__(256) void ln_kernel(
    const float* __restrict__ x, const float* __restrict__ g,
    const float* __restrict__ b, __half* __restrict__ out)
{
    int warp = (blockIdx.x * blockDim.x + threadIdx.x) >> 5;
    int lane = threadIdx.x & 31;
    if (warp >= NTOK) return;
    const float* xr = x + (size_t)warp * D_MODEL;
    float v[24];
    float s = 0.f;
#pragma unroll
    for (int i = 0; i < 24; i++) { v[i] = xr[lane + 32 * i]; s += v[i]; }
#pragma unroll
    for (int off = 16; off > 0; off >>= 1) s += __shfl_xor_sync(0xffffffffu, s, off);
    float mu = s * (1.f / D_MODEL);
    float sq = 0.f;
#pragma unroll
    for (int i = 0; i < 24; i++) { float d = v[i] - mu; sq += d * d; }
#pragma unroll
    for (int off = 16; off > 0; off >>= 1) sq += __shfl_xor_sync(0xffffffffu, sq, off);
    float rs = rsqrtf(sq * (1.f / D_MODEL) + LN_EPS);
    __half* orow = out + (size_t)warp * D_MODEL;
#pragma unroll
    for (int i = 0; i < 24; i++) {
        int c = lane + 32 * i;
        orow[c] = __float2half_rn((v[i] - mu) * rs * g[c] + b[c]);
    }
}

// ---------------------------------------------------------------------------
// GELU (tanh approx)
// ---------------------------------------------------------------------------
__device__ __forceinline__ float gelu_tanh(float x) {
    float x3 = x * x * x;
    float t = tanhf(0.7978845608028654f * (x + 0.044715f * x3));
    return 0.5f * x * (1.f + t);
}

// ---------------------------------------------------------------------------
// mma / ldmatrix helpers
// ---------------------------------------------------------------------------
__device__ __forceinline__ void mma_fp16(float c[4], const uint32_t a[4],
                                         const uint32_t b[2]) {
    asm volatile(
        "mma.sync.aligned.m16n8k16.row.col.f32.f16.f16.f32 "
        "{%0,%1,%2,%3}, {%4,%5,%6,%7}, {%8,%9}, {%0,%1,%2,%3};"
        : "+f"(c[0]), "+f"(c[1]), "+f"(c[2]), "+f"(c[3])
        : "r"(a[0]), "r"(a[1]), "r"(a[2]), "r"(a[3]), "r"(b[0]), "r"(b[1]));
}

__device__ __forceinline__ void ldsm_x4(uint32_t& r0, uint32_t& r1,
                                        uint32_t& r2, uint32_t& r3,
                                        const void* p) {
    uint32_t sa = (uint32_t)__cvta_generic_to_shared(p);
    asm volatile("ldmatrix.sync.aligned.m8n8.x4.shared.b16 {%0,%1,%2,%3}, [%4];"
                 : "=r"(r0), "=r"(r1), "=r"(r2), "=r"(r3) : "r"(sa));
}

__device__ __forceinline__ void ldsm_x4_t(uint32_t& r0, uint32_t& r1,
                                          uint32_t& r2, uint32_t& r3,
                                          const void* p) {
    uint32_t sa = (uint32_t)__cvta_generic_to_shared(p);
    asm volatile("ldmatrix.sync.aligned.m8n8.x4.trans.shared.b16 {%0,%1,%2,%3}, [%4];"
                 : "=r"(r0), "=r"(r1), "=r"(r2), "=r"(r3) : "r"(sa));
}

__device__ __forceinline__ void cp_async16(void* smem_dst, const void* gsrc) {
    uint32_t d = (uint32_t)__cvta_generic_to_shared(smem_dst);
    asm volatile("cp.async.ca.shared.global [%0], [%1], 16;\n" ::"r"(d), "l"(gsrc));
}

// ---------------------------------------------------------------------------
// fp16 tensor-core GEMM: C[M,N] = A[M,K] @ W[K,N] + bias (+ epilogue)
//   A, W fp16; accumulate fp32. epi: 0 none, 1 gelu, 2 +resid.
//   out_half: 1 -> fp16 output, 0 -> fp32 output.
// Block 128x128, BK=32, 256 thr (8 warps, 64x32 warp tiles), 2-stage cp.async.
// A frags and B frags via ldmatrix (conflict-free strides).
// ---------------------------------------------------------------------------
#define AH_STRIDE 40                        // halfs per A row (80B)
#define BH_STRIDE 136                       // halfs per B row (272B)
#define AH_HALFS (128 * AH_STRIDE)          // 5120 per stage
#define BH_HALFS (32 * BH_STRIDE)           // 4352 per stage
#define GEMM_SMEM_BYTES ((2 * AH_HALFS + 2 * BH_HALFS) * 2)   // 37888 B

__global__ __launch_bounds__(256, 2) void fp16_gemm_kernel(
    const __half* __restrict__ A, const __half* __restrict__ W,
    const float* __restrict__ bias, const float* __restrict__ resid,
    void* __restrict__ Cv, int M, int N, int K, int epi, int out_half)
{
    extern __shared__ __half smh[];
    __half* Asm = smh;
    __half* Bsm = smh + 2 * AH_HALFS;

    int tid = threadIdx.x;
    int lane = tid & 31;
    int warp = tid >> 5;
    int g = lane >> 2;
    int t = lane & 3;
    int m_w = (warp >> 2) * 64;
    int n_w = (warp & 3) * 32;

    int rowBase = blockIdx.y * 128;
    int colBase = blockIdx.x * 128;

    const __half* Ag = A + (size_t)rowBase * K;
    const __half* Wg = W + colBase;

    float acc[4][4][4];
#pragma unroll
    for (int mf = 0; mf < 4; mf++)
#pragma unroll
        for (int nf = 0; nf < 4; nf++)
#pragma unroll
            for (int i = 0; i < 4; i++) acc[mf][nf][i] = 0.f;

    int ntiles = K / 32;

    auto issue_copy = [&](int s, int kt) {
        __half* as = Asm + s * AH_HALFS;
        __half* bs = Bsm + s * BH_HALFS;
#pragma unroll
        for (int i = 0; i < 2; i++) {
            int id = tid + i * 256;
            int r = id >> 2;            // 0..127
            int c = (id & 3) * 8;       // 0..24
            cp_async16(as + r * AH_STRIDE + c, Ag + (size_t)r * K + kt + c);
        }
#pragma unroll
        for (int i = 0; i < 2; i++) {
            int id = tid + i * 256;
            int r = id >> 4;            // 0..31
            int c = (id & 15) * 8;      // 0..120
            cp_async16(bs + r * BH_STRIDE + c, Wg + (size_t)(kt + r) * N + c);
        }
        asm volatile("cp.async.commit_group;\n");
    };

    issue_copy(0, 0);

    for (int kt = 0; kt < ntiles; kt++) {
        if (kt + 1 < ntiles) {
            issue_copy((kt + 1) & 1, (kt + 1) * 32);
            asm volatile("cp.async.wait_group 1;\n");
        } else {
            asm volatile("cp.async.wait_group 0;\n");
        }
        __syncthreads();

        const __half* as = Asm + (kt & 1) * AH_HALFS;
        const __half* bs = Bsm + (kt & 1) * BH_HALFS;

#pragma unroll
        for (int ks = 0; ks < 2; ks++) {
            uint32_t af[4][4];
#pragma unroll
            for (int mf = 0; mf < 4; mf++) {
                const __half* ap = as + (m_w + mf * 16 + (lane & 15)) * AH_STRIDE
                                      + ks * 16 + (lane >> 4) * 8;
                ldsm_x4(af[mf][0], af[mf][1], af[mf][2], af[mf][3], ap);
            }
            uint32_t bfr[2][4];
#pragma unroll
            for (int nfp = 0; nfp < 2; nfp++) {
                const __half* bp = bs + (ks * 16 + (lane & 15)) * BH_STRIDE
                                      + n_w + nfp * 16 + (lane >> 4) * 8;
                ldsm_x4_t(bfr[nfp][0], bfr[nfp][1], bfr[nfp][2], bfr[nfp][3], bp);
            }
#pragma unroll
            for (int mf = 0; mf < 4; mf++)
#pragma unroll
                for (int nf = 0; nf < 4; nf++) {
                    int nfp = nf >> 1, pr = nf & 1;
                    uint32_t bb[2] = {bfr[nfp][2 * pr], bfr[nfp][2 * pr + 1]};
                    mma_fp16(acc[mf][nf], af[mf], bb);
                }
        }
        __syncthreads();
    }

#pragma unroll
    for (int mf = 0; mf < 4; mf++) {
        int row0 = rowBase + m_w + mf * 16 + g;
        int row1 = row0 + 8;
#pragma unroll
        for (int nf = 0; nf < 4; nf++) {
            int col = colBase + n_w + nf * 8 + 2 * t;
            float2 bv = *(const float2*)&bias[col];
            float v00 = acc[mf][nf][0] + bv.x;
            float v01 = acc[mf][nf][1] + bv.y;
            float v10 = acc[mf][nf][2] + bv.x;
            float v11 = acc[mf][nf][3] + bv.y;
            if (epi == 1) {
                v00 = gelu_tanh(v00); v01 = gelu_tanh(v01);
                v10 = gelu_tanh(v10); v11 = gelu_tanh(v11);
            } else if (epi == 2) {
                float2 r0 = *(const float2*)&resid[(size_t)row0 * N + col];
                float2 r1 = *(const float2*)&resid[(size_t)row1 * N + col];
                v00 += r0.x; v01 += r0.y; v10 += r1.x; v11 += r1.y;
            }
            if (out_half) {
                __half* Ch = (__half*)Cv;
                __half2 p0 = __floats2half2_rn(v00, v01);
                __half2 p1 = __floats2half2_rn(v10, v11);
                *(uint32_t*)&Ch[(size_t)row0 * N + col] = *(uint32_t*)&p0;
                *(uint32_t*)&Ch[(size_t)row1 * N + col] = *(uint32_t*)&p1;
            } else {
                float* C = (float*)Cv;
                *(float2*)&C[(size_t)row0 * N + col] = make_float2(v00, v01);
                *(float2*)&C[(size_t)row1 * N + col] = make_float2(v10, v11);
            }
        }
    }
}

// ---------------------------------------------------------------------------
// Flash attention, fp16 mma. BQ=128, 4 warps x 32 Q rows (2 m-frags/warp),
// BK=64, 2-stage. Same structure as R7, fp16 types (better precision too).
// ---------------------------------------------------------------------------
#define FST 72                         // halfs per smem row (144B)
#define FQ_ELEMS (128 * FST)
#define FKV_ELEMS (64 * FST)
#define FLASHB_SMEM_BYTES ((FQ_ELEMS + 4 * FKV_ELEMS) * 2)   // 55296 B

__global__ __launch_bounds__(128, 2) void flash_fp16_kernel(
    const __half* __restrict__ qkv, __half* __restrict__ attn_out)
{
    extern __shared__ __align__(16) char smraw[];
    __half* Qs = (__half*)smraw;
    __half* Ks = Qs + FQ_ELEMS;        // 2 stages x 64 rows
    __half* Vs = Ks + 2 * FKV_ELEMS;   // 2 stages x 64 rows

    int qi = blockIdx.x, h = blockIdx.y, bz = blockIdx.z;
    int tid = threadIdx.x;
    int lane = tid & 31;
    int warp = tid >> 5;            // 0..3
    int g = lane >> 2, t = lane & 3;
    int m_w = warp * 32;            // 32 rows per warp

    size_t rowB = (size_t)bz * T_SEQ;
    const __half* Qg = qkv + (rowB + (size_t)qi * 128) * D_QKV + h * D_HEAD;
    const __half* Kg = qkv + rowB * D_QKV + D_MODEL     + h * D_HEAD;
    const __half* Vg = qkv + rowB * D_QKV + 2 * D_MODEL + h * D_HEAD;

    // stage Q: 128 rows x 64 cols (8 chunks/thread)
#pragma unroll
    for (int i = 0; i < 8; i++) {
        int id = tid + i * 128;
        int r = id >> 3, c = (id & 7) * 8;
        cp_async16(Qs + r * FST + c, Qg + (size_t)r * D_QKV + c);
    }
    asm volatile("cp.async.commit_group;\n");

    auto load_kv = [&](int s, int kt) {
        const __half* Kt_ = Kg + (size_t)kt * 64 * D_QKV;
        const __half* Vt_ = Vg + (size_t)kt * 64 * D_QKV;
        __half* ks_ = Ks + s * FKV_ELEMS;
        __half* vs_ = Vs + s * FKV_ELEMS;
#pragma unroll
        for (int i = 0; i < 4; i++) {
            int id = tid + i * 128;
            int r = id >> 3, c = (id & 7) * 8;
            cp_async16(ks_ + r * FST + c, Kt_ + (size_t)r * D_QKV + c);
            cp_async16(vs_ + r * FST + c, Vt_ + (size_t)r * D_QKV + c);
        }
        asm volatile("cp.async.commit_group;\n");
    };
    load_kv(0, 0);

    asm volatile("cp.async.wait_group 1;\n");   // Q ready
    __syncthreads();

    // Q a-fragments for both m-frags, scaled by 0.125 (exact in fp16)
    uint32_t qa[2][4][4];
#pragma unroll
    for (int mf = 0; mf < 2; mf++) {
        const __half* q0 = Qs + (m_w + mf * 16 + g) * FST;
        const __half* q1 = q0 + 8 * FST;
        __half2 sc2 = __float2half2_rn(0.125f);
#pragma unroll
        for (int kb = 0; kb < 4; kb++) {
            __half2 v;
            v = __hmul2(*(const __half2*)(q0 + kb * 16 + 2 * t), sc2);
            qa[mf][kb][0] = *(uint32_t*)&v;
            v = __hmul2(*(const __half2*)(q1 + kb * 16 + 2 * t), sc2);
            qa[mf][kb][1] = *(uint32_t*)&v;
            v = __hmul2(*(const __half2*)(q0 + kb * 16 + 2 * t + 8), sc2);
            qa[mf][kb][2] = *(uint32_t*)&v;
            v = __hmul2(*(const __half2*)(q1 + kb * 16 + 2 * t + 8), sc2);
            qa[mf][kb][3] = *(uint32_t*)&v;
        }
    }

    float o[2][8][4];
    float m[2][2], l[2][2];
#pragma unroll
    for (int mf = 0; mf < 2; mf++) {
#pragma unroll
        for (int nf = 0; nf < 8; nf++)
#pragma unroll
            for (int i = 0; i < 4; i++) o[mf][nf][i] = 0.f;
        m[mf][0] = m[mf][1] = -CUDART_INF_F;
        l[mf][0] = l[mf][1] = 0.f;
    }

    const int NITER = T_SEQ / 64;   // 32
    for (int kt = 0; kt < NITER; kt++) {
        if (kt + 1 < NITER) {
            load_kv((kt + 1) & 1, kt + 1);
            asm volatile("cp.async.wait_group 1;\n");
        } else {
            asm volatile("cp.async.wait_group 0;\n");
        }
        __syncthreads();

        const __half* ks_ = Ks + (kt & 1) * FKV_ELEMS;
        const __half* vs_ = Vs + (kt & 1) * FKV_ELEMS;

        // ---- S = (Q*scale) @ K^T : K b-frags shared across both m-frags ----
        float sf[2][8][4];
#pragma unroll
        for (int nf = 0; nf < 8; nf++) {
            uint32_t b0[4], b1[4];
            const __half* kp = ks_ + (nf * 8 + (lane & 7)) * FST + (lane >> 3) * 8;
            ldsm_x4(b0[0], b0[1], b0[2], b0[3], kp);
            ldsm_x4(b1[0], b1[1], b1[2], b1[3], kp + 32);
#pragma unroll
            for (int mf = 0; mf < 2; mf++) {
                sf[mf][nf][0] = sf[mf][nf][1] = sf[mf][nf][2] = sf[mf][nf][3] = 0.f;
                { uint32_t bb[2] = {b0[0], b0[1]}; mma_fp16(sf[mf][nf], qa[mf][0], bb); }
                { uint32_t bb[2] = {b0[2], b0[3]}; mma_fp16(sf[mf][nf], qa[mf][1], bb); }
                { uint32_t bb[2] = {b1[0], b1[1]}; mma_fp16(sf[mf][nf], qa[mf][2], bb); }
                { uint32_t bb[2] = {b1[2], b1[3]}; mma_fp16(sf[mf][nf], qa[mf][3], bb); }
            }
        }

        // ---- online softmax (registers only), per m-frag ----
        float sc_[2][2];
#pragma unroll
        for (int mf = 0; mf < 2; mf++) {
            float mx0 = -CUDART_INF_F, mx1 = -CUDART_INF_F;
#pragma unroll
            for (int nf = 0; nf < 8; nf++) {
                mx0 = fmaxf(mx0, fmaxf(sf[mf][nf][0], sf[mf][nf][1]));
                mx1 = fmaxf(mx1, fmaxf(sf[mf][nf][2], sf[mf][nf][3]));
            }
#pragma unroll
            for (int off = 1; off <= 2; off <<= 1) {
                mx0 = fmaxf(mx0, __shfl_xor_sync(0xffffffffu, mx0, off));
                mx1 = fmaxf(mx1, __shfl_xor_sync(0xffffffffu, mx1, off));
            }
            float mn0 = fmaxf(m[mf][0], mx0), mn1 = fmaxf(m[mf][1], mx1);
            sc_[mf][0] = __expf(m[mf][0] - mn0);
            sc_[mf][1] = __expf(m[mf][1] - mn1);
            m[mf][0] = mn0; m[mf][1] = mn1;

            float rs0 = 0.f, rs1 = 0.f;
#pragma unroll
            for (int nf = 0; nf < 8; nf++) {
                sf[mf][nf][0] = __expf(sf[mf][nf][0] - mn0);
                sf[mf][nf][1] = __expf(sf[mf][nf][1] - mn0);
                sf[mf][nf][2] = __expf(sf[mf][nf][2] - mn1);
                sf[mf][nf][3] = __expf(sf[mf][nf][3] - mn1);
                rs0 += sf[mf][nf][0] + sf[mf][nf][1];
                rs1 += sf[mf][nf][2] + sf[mf][nf][3];
            }
#pragma unroll
            for (int off = 1; off <= 2; off <<= 1) {
                rs0 += __shfl_xor_sync(0xffffffffu, rs0, off);
                rs1 += __shfl_xor_sync(0xffffffffu, rs1, off);
            }
            l[mf][0] = l[mf][0] * sc_[mf][0] + rs0;
            l[mf][1] = l[mf][1] * sc_[mf][1] + rs1;
#pragma unroll
            for (int nf = 0; nf < 8; nf++) {
                o[mf][nf][0] *= sc_[mf][0]; o[mf][nf][1] *= sc_[mf][0];
                o[mf][nf][2] *= sc_[mf][1]; o[mf][nf][3] *= sc_[mf][1];
            }
        }

        // ---- O += P @ V : V b-frags shared across both m-frags ----
#pragma unroll
        for (int kb = 0; kb < 4; kb++) {
            uint32_t a[2][4];
#pragma unroll
            for (int mf = 0; mf < 2; mf++) {
                __half2 p;
                p = __floats2half2_rn(sf[mf][2*kb][0],   sf[mf][2*kb][1]);
                a[mf][0] = *(uint32_t*)&p;
                p = __floats2half2_rn(sf[mf][2*kb][2],   sf[mf][2*kb][3]);
                a[mf][1] = *(uint32_t*)&p;
                p = __floats2half2_rn(sf[mf][2*kb+1][0], sf[mf][2*kb+1][1]);
                a[mf][2] = *(uint32_t*)&p;
                p = __floats2half2_rn(sf[mf][2*kb+1][2], sf[mf][2*kb+1][3]);
                a[mf][3] = *(uint32_t*)&p;
            }
            const __half* vp = vs_ + (kb * 16 + (lane & 15)) * FST + (lane >> 4) * 8;
#pragma unroll
            for (int nfp = 0; nfp < 4; nfp++) {
                uint32_t v0, v1, v2, v3;
                ldsm_x4_t(v0, v1, v2, v3, vp + nfp * 16);
#pragma unroll
                for (int mf = 0; mf < 2; mf++) {
                    { uint32_t bb[2] = {v0, v1}; mma_fp16(o[mf][2*nfp],     a[mf], bb); }
                    { uint32_t bb[2] = {v2, v3}; mma_fp16(o[mf][2*nfp + 1], a[mf], bb); }
                }
            }
        }
        __syncthreads();   // stage reuse barrier
    }

    // ---- epilogue: O / l -> fp16 attn (feeds next GEMM A) ----
#pragma unroll
    for (int mf = 0; mf < 2; mf++) {
        float i0 = 1.f / l[mf][0], i1 = 1.f / l[mf][1];
        size_t tok0 = rowB + (size_t)qi * 128 + m_w + mf * 16 + g;
        __half* out0 = attn_out + tok0 * D_MODEL + h * D_HEAD;
        __half* out1 = out0 + 8 * (size_t)D_MODEL;
#pragma unroll
        for (int nf = 0; nf < 8; nf++) {
            __half2 p0 = __floats2half2_rn(o[mf][nf][0] * i0, o[mf][nf][1] * i0);
            __half2 p1 = __floats2half2_rn(o[mf][nf][2] * i1, o[mf][nf][3] * i1);
            *(uint32_t*)(out0 + nf * 8 + 2 * t) = *(uint32_t*)&p0;
            *(uint32_t*)(out1 + nf * 8 + 2 * t) = *(uint32_t*)&p1;
        }
    }
}

// ---------------------------------------------------------------------------
// Launch
// ---------------------------------------------------------------------------
extern "C" void kernel_launch(void* const* d_in, const int* in_sizes, int n_in,
                              void* d_out, int out_size)
{
    const float* x          = (const float*)d_in[0];
    const float* ln1_g      = (const float*)d_in[1];
    const float* ln1_b      = (const float*)d_in[2];
    const float* qkv_w      = (const float*)d_in[3];
    const float* qkv_b      = (const float*)d_in[4];
    const float* attn_out_w = (const float*)d_in[5];
    const float* attn_out_b = (const float*)d_in[6];
    const float* ln2_g      = (const float*)d_in[7];
    const float* ln2_b      = (const float*)d_in[8];
    const float* ff1_w      = (const float*)d_in[9];
    const float* ff1_b      = (const float*)d_in[10];
    const float* ff2_w      = (const float*)d_in[11];
    const float* ff2_b      = (const float*)d_in[12];
    float* out = (float*)d_out;

    void *p_h, *p_qkv, *p_attn, *p_x1, *p_mid, *p_w;
    cudaGetSymbolAddress(&p_h,    g_h);
    cudaGetSymbolAddress(&p_qkv,  g_qkv);
    cudaGetSymbolAddress(&p_attn, g_attn);
    cudaGetSymbolAddress(&p_x1,   g_x1);
    cudaGetSymbolAddress(&p_mid,  g_mid);
    cudaGetSymbolAddress(&p_w,    g_w);
    __half* h    = (__half*)p_h;
    __half* qkv  = (__half*)p_qkv;
    __half* attn = (__half*)p_attn;
    float*  x1   = (float*)p_x1;
    __half* mid  = (__half*)p_mid;
    __half* w_qkv = (__half*)p_w;
    __half* w_ao  = w_qkv + W_QKV_N;
    __half* w_ff1 = w_ao  + W_AO_N;
    __half* w_ff2 = w_ff1 + W_FF1_N;

    cudaFuncSetAttribute(flash_fp16_kernel,
                         cudaFuncAttributeMaxDynamicSharedMemorySize,
                         FLASHB_SMEM_BYTES);
    cudaFuncSetAttribute(fp16_gemm_kernel,
                         cudaFuncAttributeMaxDynamicSharedMemorySize,
                         GEMM_SMEM_BYTES);

    // 0. convert all weights to fp16 (single launch)
    round_all_kernel<<<(W_TOTAL_N / 4 + 255) / 256, 256>>>(
        qkv_w, attn_out_w, ff1_w, ff2_w, (__half*)p_w);

    // 1. h = LN1(x)  (fp16 out)
    ln_kernel<<<NTOK / 8, 256>>>(x, ln1_g, ln1_b, h);
    // 2. qkv(fp16) = h @ qkv_w + qkv_b
    fp16_gemm_kernel<<<dim3(D_QKV / 128, NTOK / 128), 256, GEMM_SMEM_BYTES>>>(
        h, w_qkv, qkv_b, nullptr, qkv, NTOK, D_QKV, D_MODEL, 0, 1);
    // 3. attention (fp16 tensor cores)
    flash_fp16_kernel<<<dim3(T_SEQ / 128, N_HEADS, B_SZ), 128, FLASHB_SMEM_BYTES>>>(
        qkv, attn);
    // 4. x1 = x + attn @ attn_out_w + attn_out_b  (fp32 out)
    fp16_gemm_kernel<<<dim3(D_MODEL / 128, NTOK / 128), 256, GEMM_SMEM_BYTES>>>(
        attn, w_ao, attn_out_b, x, x1, NTOK, D_MODEL, D_MODEL, 2, 0);
    // 5. h = LN2(x1)  (fp16 out)
    ln_kernel<<<NTOK / 8, 256>>>(x1, ln2_g, ln2_b, h);
    // 6. mid = gelu(h @ ff1_w + ff1_b)  (fp16 out)
    fp16_gemm_kernel<<<dim3(D_FF / 128, NTOK / 128), 256, GEMM_SMEM_BYTES>>>(
        h, w_ff1, ff1_b, nullptr, mid, NTOK, D_FF, D_MODEL, 1, 1);
    // 7. out = x1 + mid @ ff2_w + ff2_b  (fp32 out)
    fp16_gemm_kernel<<<dim3(D_MODEL / 128, NTOK / 128), 256, GEMM_SMEM_BYTES>>>(
        mid, w_ff2, ff2_b, x1, out, NTOK, D_MODEL, D_FF, 2, 0);
}

// round 9
// speedup vs baseline: 7.4136x; 1.0267x over previous
#include <cuda_runtime.h>
#include <cuda_fp16.h>
#include <math_constants.h>
#include <cstdint>
#include <cstddef>

// ---------------------------------------------------------------------------
// Problem constants
// ---------------------------------------------------------------------------
#define D_MODEL 768
#define N_HEADS 12
#define D_HEAD  64
#define D_FF    3072
#define B_SZ    4
#define T_SEQ   2048
#define NTOK    (B_SZ * T_SEQ)      // 8192
#define D_QKV   (3 * D_MODEL)       // 2304
#define LN_EPS  1e-5f

#define W_QKV_N   (D_MODEL * D_QKV)
#define W_AO_N    (D_MODEL * D_MODEL)
#define W_FF1_N   (D_MODEL * D_FF)
#define W_FF2_N   (D_FF * D_MODEL)
#define W_TOTAL_N (W_QKV_N + W_AO_N + W_FF1_N + W_FF2_N)

// ---------------------------------------------------------------------------
// Scratch (device globals)
// ---------------------------------------------------------------------------
__device__ __half  g_h   [NTOK * D_MODEL];
__device__ __half  g_qkv [NTOK * D_QKV];
__device__ __half  g_attn[NTOK * D_MODEL];
__device__ float   g_x1  [NTOK * D_MODEL];
__device__ __half  g_mid [NTOK * D_FF];
__device__ __half  g_w   [W_TOTAL_N];

// ---------------------------------------------------------------------------
// weight conversion fp32 -> fp16 (single launch)
// ---------------------------------------------------------------------------
__global__ __launch_bounds__(256) void round_all_kernel(
    const float* __restrict__ w0, const float* __restrict__ w1,
    const float* __restrict__ w2, const float* __restrict__ w3,
    __half* __restrict__ dst)
{
    int i = (blockIdx.x * blockDim.x + threadIdx.x) * 4;
    if (i >= W_TOTAL_N) return;
    const float* src;
    int off;
    if (i < W_QKV_N)                        { src = w0; off = 0; }
    else if (i < W_QKV_N + W_AO_N)          { src = w1; off = W_QKV_N; }
    else if (i < W_QKV_N + W_AO_N + W_FF1_N){ src = w2; off = W_QKV_N + W_AO_N; }
    else                                    { src = w3; off = W_QKV_N + W_AO_N + W_FF1_N; }
    float4 v = *(const float4*)(src + (i - off));
    __half2 h0 = __floats2half2_rn(v.x, v.y);
    __half2 h1 = __floats2half2_rn(v.z, v.w);
    uint2 packed = make_uint2(*(uint32_t*)&h0, *(uint32_t*)&h1);
    *(uint2*)(dst + i) = packed;
}

// ---------------------------------------------------------------------------
// LayerNorm: one warp per token; fp16 output
// ---------------------------------------------------------------------------
__global__ __launch_bounds__(256) void ln_kernel(
    const float* __restrict__ x, const float* __restrict__ g,
    const float* __restrict__ b, __half* __restrict__ out)
{
    int warp = (blockIdx.x * blockDim.x + threadIdx.x) >> 5;
    int lane = threadIdx.x & 31;
    if (warp >= NTOK) return;
    const float* xr = x + (size_t)warp * D_MODEL;
    float v[24];
    float s = 0.f;
#pragma unroll
    for (int i = 0; i < 24; i++) { v[i] = xr[lane + 32 * i]; s += v[i]; }
#pragma unroll
    for (int off = 16; off > 0; off >>= 1) s += __shfl_xor_sync(0xffffffffu, s, off);
    float mu = s * (1.f / D_MODEL);
    float sq = 0.f;
#pragma unroll
    for (int i = 0; i < 24; i++) { float d = v[i] - mu; sq += d * d; }
#pragma unroll
    for (int off = 16; off > 0; off >>= 1) sq += __shfl_xor_sync(0xffffffffu, sq, off);
    float rs = rsqrtf(sq * (1.f / D_MODEL) + LN_EPS);
    __half* orow = out + (size_t)warp * D_MODEL;
#pragma unroll
    for (int i = 0; i < 24; i++) {
        int c = lane + 32 * i;
        orow[c] = __float2half_rn((v[i] - mu) * rs * g[c] + b[c]);
    }
}

// ---------------------------------------------------------------------------
// GELU (tanh approx)
// ---------------------------------------------------------------------------
__device__ __forceinline__ float gelu_tanh(float x) {
    float x3 = x * x * x;
    float t = tanhf(0.7978845608028654f * (x + 0.044715f * x3));
    return 0.5f * x * (1.f + t);
}

// ---------------------------------------------------------------------------
// mma / ldmatrix helpers
// ---------------------------------------------------------------------------
__device__ __forceinline__ void mma_fp16(float c[4], const uint32_t a[4],
                                         const uint32_t b[2]) {
    asm volatile(
        "mma.sync.aligned.m16n8k16.row.col.f32.f16.f16.f32 "
        "{%0,%1,%2,%3}, {%4,%5,%6,%7}, {%8,%9}, {%0,%1,%2,%3};"
        : "+f"(c[0]), "+f"(c[1]), "+f"(c[2]), "+f"(c[3])
        : "r"(a[0]), "r"(a[1]), "r"(a[2]), "r"(a[3]), "r"(b[0]), "r"(b[1]));
}

// fp16-accumulate variant: C is 2 regs of f16x2
__device__ __forceinline__ void mma_f16acc(uint32_t c[2], const uint32_t a[4],
                                           const uint32_t b[2]) {
    asm volatile(
        "mma.sync.aligned.m16n8k16.row.col.f16.f16.f16.f16 "
        "{%0,%1}, {%2,%3,%4,%5}, {%6,%7}, {%0,%1};"
        : "+r"(c[0]), "+r"(c[1])
        : "r"(a[0]), "r"(a[1]), "r"(a[2]), "r"(a[3]), "r"(b[0]), "r"(b[1]));
}

__device__ __forceinline__ __half2 h2exp2_(__half2 x) {
    uint32_t r, xi = *(uint32_t*)&x;
    asm("ex2.approx.f16x2 %0, %1;" : "=r"(r) : "r"(xi));
    return *(__half2*)&r;
}

__device__ __forceinline__ void ldsm_x4(uint32_t& r0, uint32_t& r1,
                                        uint32_t& r2, uint32_t& r3,
                                        const void* p) {
    uint32_t sa = (uint32_t)__cvta_generic_to_shared(p);
    asm volatile("ldmatrix.sync.aligned.m8n8.x4.shared.b16 {%0,%1,%2,%3}, [%4];"
                 : "=r"(r0), "=r"(r1), "=r"(r2), "=r"(r3) : "r"(sa));
}

__device__ __forceinline__ void ldsm_x4_t(uint32_t& r0, uint32_t& r1,
                                          uint32_t& r2, uint32_t& r3,
                                          const void* p) {
    uint32_t sa = (uint32_t)__cvta_generic_to_shared(p);
    asm volatile("ldmatrix.sync.aligned.m8n8.x4.trans.shared.b16 {%0,%1,%2,%3}, [%4];"
                 : "=r"(r0), "=r"(r1), "=r"(r2), "=r"(r3) : "r"(sa));
}

__device__ __forceinline__ void cp_async16(void* smem_dst, const void* gsrc) {
    uint32_t d = (uint32_t)__cvta_generic_to_shared(smem_dst);
    asm volatile("cp.async.ca.shared.global [%0], [%1], 16;\n" ::"r"(d), "l"(gsrc));
}

// ---------------------------------------------------------------------------
// fp16 tensor-core GEMM, 3-stage cp.async pipeline.
// ---------------------------------------------------------------------------
#define AH_STRIDE 40
#define BH_STRIDE 136
#define AH_HALFS (128 * AH_STRIDE)
#define BH_HALFS (32 * BH_STRIDE)
#define GEMM_SMEM_BYTES ((3 * AH_HALFS + 3 * BH_HALFS) * 2)   // 56832 B

__global__ __launch_bounds__(256, 2) void fp16_gemm_kernel(
    const __half* __restrict__ A, const __half* __restrict__ W,
    const float* __restrict__ bias, const float* __restrict__ resid,
    void* __restrict__ Cv, int M, int N, int K, int epi, int out_half)
{
    extern __shared__ __half smh[];
    __half* Asm = smh;
    __half* Bsm = smh + 3 * AH_HALFS;

    int tid = threadIdx.x;
    int lane = tid & 31;
    int warp = tid >> 5;
    int g = lane >> 2;
    int t = lane & 3;
    int m_w = (warp >> 2) * 64;
    int n_w = (warp & 3) * 32;

    int rowBase = blockIdx.y * 128;
    int colBase = blockIdx.x * 128;

    const __half* Ag = A + (size_t)rowBase * K;
    const __half* Wg = W + colBase;

    float acc[4][4][4];
#pragma unroll
    for (int mf = 0; mf < 4; mf++)
#pragma unroll
        for (int nf = 0; nf < 4; nf++)
#pragma unroll
            for (int i = 0; i < 4; i++) acc[mf][nf][i] = 0.f;

    int ntiles = K / 32;

    auto issue_copy = [&](int s, int kt) {
        __half* as = Asm + s * AH_HALFS;
        __half* bs = Bsm + s * BH_HALFS;
#pragma unroll
        for (int i = 0; i < 2; i++) {
            int id = tid + i * 256;
            int r = id >> 2;
            int c = (id & 3) * 8;
            cp_async16(as + r * AH_STRIDE + c, Ag + (size_t)r * K + kt + c);
        }
#pragma unroll
        for (int i = 0; i < 2; i++) {
            int id = tid + i * 256;
            int r = id >> 4;
            int c = (id & 15) * 8;
            cp_async16(bs + r * BH_STRIDE + c, Wg + (size_t)(kt + r) * N + c);
        }
        asm volatile("cp.async.commit_group;\n");
    };

    issue_copy(0, 0);
    issue_copy(1, 32);

    for (int kt = 0; kt < ntiles; kt++) {
        if (kt == ntiles - 1) {
            asm volatile("cp.async.wait_group 0;\n");
        } else {
            asm volatile("cp.async.wait_group 1;\n");
        }
        __syncthreads();
        if (kt + 2 < ntiles) issue_copy((kt + 2) % 3, (kt + 2) * 32);

        const __half* as = Asm + (kt % 3) * AH_HALFS;
        const __half* bs = Bsm + (kt % 3) * BH_HALFS;

#pragma unroll
        for (int ks = 0; ks < 2; ks++) {
            uint32_t af[4][4];
#pragma unroll
            for (int mf = 0; mf < 4; mf++) {
                const __half* ap = as + (m_w + mf * 16 + (lane & 15)) * AH_STRIDE
                                      + ks * 16 + (lane >> 4) * 8;
                ldsm_x4(af[mf][0], af[mf][1], af[mf][2], af[mf][3], ap);
            }
            uint32_t bfr[2][4];
#pragma unroll
            for (int nfp = 0; nfp < 2; nfp++) {
                const __half* bp = bs + (ks * 16 + (lane & 15)) * BH_STRIDE
                                      + n_w + nfp * 16 + (lane >> 4) * 8;
                ldsm_x4_t(bfr[nfp][0], bfr[nfp][1], bfr[nfp][2], bfr[nfp][3], bp);
            }
#pragma unroll
            for (int mf = 0; mf < 4; mf++)
#pragma unroll
                for (int nf = 0; nf < 4; nf++) {
                    int nfp = nf >> 1, pr = nf & 1;
                    uint32_t bb[2] = {bfr[nfp][2 * pr], bfr[nfp][2 * pr + 1]};
                    mma_fp16(acc[mf][nf], af[mf], bb);
                }
        }
    }

#pragma unroll
    for (int mf = 0; mf < 4; mf++) {
        int row0 = rowBase + m_w + mf * 16 + g;
        int row1 = row0 + 8;
#pragma unroll
        for (int nf = 0; nf < 4; nf++) {
            int col = colBase + n_w + nf * 8 + 2 * t;
            float2 bv = *(const float2*)&bias[col];
            float v00 = acc[mf][nf][0] + bv.x;
            float v01 = acc[mf][nf][1] + bv.y;
            float v10 = acc[mf][nf][2] + bv.x;
            float v11 = acc[mf][nf][3] + bv.y;
            if (epi == 1) {
                v00 = gelu_tanh(v00); v01 = gelu_tanh(v01);
                v10 = gelu_tanh(v10); v11 = gelu_tanh(v11);
            } else if (epi == 2) {
                float2 r0 = *(const float2*)&resid[(size_t)row0 * N + col];
                float2 r1 = *(const float2*)&resid[(size_t)row1 * N + col];
                v00 += r0.x; v01 += r0.y; v10 += r1.x; v11 += r1.y;
            }
            if (out_half) {
                __half* Ch = (__half*)Cv;
                __half2 p0 = __floats2half2_rn(v00, v01);
                __half2 p1 = __floats2half2_rn(v10, v11);
                *(uint32_t*)&Ch[(size_t)row0 * N + col] = *(uint32_t*)&p0;
                *(uint32_t*)&Ch[(size_t)row1 * N + col] = *(uint32_t*)&p1;
            } else {
                float* C = (float*)Cv;
                *(float2*)&C[(size_t)row0 * N + col] = make_float2(v00, v01);
                *(float2*)&C[(size_t)row1 * N + col] = make_float2(v10, v11);
            }
        }
    }
}

// ---------------------------------------------------------------------------
// Flash attention: fp16 S-accumulate MMA + exp2-domain f16x2 softmax.
// BQ=128, 4 warps x 32 rows, BK=64, 3-stage KV pipeline. P = S C-frags
// directly (f16 C layout == A layout). O accumulates fp32.
// ---------------------------------------------------------------------------
#define FST 72
#define FQ_ELEMS (128 * FST)
#define FKV_ELEMS (64 * FST)
#define FLASHB_SMEM_BYTES ((FQ_ELEMS + 6 * FKV_ELEMS) * 2)   // 73728 B

__global__ __launch_bounds__(128, 2) void flash_fp16_kernel(
    const __half* __restrict__ qkv, __half* __restrict__ attn_out)
{
    extern __shared__ __align__(16) char smraw[];
    __half* Qs = (__half*)smraw;
    __half* Ks = Qs + FQ_ELEMS;        // 3 stages x 64 rows
    __half* Vs = Ks + 3 * FKV_ELEMS;   // 3 stages x 64 rows

    int qi = blockIdx.x, h = blockIdx.y, bz = blockIdx.z;
    int tid = threadIdx.x;
    int lane = tid & 31;
    int warp = tid >> 5;
    int g = lane >> 2, t = lane & 3;
    int m_w = warp * 32;

    size_t rowB = (size_t)bz * T_SEQ;
    const __half* Qg = qkv + (rowB + (size_t)qi * 128) * D_QKV + h * D_HEAD;
    const __half* Kg = qkv + rowB * D_QKV + D_MODEL     + h * D_HEAD;
    const __half* Vg = qkv + rowB * D_QKV + 2 * D_MODEL + h * D_HEAD;

    // stage Q
#pragma unroll
    for (int i = 0; i < 8; i++) {
        int id = tid + i * 128;
        int r = id >> 3, c = (id & 7) * 8;
        cp_async16(Qs + r * FST + c, Qg + (size_t)r * D_QKV + c);
    }
    asm volatile("cp.async.commit_group;\n");

    auto load_kv = [&](int s, int kt) {
        const __half* Kt_ = Kg + (size_t)kt * 64 * D_QKV;
        const __half* Vt_ = Vg + (size_t)kt * 64 * D_QKV;
        __half* ks_ = Ks + s * FKV_ELEMS;
        __half* vs_ = Vs + s * FKV_ELEMS;
#pragma unroll
        for (int i = 0; i < 4; i++) {
            int id = tid + i * 128;
            int r = id >> 3, c = (id & 7) * 8;
            cp_async16(ks_ + r * FST + c, Kt_ + (size_t)r * D_QKV + c);
            cp_async16(vs_ + r * FST + c, Vt_ + (size_t)r * D_QKV + c);
        }
        asm volatile("cp.async.commit_group;\n");
    };
    load_kv(0, 0);
    load_kv(1, 1);

    asm volatile("cp.async.wait_group 2;\n");   // Q ready
    __syncthreads();

    // Q a-fragments, scaled by 0.125 * log2(e) -> exp2 domain
    uint32_t qa[2][4][4];
    {
        __half2 sc2 = __float2half2_rn(0.18033688011111837f);
#pragma unroll
        for (int mf = 0; mf < 2; mf++) {
            const __half* q0 = Qs + (m_w + mf * 16 + g) * FST;
            const __half* q1 = q0 + 8 * FST;
#pragma unroll
            for (int kb = 0; kb < 4; kb++) {
                __half2 v;
                v = __hmul2(*(const __half2*)(q0 + kb * 16 + 2 * t), sc2);
                qa[mf][kb][0] = *(uint32_t*)&v;
                v = __hmul2(*(const __half2*)(q1 + kb * 16 + 2 * t), sc2);
                qa[mf][kb][1] = *(uint32_t*)&v;
                v = __hmul2(*(const __half2*)(q0 + kb * 16 + 2 * t + 8), sc2);
                qa[mf][kb][2] = *(uint32_t*)&v;
                v = __hmul2(*(const __half2*)(q1 + kb * 16 + 2 * t + 8), sc2);
                qa[mf][kb][3] = *(uint32_t*)&v;
            }
        }
    }

    float o[2][8][4];
    float m[2][2], l[2][2];
#pragma unroll
    for (int mf = 0; mf < 2; mf++) {
#pragma unroll
        for (int nf = 0; nf < 8; nf++)
#pragma unroll
            for (int i = 0; i < 4; i++) o[mf][nf][i] = 0.f;
        m[mf][0] = m[mf][1] = -CUDART_INF_F;
        l[mf][0] = l[mf][1] = 0.f;
    }

    const int NITER = T_SEQ / 64;   // 32
    for (int kt = 0; kt < NITER; kt++) {
        if (kt == NITER - 1) {
            asm volatile("cp.async.wait_group 0;\n");
        } else {
            asm volatile("cp.async.wait_group 1;\n");
        }
        __syncthreads();
        if (kt + 2 < NITER) load_kv((kt + 2) % 3, kt + 2);

        const __half* ks_ = Ks + (kt % 3) * FKV_ELEMS;
        const __half* vs_ = Vs + (kt % 3) * FKV_ELEMS;

        // ---- S' = (Q*0.125*log2e) @ K^T in f16-accumulate ----
        uint32_t sh[2][8][2];
#pragma unroll
        for (int nf = 0; nf < 8; nf++) {
            uint32_t b0[4], b1[4];
            const __half* kp = ks_ + (nf * 8 + (lane & 7)) * FST + (lane >> 3) * 8;
            ldsm_x4(b0[0], b0[1], b0[2], b0[3], kp);
            ldsm_x4(b1[0], b1[1], b1[2], b1[3], kp + 32);
#pragma unroll
            for (int mf = 0; mf < 2; mf++) {
                sh[mf][nf][0] = 0u; sh[mf][nf][1] = 0u;
                { uint32_t bb[2] = {b0[0], b0[1]}; mma_f16acc(sh[mf][nf], qa[mf][0], bb); }
                { uint32_t bb[2] = {b0[2], b0[3]}; mma_f16acc(sh[mf][nf], qa[mf][1], bb); }
                { uint32_t bb[2] = {b1[0], b1[1]}; mma_f16acc(sh[mf][nf], qa[mf][2], bb); }
                { uint32_t bb[2] = {b1[2], b1[3]}; mma_f16acc(sh[mf][nf], qa[mf][3], bb); }
            }
        }

        // ---- online softmax in exp2 domain ----
        float sc_[2][2];
#pragma unroll
        for (int mf = 0; mf < 2; mf++) {
            __half2 hm0 = *(__half2*)&sh[mf][0][0];
            __half2 hm1 = *(__half2*)&sh[mf][0][1];
#pragma unroll
            for (int nf = 1; nf < 8; nf++) {
                hm0 = __hmax2(hm0, *(__half2*)&sh[mf][nf][0]);
                hm1 = __hmax2(hm1, *(__half2*)&sh[mf][nf][1]);
            }
            float mx0 = fmaxf(__low2float(hm0), __high2float(hm0));
            float mx1 = fmaxf(__low2float(hm1), __high2float(hm1));
#pragma unroll
            for (int off = 1; off <= 2; off <<= 1) {
                mx0 = fmaxf(mx0, __shfl_xor_sync(0xffffffffu, mx0, off));
                mx1 = fmaxf(mx1, __shfl_xor_sync(0xffffffffu, mx1, off));
            }
            float mn0 = fmaxf(m[mf][0], mx0), mn1 = fmaxf(m[mf][1], mx1);
            sc_[mf][0] = exp2f(m[mf][0] - mn0);
            sc_[mf][1] = exp2f(m[mf][1] - mn1);
            m[mf][0] = mn0; m[mf][1] = mn1;

            __half2 mn0h = __float2half2_rn(mn0);
            __half2 mn1h = __float2half2_rn(mn1);
            float rs0 = 0.f, rs1 = 0.f;
#pragma unroll
            for (int nf = 0; nf < 8; nf++) {
                __half2 e0 = h2exp2_(__hsub2(*(__half2*)&sh[mf][nf][0], mn0h));
                __half2 e1 = h2exp2_(__hsub2(*(__half2*)&sh[mf][nf][1], mn1h));
                sh[mf][nf][0] = *(uint32_t*)&e0;   // P packed (A-frag ready)
                sh[mf][nf][1] = *(uint32_t*)&e1;
                float2 f0 = __half22float2(e0);
                float2 f1 = __half22float2(e1);
                rs0 += f0.x + f0.y;
                rs1 += f1.x + f1.y;
            }
#pragma unroll
            for (int off = 1; off <= 2; off <<= 1) {
                rs0 += __shfl_xor_sync(0xffffffffu, rs0, off);
                rs1 += __shfl_xor_sync(0xffffffffu, rs1, off);
            }
            l[mf][0] = l[mf][0] * sc_[mf][0] + rs0;
            l[mf][1] = l[mf][1] * sc_[mf][1] + rs1;
#pragma unroll
            for (int nf = 0; nf < 8; nf++) {
                o[mf][nf][0] *= sc_[mf][0]; o[mf][nf][1] *= sc_[mf][0];
                o[mf][nf][2] *= sc_[mf][1]; o[mf][nf][3] *= sc_[mf][1];
            }
        }

        // ---- O += P @ V : P a-frags ARE the exp'd S C-frags ----
#pragma unroll
        for (int kb = 0; kb < 4; kb++) {
            const __half* vp = vs_ + (kb * 16 + (lane & 15)) * FST + (lane >> 4) * 8;
#pragma unroll
            for (int nfp = 0; nfp < 4; nfp++) {
                uint32_t v0, v1, v2, v3;
                ldsm_x4_t(v0, v1, v2, v3, vp + nfp * 16);
#pragma unroll
                for (int mf = 0; mf < 2; mf++) {
                    uint32_t a[4] = {sh[mf][2*kb][0], sh[mf][2*kb][1],
                                     sh[mf][2*kb+1][0], sh[mf][2*kb+1][1]};
                    { uint32_t bb[2] = {v0, v1}; mma_fp16(o[mf][2*nfp],     a, bb); }
                    { uint32_t bb[2] = {v2, v3}; mma_fp16(o[mf][2*nfp + 1], a, bb); }
                }
            }
        }
    }

    // ---- epilogue: O / l -> fp16 attn ----
#pragma unroll
    for (int mf = 0; mf < 2; mf++) {
        float i0 = 1.f / l[mf][0], i1 = 1.f / l[mf][1];
        size_t tok0 = rowB + (size_t)qi * 128 + m_w + mf * 16 + g;
        __half* out0 = attn_out + tok0 * D_MODEL + h * D_HEAD;
        __half* out1 = out0 + 8 * (size_t)D_MODEL;
#pragma unroll
        for (int nf = 0; nf < 8; nf++) {
            __half2 p0 = __floats2half2_rn(o[mf][nf][0] * i0, o[mf][nf][1] * i0);
            __half2 p1 = __floats2half2_rn(o[mf][nf][2] * i1, o[mf][nf][3] * i1);
            *(uint32_t*)(out0 + nf * 8 + 2 * t) = *(uint32_t*)&p0;
            *(uint32_t*)(out1 + nf * 8 + 2 * t) = *(uint32_t*)&p1;
        }
    }
}

// ---------------------------------------------------------------------------
// Launch
// ---------------------------------------------------------------------------
extern "C" void kernel_launch(void* const* d_in, const int* in_sizes, int n_in,
                              void* d_out, int out_size)
{
    const float* x          = (const float*)d_in[0];
    const float* ln1_g      = (const float*)d_in[1];
    const float* ln1_b      = (const float*)d_in[2];
    const float* qkv_w      = (const float*)d_in[3];
    const float* qkv_b      = (const float*)d_in[4];
    const float* attn_out_w = (const float*)d_in[5];
    const float* attn_out_b = (const float*)d_in[6];
    const float* ln2_g      = (const float*)d_in[7];
    const float* ln2_b      = (const float*)d_in[8];
    const float* ff1_w      = (const float*)d_in[9];
    const float* ff1_b      = (const float*)d_in[10];
    const float* ff2_w      = (const float*)d_in[11];
    const float* ff2_b      = (const float*)d_in[12];
    float* out = (float*)d_out;

    void *p_h, *p_qkv, *p_attn, *p_x1, *p_mid, *p_w;
    cudaGetSymbolAddress(&p_h,    g_h);
    cudaGetSymbolAddress(&p_qkv,  g_qkv);
    cudaGetSymbolAddress(&p_attn, g_attn);
    cudaGetSymbolAddress(&p_x1,   g_x1);
    cudaGetSymbolAddress(&p_mid,  g_mid);
    cudaGetSymbolAddress(&p_w,    g_w);
    __half* h    = (__half*)p_h;
    __half* qkv  = (__half*)p_qkv;
    __half* attn = (__half*)p_attn;
    float*  x1   = (float*)p_x1;
    __half* mid  = (__half*)p_mid;
    __half* w_qkv = (__half*)p_w;
    __half* w_ao  = w_qkv + W_QKV_N;
    __half* w_ff1 = w_ao  + W_AO_N;
    __half* w_ff2 = w_ff1 + W_FF1_N;

    cudaFuncSetAttribute(flash_fp16_kernel,
                         cudaFuncAttributeMaxDynamicSharedMemorySize,
                         FLASHB_SMEM_BYTES);
    cudaFuncSetAttribute(fp16_gemm_kernel,
                         cudaFuncAttributeMaxDynamicSharedMemorySize,
                         GEMM_SMEM_BYTES);

    // 0. convert all weights to fp16
    round_all_kernel<<<(W_TOTAL_N / 4 + 255) / 256, 256>>>(
        qkv_w, attn_out_w, ff1_w, ff2_w, (__half*)p_w);

    // 1. h = LN1(x)
    ln_kernel<<<NTOK / 8, 256>>>(x, ln1_g, ln1_b, h);
    // 2. qkv = h @ qkv_w + qkv_b
    fp16_gemm_kernel<<<dim3(D_QKV / 128, NTOK / 128), 256, GEMM_SMEM_BYTES>>>(
        h, w_qkv, qkv_b, nullptr, qkv, NTOK, D_QKV, D_MODEL, 0, 1);
    // 3. attention
    flash_fp16_kernel<<<dim3(T_SEQ / 128, N_HEADS, B_SZ), 128, FLASHB_SMEM_BYTES>>>(
        qkv, attn);
    // 4. x1 = x + attn @ attn_out_w + attn_out_b
    fp16_gemm_kernel<<<dim3(D_MODEL / 128, NTOK / 128), 256, GEMM_SMEM_BYTES>>>(
        attn, w_ao, attn_out_b, x, x1, NTOK, D_MODEL, D_MODEL, 2, 0);
    // 5. h = LN2(x1)
    ln_kernel<<<NTOK / 8, 256>>>(x1, ln2_g, ln2_b, h);
    // 6. mid = gelu(h @ ff1_w + ff1_b)
    fp16_gemm_kernel<<<dim3(D_FF / 128, NTOK / 128), 256, GEMM_SMEM_BYTES>>>(
        h, w_ff1, ff1_b, nullptr, mid, NTOK, D_FF, D_MODEL, 1, 1);
    // 7. out = x1 + mid @ ff2_w + ff2_b
    fp16_gemm_kernel<<<dim3(D_MODEL / 128, NTOK / 128), 256, GEMM_SMEM_BYTES>>>(
        mid, w_ff2, ff2_b, x1, out, NTOK, D_MODEL, D_FF, 2, 0);
}